// round 12
// baseline (speedup 1.0000x reference)
#include <cuda_runtime.h>
#include <cuda_bf16.h>
#include <math.h>
#include <cstdint>
#include <stdint.h>

#define B_    4
#define S_    1024
#define DIM_  2048
#define H_    16
#define HD_   128
#define BSTOT 4096   // B_*S_
#define NSB   8      // S_/128 blocks
#define NTRI  36     // lower-tri 128x128 tiles per head

// ---------------- scratch ----------------
__device__ float d_V[(size_t)H_*B_*S_*HD_];      // fp32 V (suffix + vtrans src)
__device__ float d_O[(size_t)BSTOT*DIM_];
__device__ float d_G[(size_t)BSTOT*DIM_];        // relu(x@wg) fp32
__device__ float d_bsum[(size_t)H_*B_*NSB*HD_];
__device__ float d_suf[(size_t)H_*B_*NSB*HD_];
__device__ float d_rs[H_*S_];
__device__ float d_l2g[H_];
// bf16 hi/lo operand buffers
__device__ __nv_bfloat16 d_Qh[(size_t)H_*B_*S_*HD_];  // [h,b,s,e]
__device__ __nv_bfloat16 d_Ql[(size_t)H_*B_*S_*HD_];
__device__ __nv_bfloat16 d_Kh[(size_t)H_*B_*S_*HD_];  // [h,b,t,e]
__device__ __nv_bfloat16 d_Kl[(size_t)H_*B_*S_*HD_];
__device__ __nv_bfloat16 d_Vth[(size_t)H_*B_*HD_*S_]; // V^T [h,b,e,t]
__device__ __nv_bfloat16 d_Vtl[(size_t)H_*B_*HD_*S_];
__device__ __nv_bfloat16 d_Ahh[(size_t)H_*S_*S_];     // A [h,s,t] hi
__device__ __nv_bfloat16 d_Ahl[(size_t)H_*S_*S_];     // A lo
__device__ __nv_bfloat16 d_xh[(size_t)BSTOT*DIM_];    // x/G hi [m][k]
__device__ __nv_bfloat16 d_xl[(size_t)BSTOT*DIM_];
__device__ __nv_bfloat16 d_kh2[(size_t)BSTOT*DIM_];   // k input hi [m][k]
__device__ __nv_bfloat16 d_kl2[(size_t)BSTOT*DIM_];
__device__ __nv_bfloat16 d_vh2[(size_t)BSTOT*DIM_];   // v input hi [m][k]
__device__ __nv_bfloat16 d_vl2[(size_t)BSTOT*DIM_];
__device__ __nv_bfloat16 d_whh[(size_t)H_*HD_*HD_];   // Wh^T [h][e][d] hi
__device__ __nv_bfloat16 d_whl[(size_t)H_*HD_*HD_];
__device__ __nv_bfloat16 d_wgh[(size_t)DIM_*DIM_];    // wg^T [n][k]
__device__ __nv_bfloat16 d_wgl[(size_t)DIM_*DIM_];
__device__ __nv_bfloat16 d_woh[(size_t)DIM_*DIM_];
__device__ __nv_bfloat16 d_wol[(size_t)DIM_*DIM_];

// ---------------- decay tables ----------------
__global__ void decay_kernel() {
    int h = blockIdx.x;
    int j = threadIdx.x;
    double g  = 1.0 - exp2((double)(-5 - h));
    double r  = 1.0 / g;
    double rp = pow(r, (double)(j + 1));
    double Sj = (rp - 1.0) / (r - 1.0);
    d_rs[h * S_ + j] = (float)(1.0 / sqrt(Sj));
    if (j == 0) d_l2g[h] = (float)log2(g);
}

// ---------------- fp32 -> (hi,lo) bf16 split (activations) ----------------
// which: 0 = x -> xh/xl ; 4 = k -> kh2/kl2 ; 5 = v -> vh2/vl2
__global__ void split_kernel(const float* __restrict__ srcParam, int which) {
    const float* src = srcParam;
    __nv_bfloat16* hi = (which == 4) ? d_kh2 : (which == 5) ? d_vh2 : d_xh;
    __nv_bfloat16* lo = (which == 4) ? d_kl2 : (which == 5) ? d_vl2 : d_xl;
    size_t i = (size_t)(blockIdx.x) * blockDim.x + threadIdx.x;
    float4 v = ((const float4*)src)[i];
    __nv_bfloat16 h0 = __float2bfloat16(v.x);
    __nv_bfloat16 h1 = __float2bfloat16(v.y);
    __nv_bfloat16 h2 = __float2bfloat16(v.z);
    __nv_bfloat16 h3 = __float2bfloat16(v.w);
    __nv_bfloat16 l0 = __float2bfloat16(v.x - __bfloat162float(h0));
    __nv_bfloat16 l1 = __float2bfloat16(v.y - __bfloat162float(h1));
    __nv_bfloat16 l2 = __float2bfloat16(v.z - __bfloat162float(h2));
    __nv_bfloat16 l3 = __float2bfloat16(v.w - __bfloat162float(h3));
    __nv_bfloat162 hA; hA.x = h0; hA.y = h1;
    __nv_bfloat162 hB; hB.x = h2; hB.y = h3;
    __nv_bfloat162 lA; lA.x = l0; lA.y = l1;
    __nv_bfloat162 lB; lB.x = l2; lB.y = l3;
    *(__nv_bfloat162*)&hi[i * 4]     = hA;
    *(__nv_bfloat162*)&hi[i * 4 + 2] = hB;
    *(__nv_bfloat162*)&lo[i * 4]     = lA;
    *(__nv_bfloat162*)&lo[i * 4 + 2] = lB;
}

// ---------------- big weight transpose + split ----
__global__ void wtrans_kernel(const float* __restrict__ w, int which) {
    __nv_bfloat16* hi = (which == 0) ? d_wgh : d_woh;
    __nv_bfloat16* lo = (which == 0) ? d_wgl : d_wol;
    __shared__ float tile[32][33];
    const int bx = blockIdx.x * 32;
    const int by = blockIdx.y * 32;
    const int tx = threadIdx.x;
    const int ty = threadIdx.y;
#pragma unroll
    for (int i = 0; i < 4; i++) {
        int r = ty * 4 + i;
        tile[r][tx] = w[(size_t)(by + r) * DIM_ + bx + tx];
    }
    __syncthreads();
#pragma unroll
    for (int i = 0; i < 4; i++) {
        int nl = ty * 4 + i;
        float vv = tile[tx][nl];
        __nv_bfloat16 hv = __float2bfloat16(vv);
        __nv_bfloat16 lv = __float2bfloat16(vv - __bfloat162float(hv));
        size_t idx = (size_t)(bx + nl) * DIM_ + by + tx;
        hi[idx] = hv;
        lo[idx] = lv;
    }
}

// ---------------- per-head Wh transpose + split: Wh[h][d][e] -> [h][e][d] --
__global__ void whtrans_kernel(const float* __restrict__ Wh) {
    __shared__ float tile[32][33];
    const int h  = blockIdx.z;
    const int bx = blockIdx.x * 32;   // e offset
    const int by = blockIdx.y * 32;   // d offset
    const int tx = threadIdx.x;
    const int ty = threadIdx.y;
    const float* W = Wh + (size_t)h * HD_ * HD_;
#pragma unroll
    for (int i = 0; i < 4; i++) {
        int r = ty * 4 + i;           // d-local
        tile[r][tx] = W[(size_t)(by + r) * HD_ + bx + tx];
    }
    __syncthreads();
#pragma unroll
    for (int i = 0; i < 4; i++) {
        int el = ty * 4 + i;          // e-local
        float vv = tile[tx][el];      // = W[by+tx][bx+el]
        __nv_bfloat16 hv = __float2bfloat16(vv);
        __nv_bfloat16 lv = __float2bfloat16(vv - __bfloat162float(hv));
        size_t idx = (size_t)h * HD_ * HD_ + (size_t)(bx + el) * HD_ + by + tx;
        d_whh[idx] = hv;
        d_whl[idx] = lv;
    }
}

// ---------------- V transpose + split: d_V[hb][s][e] -> Vt [hb][e][s] -----
__global__ void vtrans_kernel() {
    __shared__ float tile[32][33];
    const int hb = blockIdx.z;
    const int bx = blockIdx.x * 32;   // e offset
    const int by = blockIdx.y * 32;   // s offset
    const int tx = threadIdx.x;
    const int ty = threadIdx.y;
    const float* Vsrc = d_V + (size_t)hb * S_ * HD_;
#pragma unroll
    for (int i = 0; i < 4; i++) {
        int r = ty * 4 + i;           // s-local
        tile[r][tx] = Vsrc[(size_t)(by + r) * HD_ + bx + tx];
    }
    __syncthreads();
#pragma unroll
    for (int i = 0; i < 4; i++) {
        int el = ty * 4 + i;          // e-local
        float vv = tile[tx][el];      // = V[by+tx][bx+el]
        __nv_bfloat16 hv = __float2bfloat16(vv);
        __nv_bfloat16 lv = __float2bfloat16(vv - __bfloat162float(hv));
        size_t idx = (size_t)hb * HD_ * S_ + (size_t)(bx + el) * S_ + by + tx;
        d_Vth[idx] = hv;
        d_Vtl[idx] = lv;
    }
}

// ---------------- shared mma helpers ----------
#define T_LDS 40
__device__ __forceinline__ void ldsm4(unsigned int& r0, unsigned int& r1,
                                      unsigned int& r2, unsigned int& r3, unsigned int addr) {
    asm volatile("ldmatrix.sync.aligned.m8n8.x4.shared.b16 {%0,%1,%2,%3}, [%4];"
                 : "=r"(r0), "=r"(r1), "=r"(r2), "=r"(r3) : "r"(addr));
}
__device__ __forceinline__ void mma16816(float* c, const unsigned int* a, const unsigned int* b) {
    asm volatile("mma.sync.aligned.m16n8k16.row.col.f32.bf16.bf16.f32 "
                 "{%0,%1,%2,%3}, {%4,%5,%6,%7}, {%8,%9}, {%0,%1,%2,%3};"
                 : "+f"(c[0]), "+f"(c[1]), "+f"(c[2]), "+f"(c[3])
                 : "r"(a[0]), "r"(a[1]), "r"(a[2]), "r"(a[3]), "r"(b[0]), "r"(b[1]));
}

// ---------------- qkv tensor kernel -----------------------
// which 0/1/2 = x/k/v stream. C[4096 x 128] = X_h @ Wh_h (split-3).
// which<2: epilogue split -> Qh/Ql or Kh/Kl. which==2: fp32 d_V.
__global__ __launch_bounds__(256, 2)
void qkv_tensor_kernel() {
    const int m0    = blockIdx.x * 128;
    const int h     = blockIdx.y;
    const int which = blockIdx.z;

    const __nv_bfloat16* Ahp = (which == 0) ? d_xh : (which == 1) ? d_kh2 : d_vh2;
    const __nv_bfloat16* Alp = (which == 0) ? d_xl : (which == 1) ? d_kl2 : d_vl2;
    const __nv_bfloat16* Bhp = d_whh + (size_t)h * HD_ * HD_;
    const __nv_bfloat16* Blp = d_whl + (size_t)h * HD_ * HD_;

    __shared__ __align__(16) unsigned short AsB[128 * T_LDS];
    __shared__ __align__(16) unsigned short BtB[128 * T_LDS];

    const int tid  = threadIdx.x;
    const int wid  = tid >> 5;
    const int lane = tid & 31;
    const int wm = wid & 3;
    const int wn = wid >> 2;

    const unsigned int asbase = (unsigned int)__cvta_generic_to_shared(AsB);
    const unsigned int bsbase = (unsigned int)__cvta_generic_to_shared(BtB);

    const __nv_bfloat16* APtr[3] = {Ahp, Ahp, Alp};
    const __nv_bfloat16* BPtr[3] = {Bhp, Blp, Bhp};

    float acc[2][8][4];
#pragma unroll
    for (int i = 0; i < 2; i++)
#pragma unroll
        for (int j = 0; j < 8; j++)
#pragma unroll
            for (int c = 0; c < 4; c++) acc[i][j][c] = 0.0f;

    const int a_r  = lane & 15;
    const int a_k8 = ((lane >> 4) & 1) * 8;
    const int b_r  = ((lane >> 4) << 3) + (lane & 7);
    const int b_k8 = ((lane >> 3) & 1) * 8;

    uint4 pa0, pa1, pb0, pb1;
    const int NITER = 12;   // 3 terms x 4 k-chunks (128/32)

    {
        const __nv_bfloat16* Ag = APtr[0] + (size_t)m0 * DIM_ + h * HD_;
        const __nv_bfloat16* Bg = BPtr[0];
        int ia0 = tid, ia1 = tid + 256;
        pa0 = *(const uint4*)(Ag + (size_t)(ia0 >> 2) * DIM_ + (ia0 & 3) * 8);
        pa1 = *(const uint4*)(Ag + (size_t)(ia1 >> 2) * DIM_ + (ia1 & 3) * 8);
        pb0 = *(const uint4*)(Bg + (size_t)(ia0 >> 2) * HD_ + (ia0 & 3) * 8);
        pb1 = *(const uint4*)(Bg + (size_t)(ia1 >> 2) * HD_ + (ia1 & 3) * 8);
    }

    for (int it = 0; it < NITER; it++) {
        {
            int ia0 = tid, ia1 = tid + 256;
            *(uint4*)&AsB[(ia0 >> 2) * T_LDS + (ia0 & 3) * 8] = pa0;
            *(uint4*)&AsB[(ia1 >> 2) * T_LDS + (ia1 & 3) * 8] = pa1;
            *(uint4*)&BtB[(ia0 >> 2) * T_LDS + (ia0 & 3) * 8] = pb0;
            *(uint4*)&BtB[(ia1 >> 2) * T_LDS + (ia1 & 3) * 8] = pb1;
        }
        __syncthreads();

        if (it + 1 < NITER) {
            int nit = it + 1;
            int term = nit >> 2;
            int k0 = (nit & 3) * 32;
            const __nv_bfloat16* Ag = APtr[term] + (size_t)m0 * DIM_ + h * HD_ + k0;
            const __nv_bfloat16* Bg = BPtr[term] + k0;
            int ia0 = tid, ia1 = tid + 256;
            pa0 = *(const uint4*)(Ag + (size_t)(ia0 >> 2) * DIM_ + (ia0 & 3) * 8);
            pa1 = *(const uint4*)(Ag + (size_t)(ia1 >> 2) * DIM_ + (ia1 & 3) * 8);
            pb0 = *(const uint4*)(Bg + (size_t)(ia0 >> 2) * HD_ + (ia0 & 3) * 8);
            pb1 = *(const uint4*)(Bg + (size_t)(ia1 >> 2) * HD_ + (ia1 & 3) * 8);
        }

#pragma unroll
        for (int ks = 0; ks < 2; ks++) {
            const int kb = ks * 16;
            unsigned int af[2][4];
#pragma unroll
            for (int mi = 0; mi < 2; mi++) {
                int row = wm * 32 + mi * 16 + a_r;
                unsigned int addr = asbase + (unsigned int)(row * T_LDS + kb + a_k8) * 2;
                ldsm4(af[mi][0], af[mi][1], af[mi][2], af[mi][3], addr);
            }
#pragma unroll
            for (int nj = 0; nj < 4; nj++) {
                int nrow = wn * 64 + nj * 16 + b_r;
                unsigned int addr = bsbase + (unsigned int)(nrow * T_LDS + kb + b_k8) * 2;
                unsigned int bf[4];
                ldsm4(bf[0], bf[1], bf[2], bf[3], addr);
#pragma unroll
                for (int mi = 0; mi < 2; mi++) {
                    mma16816(acc[mi][nj * 2 + 0], af[mi], &bf[0]);
                    mma16816(acc[mi][nj * 2 + 1], af[mi], &bf[2]);
                }
            }
        }
        __syncthreads();
    }

    const int qr = lane >> 2;
    const int qc = (lane & 3) * 2;
    const int b = m0 >> 10;
    if (which < 2) {
        __nv_bfloat16* hid = (which == 0) ? d_Qh : d_Kh;
        __nv_bfloat16* lod = (which == 0) ? d_Ql : d_Kl;
#pragma unroll
        for (int mi = 0; mi < 2; mi++) {
#pragma unroll
            for (int n8 = 0; n8 < 8; n8++) {
                int e = wn * 64 + n8 * 8 + qc;
#pragma unroll
                for (int half = 0; half < 2; half++) {
                    int m = m0 + wm * 32 + mi * 16 + qr + half * 8;
                    int s = m & 1023;
                    float v1 = acc[mi][n8][half * 2 + 0];
                    float v2 = acc[mi][n8][half * 2 + 1];
                    __nv_bfloat16 h1 = __float2bfloat16(v1);
                    __nv_bfloat16 h2 = __float2bfloat16(v2);
                    __nv_bfloat16 l1 = __float2bfloat16(v1 - __bfloat162float(h1));
                    __nv_bfloat16 l2 = __float2bfloat16(v2 - __bfloat162float(h2));
                    __nv_bfloat162 hp; hp.x = h1; hp.y = h2;
                    __nv_bfloat162 lp; lp.x = l1; lp.y = l2;
                    size_t off = ((size_t)(h * B_ + b) * S_ + s) * HD_ + e;
                    *(__nv_bfloat162*)&hid[off] = hp;
                    *(__nv_bfloat162*)&lod[off] = lp;
                }
            }
        }
    } else {
#pragma unroll
        for (int mi = 0; mi < 2; mi++) {
#pragma unroll
            for (int n8 = 0; n8 < 8; n8++) {
                int e = wn * 64 + n8 * 8 + qc;
                int m = m0 + wm * 32 + mi * 16 + qr;
                int s = m & 1023;
                float2 v0; v0.x = acc[mi][n8][0]; v0.y = acc[mi][n8][1];
                float2 v1; v1.x = acc[mi][n8][2]; v1.y = acc[mi][n8][3];
                *(float2*)&d_V[((size_t)(h * B_ + b) * S_ + s) * HD_ + e] = v0;
                *(float2*)&d_V[((size_t)(h * B_ + b) * S_ + s + 8) * HD_ + e] = v1;
            }
        }
    }
}

// ---------------- suffix phase A ----------
__global__ void bsum_kernel() {
    const int hb = blockIdx.x;
    const int i  = blockIdx.y;
    const int e  = threadIdx.x;
    const float* blk = d_V + ((size_t)hb * S_ + i * 128) * HD_;
    float a0 = 0.f, a1 = 0.f, a2 = 0.f, a3 = 0.f;
#pragma unroll 8
    for (int t = 0; t < 128; t += 4) {
        a0 += blk[(t + 0) * HD_ + e];
        a1 += blk[(t + 1) * HD_ + e];
        a2 += blk[(t + 2) * HD_ + e];
        a3 += blk[(t + 3) * HD_ + e];
    }
    d_bsum[((size_t)hb * NSB + i) * HD_ + e] = (a0 + a1) + (a2 + a3);
}

// ---------------- suffix phase B ----
__global__ void sufscan_kernel() {
    const int hb = blockIdx.x;
    const int e  = threadIdx.x;
    float acc = 0.f;
#pragma unroll
    for (int i = NSB - 1; i >= 0; i--) {
        d_suf[((size_t)hb * NSB + i) * HD_ + e] = acc;
        acc += d_bsum[((size_t)hb * NSB + i) * HD_ + e];
    }
}

// ---------------- scores tensor kernel (R11-proven) ----------
__global__ __launch_bounds__(256, 2)
void scores_tensor_kernel() {
    const int h = blockIdx.y;
    int kidx = blockIdx.x;
    int si = 0;
    while ((si + 1) * (si + 2) / 2 <= kidx) si++;
    const int tj = kidx - si * (si + 1) / 2;
    const int s0 = si * 128, t0 = tj * 128;

    __shared__ __align__(16) unsigned short AsB[128 * T_LDS];
    __shared__ __align__(16) unsigned short BtB[128 * T_LDS];

    const int tid  = threadIdx.x;
    const int wid  = tid >> 5;
    const int lane = tid & 31;
    const int wm = wid & 3;
    const int wn = wid >> 2;

    const unsigned int asbase = (unsigned int)__cvta_generic_to_shared(AsB);
    const unsigned int bsbase = (unsigned int)__cvta_generic_to_shared(BtB);

    const __nv_bfloat16* APtr[3] = {d_Qh, d_Qh, d_Ql};
    const __nv_bfloat16* BPtr[3] = {d_Kh, d_Kl, d_Kh};

    float acc[2][8][4];
#pragma unroll
    for (int i = 0; i < 2; i++)
#pragma unroll
        for (int j = 0; j < 8; j++)
#pragma unroll
            for (int c = 0; c < 4; c++) acc[i][j][c] = 0.0f;

    const int a_r  = lane & 15;
    const int a_k8 = ((lane >> 4) & 1) * 8;
    const int b_r  = ((lane >> 4) << 3) + (lane & 7);
    const int b_k8 = ((lane >> 3) & 1) * 8;

    uint4 pa0, pa1, pb0, pb1;
    const int NITER = 48;

    {
        const __nv_bfloat16* Ag = APtr[0] + ((size_t)(h * B_) * S_ + s0) * HD_;
        const __nv_bfloat16* Bg = BPtr[0] + ((size_t)(h * B_) * S_ + t0) * HD_;
        int ia0 = tid, ia1 = tid + 256;
        pa0 = *(const uint4*)(Ag + (size_t)(ia0 >> 2) * HD_ + (ia0 & 3) * 8);
        pa1 = *(const uint4*)(Ag + (size_t)(ia1 >> 2) * HD_ + (ia1 & 3) * 8);
        pb0 = *(const uint4*)(Bg + (size_t)(ia0 >> 2) * HD_ + (ia0 & 3) * 8);
        pb1 = *(const uint4*)(Bg + (size_t)(ia1 >> 2) * HD_ + (ia1 & 3) * 8);
    }

    for (int it = 0; it < NITER; it++) {
        {
            int ia0 = tid, ia1 = tid + 256;
            *(uint4*)&AsB[(ia0 >> 2) * T_LDS + (ia0 & 3) * 8] = pa0;
            *(uint4*)&AsB[(ia1 >> 2) * T_LDS + (ia1 & 3) * 8] = pa1;
            *(uint4*)&BtB[(ia0 >> 2) * T_LDS + (ia0 & 3) * 8] = pb0;
            *(uint4*)&BtB[(ia1 >> 2) * T_LDS + (ia1 & 3) * 8] = pb1;
        }
        __syncthreads();

        if (it + 1 < NITER) {
            int nit = it + 1;
            int term = nit >> 4;
            int kk = (nit & 15) * 32;
            int b = kk >> 7, e0 = kk & 127;
            const __nv_bfloat16* Ag = APtr[term] + ((size_t)(h * B_ + b) * S_ + s0) * HD_ + e0;
            const __nv_bfloat16* Bg = BPtr[term] + ((size_t)(h * B_ + b) * S_ + t0) * HD_ + e0;
            int ia0 = tid, ia1 = tid + 256;
            pa0 = *(const uint4*)(Ag + (size_t)(ia0 >> 2) * HD_ + (ia0 & 3) * 8);
            pa1 = *(const uint4*)(Ag + (size_t)(ia1 >> 2) * HD_ + (ia1 & 3) * 8);
            pb0 = *(const uint4*)(Bg + (size_t)(ia0 >> 2) * HD_ + (ia0 & 3) * 8);
            pb1 = *(const uint4*)(Bg + (size_t)(ia1 >> 2) * HD_ + (ia1 & 3) * 8);
        }

#pragma unroll
        for (int ks = 0; ks < 2; ks++) {
            const int kb = ks * 16;
            unsigned int af[2][4];
#pragma unroll
            for (int mi = 0; mi < 2; mi++) {
                int row = wm * 32 + mi * 16 + a_r;
                unsigned int addr = asbase + (unsigned int)(row * T_LDS + kb + a_k8) * 2;
                ldsm4(af[mi][0], af[mi][1], af[mi][2], af[mi][3], addr);
            }
#pragma unroll
            for (int nj = 0; nj < 4; nj++) {
                int nrow = wn * 64 + nj * 16 + b_r;
                unsigned int addr = bsbase + (unsigned int)(nrow * T_LDS + kb + b_k8) * 2;
                unsigned int bf[4];
                ldsm4(bf[0], bf[1], bf[2], bf[3], addr);
#pragma unroll
                for (int mi = 0; mi < 2; mi++) {
                    mma16816(acc[mi][nj * 2 + 0], af[mi], &bf[0]);
                    mma16816(acc[mi][nj * 2 + 1], af[mi], &bf[2]);
                }
            }
        }
        __syncthreads();
    }

    const float l2g = d_l2g[h];
    const float inv_sqrt_hd = 0.08838834764831845f;
    __nv_bfloat16* Ahh = d_Ahh + (size_t)h * S_ * S_;
    __nv_bfloat16* Ahl = d_Ahl + (size_t)h * S_ * S_;
    const int qr = lane >> 2;
    const int qc = (lane & 3) * 2;
#pragma unroll
    for (int mi = 0; mi < 2; mi++) {
#pragma unroll
        for (int n8 = 0; n8 < 8; n8++) {
            int t1 = t0 + wn * 64 + n8 * 8 + qc;
            float rs1 = d_rs[h * S_ + t1];
            float rs2 = d_rs[h * S_ + t1 + 1];
#pragma unroll
            for (int half = 0; half < 2; half++) {
                int s = s0 + wm * 32 + mi * 16 + qr + half * 8;
                float a1 = acc[mi][n8][half * 2 + 0];
                float a2 = acc[mi][n8][half * 2 + 1];
                float v1 = (t1 > s) ? 1.0f
                   : fmaxf(fabsf(a1 * inv_sqrt_hd * exp2f((float)(t1 - s) * l2g) * rs1), 1.0f);
                float v2 = (t1 + 1 > s) ? 1.0f
                   : fmaxf(fabsf(a2 * inv_sqrt_hd * exp2f((float)(t1 + 1 - s) * l2g) * rs2), 1.0f);
                __nv_bfloat16 h1 = __float2bfloat16(v1);
                __nv_bfloat16 h2 = __float2bfloat16(v2);
                __nv_bfloat16 l1 = __float2bfloat16(v1 - __bfloat162float(h1));
                __nv_bfloat16 l2 = __float2bfloat16(v2 - __bfloat162float(h2));
                __nv_bfloat162 hp; hp.x = h1; hp.y = h2;
                __nv_bfloat162 lp; lp.x = l1; lp.y = l2;
                *(__nv_bfloat162*)&Ahh[(size_t)s * S_ + t1] = hp;
                *(__nv_bfloat162*)&Ahl[(size_t)s * S_ + t1] = lp;
            }
        }
    }
}

// ---------------- ogemm tensor kernel (R11-proven) ---------
__global__ __launch_bounds__(256, 2)
void ogemm_tensor_kernel() {
    const int bh = blockIdx.y;
    const int b = bh >> 4, h = bh & 15;
    const int si = blockIdx.x;
    const int s0 = si * 128;
    const int KT = (si + 1) * 4;

    __shared__ __align__(16) unsigned short AsB[128 * T_LDS];
    __shared__ __align__(16) unsigned short BtB[128 * T_LDS];

    const int tid  = threadIdx.x;
    const int wid  = tid >> 5;
    const int lane = tid & 31;
    const int wm = wid & 3;
    const int wn = wid >> 2;

    const unsigned int asbase = (unsigned int)__cvta_generic_to_shared(AsB);
    const unsigned int bsbase = (unsigned int)__cvta_generic_to_shared(BtB);

    const __nv_bfloat16* Abase_h = d_Ahh + (size_t)h * S_ * S_;
    const __nv_bfloat16* Abase_l = d_Ahl + (size_t)h * S_ * S_;
    const __nv_bfloat16* Vbase_h = d_Vth + (size_t)(h * B_ + b) * HD_ * S_;
    const __nv_bfloat16* Vbase_l = d_Vtl + (size_t)(h * B_ + b) * HD_ * S_;
    const __nv_bfloat16* APtr[3] = {Abase_h, Abase_h, Abase_l};
    const __nv_bfloat16* BPtr[3] = {Vbase_h, Vbase_l, Vbase_h};

    float acc[2][8][4];
#pragma unroll
    for (int i = 0; i < 2; i++)
#pragma unroll
        for (int j = 0; j < 8; j++)
#pragma unroll
            for (int c = 0; c < 4; c++) acc[i][j][c] = 0.0f;

    const int a_r  = lane & 15;
    const int a_k8 = ((lane >> 4) & 1) * 8;
    const int b_r  = ((lane >> 4) << 3) + (lane & 7);
    const int b_k8 = ((lane >> 3) & 1) * 8;

    uint4 pa0, pa1, pb0, pb1;
    const int NITER = 3 * KT;

    {
        const __nv_bfloat16* Ag = APtr[0] + (size_t)s0 * S_;
        const __nv_bfloat16* Bg = BPtr[0];
        int ia0 = tid, ia1 = tid + 256;
        pa0 = *(const uint4*)(Ag + (size_t)(ia0 >> 2) * S_ + (ia0 & 3) * 8);
        pa1 = *(const uint4*)(Ag + (size_t)(ia1 >> 2) * S_ + (ia1 & 3) * 8);
        pb0 = *(const uint4*)(Bg + (size_t)(ia0 >> 2) * S_ + (ia0 & 3) * 8);
        pb1 = *(const uint4*)(Bg + (size_t)(ia1 >> 2) * S_ + (ia1 & 3) * 8);
    }

    for (int it = 0; it < NITER; it++) {
        {
            int ia0 = tid, ia1 = tid + 256;
            *(uint4*)&AsB[(ia0 >> 2) * T_LDS + (ia0 & 3) * 8] = pa0;
            *(uint4*)&AsB[(ia1 >> 2) * T_LDS + (ia1 & 3) * 8] = pa1;
            *(uint4*)&BtB[(ia0 >> 2) * T_LDS + (ia0 & 3) * 8] = pb0;
            *(uint4*)&BtB[(ia1 >> 2) * T_LDS + (ia1 & 3) * 8] = pb1;
        }
        __syncthreads();

        if (it + 1 < NITER) {
            int nit = it + 1;
            int term = nit / KT;
            int kk = (nit - term * KT) * 32;
            const __nv_bfloat16* Ag = APtr[term] + (size_t)s0 * S_ + kk;
            const __nv_bfloat16* Bg = BPtr[term] + kk;
            int ia0 = tid, ia1 = tid + 256;
            pa0 = *(const uint4*)(Ag + (size_t)(ia0 >> 2) * S_ + (ia0 & 3) * 8);
            pa1 = *(const uint4*)(Ag + (size_t)(ia1 >> 2) * S_ + (ia1 & 3) * 8);
            pb0 = *(const uint4*)(Bg + (size_t)(ia0 >> 2) * S_ + (ia0 & 3) * 8);
            pb1 = *(const uint4*)(Bg + (size_t)(ia1 >> 2) * S_ + (ia1 & 3) * 8);
        }

#pragma unroll
        for (int ks = 0; ks < 2; ks++) {
            const int kb = ks * 16;
            unsigned int af[2][4];
#pragma unroll
            for (int mi = 0; mi < 2; mi++) {
                int row = wm * 32 + mi * 16 + a_r;
                unsigned int addr = asbase + (unsigned int)(row * T_LDS + kb + a_k8) * 2;
                ldsm4(af[mi][0], af[mi][1], af[mi][2], af[mi][3], addr);
            }
#pragma unroll
            for (int nj = 0; nj < 4; nj++) {
                int nrow = wn * 64 + nj * 16 + b_r;
                unsigned int addr = bsbase + (unsigned int)(nrow * T_LDS + kb + b_k8) * 2;
                unsigned int bf[4];
                ldsm4(bf[0], bf[1], bf[2], bf[3], addr);
#pragma unroll
                for (int mi = 0; mi < 2; mi++) {
                    mma16816(acc[mi][nj * 2 + 0], af[mi], &bf[0]);
                    mma16816(acc[mi][nj * 2 + 1], af[mi], &bf[2]);
                }
            }
        }
        __syncthreads();
    }

    const float* suf = d_suf + ((size_t)(h * B_ + b) * NSB + si) * HD_;
    const int qr = lane >> 2;
    const int qc = (lane & 3) * 2;
#pragma unroll
    for (int mi = 0; mi < 2; mi++) {
#pragma unroll
        for (int n8 = 0; n8 < 8; n8++) {
            int e = wn * 64 + n8 * 8 + qc;
            float sv1 = suf[e], sv2 = suf[e + 1];
            int s = s0 + wm * 32 + mi * 16 + qr;
            float2 v0; v0.x = acc[mi][n8][0] + sv1; v0.y = acc[mi][n8][1] + sv2;
            float2 v1; v1.x = acc[mi][n8][2] + sv1; v1.y = acc[mi][n8][3] + sv2;
            *(float2*)&d_O[(size_t)(b * S_ + s) * DIM_ + h * HD_ + e] = v0;
            *(float2*)&d_O[(size_t)(b * S_ + s + 8) * DIM_ + h * HD_ + e] = v1;
        }
    }
}

// ---------------- tensor-core FF GEMM (R10-proven) -----
#define FF_K   DIM_
__global__ __launch_bounds__(256, 2)
void ff_tensor_kernel(float* __restrict__ outParam, int mode) {
    const __nv_bfloat16* Ahp = d_xh;
    const __nv_bfloat16* Alp = d_xl;
    const __nv_bfloat16* Bhp = (mode == 0) ? d_wgh : d_woh;
    const __nv_bfloat16* Blp = (mode == 0) ? d_wgl : d_wol;
    float* Cm = (mode == 0) ? d_G : outParam;

    const int n0 = blockIdx.x * 128;
    const int m0 = blockIdx.y * 128;

    __shared__ __align__(16) unsigned short AsB[128 * T_LDS];
    __shared__ __align__(16) unsigned short BtB[128 * T_LDS];

    const int tid  = threadIdx.x;
    const int wid  = tid >> 5;
    const int lane = tid & 31;
    const int wm = wid & 3;
    const int wn = wid >> 2;

    const unsigned int asbase = (unsigned int)__cvta_generic_to_shared(AsB);
    const unsigned int bsbase = (unsigned int)__cvta_generic_to_shared(BtB);

    const __nv_bfloat16* APtr[3] = {Ahp, Ahp, Alp};
    const __nv_bfloat16* BPtr[3] = {Bhp, Blp, Bhp};

    float acc[2][8][4];
#pragma unroll
    for (int i = 0; i < 2; i++)
#pragma unroll
        for (int j = 0; j < 8; j++)
#pragma unroll
            for (int c = 0; c < 4; c++) acc[i][j][c] = 0.0f;

    const int a_r  = lane & 15;
    const int a_k8 = ((lane >> 4) & 1) * 8;
    const int b_r  = ((lane >> 4) << 3) + (lane & 7);
    const int b_k8 = ((lane >> 3) & 1) * 8;

    uint4 pa0, pa1, pb0, pb1;
    const int NITER = 3 * (FF_K / 32);

    {
        const __nv_bfloat16* Ag = APtr[0] + (size_t)m0 * FF_K;
        const __nv_bfloat16* Bg = BPtr[0] + (size_t)n0 * FF_K;
        int ia0 = tid, ia1 = tid + 256;
        pa0 = *(const uint4*)(Ag + (size_t)(ia0 >> 2) * FF_K + (ia0 & 3) * 8);
        pa1 = *(const uint4*)(Ag + (size_t)(ia1 >> 2) * FF_K + (ia1 & 3) * 8);
        pb0 = *(const uint4*)(Bg + (size_t)(ia0 >> 2) * FF_K + (ia0 & 3) * 8);
        pb1 = *(const uint4*)(Bg + (size_t)(ia1 >> 2) * FF_K + (ia1 & 3) * 8);
    }

    for (int it = 0; it < NITER; it++) {
        {
            int ia0 = tid, ia1 = tid + 256;
            *(uint4*)&AsB[(ia0 >> 2) * T_LDS + (ia0 & 3) * 8] = pa0;
            *(uint4*)&AsB[(ia1 >> 2) * T_LDS + (ia1 & 3) * 8] = pa1;
            *(uint4*)&BtB[(ia0 >> 2) * T_LDS + (ia0 & 3) * 8] = pb0;
            *(uint4*)&BtB[(ia1 >> 2) * T_LDS + (ia1 & 3) * 8] = pb1;
        }
        __syncthreads();

        if (it + 1 < NITER) {
            int nit = it + 1;
            int term = nit >> 6;
            int k0 = (nit & 63) * 32;
            const __nv_bfloat16* Ag = APtr[term] + (size_t)m0 * FF_K + k0;
            const __nv_bfloat16* Bg = BPtr[term] + (size_t)n0 * FF_K + k0;
            int ia0 = tid, ia1 = tid + 256;
            pa0 = *(const uint4*)(Ag + (size_t)(ia0 >> 2) * FF_K + (ia0 & 3) * 8);
            pa1 = *(const uint4*)(Ag + (size_t)(ia1 >> 2) * FF_K + (ia1 & 3) * 8);
            pb0 = *(const uint4*)(Bg + (size_t)(ia0 >> 2) * FF_K + (ia0 & 3) * 8);
            pb1 = *(const uint4*)(Bg + (size_t)(ia1 >> 2) * FF_K + (ia1 & 3) * 8);
        }

#pragma unroll
        for (int ks = 0; ks < 2; ks++) {
            const int kb = ks * 16;
            unsigned int af[2][4];
#pragma unroll
            for (int mi = 0; mi < 2; mi++) {
                int row = wm * 32 + mi * 16 + a_r;
                unsigned int addr = asbase + (unsigned int)(row * T_LDS + kb + a_k8) * 2;
                ldsm4(af[mi][0], af[mi][1], af[mi][2], af[mi][3], addr);
            }
#pragma unroll
            for (int nj = 0; nj < 4; nj++) {
                int nrow = wn * 64 + nj * 16 + b_r;
                unsigned int addr = bsbase + (unsigned int)(nrow * T_LDS + kb + b_k8) * 2;
                unsigned int bf[4];
                ldsm4(bf[0], bf[1], bf[2], bf[3], addr);
#pragma unroll
                for (int mi = 0; mi < 2; mi++) {
                    mma16816(acc[mi][nj * 2 + 0], af[mi], &bf[0]);
                    mma16816(acc[mi][nj * 2 + 1], af[mi], &bf[2]);
                }
            }
        }
        __syncthreads();
    }

    const int qr = lane >> 2;
    const int qc = (lane & 3) * 2;
#pragma unroll
    for (int mi = 0; mi < 2; mi++) {
#pragma unroll
        for (int n8 = 0; n8 < 8; n8++) {
            int m = m0 + wm * 32 + mi * 16 + qr;
            int n = n0 + wn * 64 + n8 * 8 + qc;
            float2 v0; v0.x = acc[mi][n8][0]; v0.y = acc[mi][n8][1];
            float2 v1; v1.x = acc[mi][n8][2]; v1.y = acc[mi][n8][3];
            if (mode == 0) {
                v0.x = fmaxf(v0.x, 0.f); v0.y = fmaxf(v0.y, 0.f);
                v1.x = fmaxf(v1.x, 0.f); v1.y = fmaxf(v1.y, 0.f);
            }
            *(float2*)&Cm[(size_t)m * DIM_ + n] = v0;
            *(float2*)&Cm[(size_t)(m + 8) * DIM_ + n] = v1;
        }
    }
}

// ---------------- layernorm + gate mul, fused bf16 hi/lo output ----------
// reads d_O (LN source) and d_G (gate); writes G*Y split into d_xh/d_xl
__global__ void gn_kernel(const float* __restrict__ gamma,
                          const float* __restrict__ beta) {
    const int row = blockIdx.x;
    const float* orow = d_O + (size_t)row * DIM_;
    const float* grow = d_G + (size_t)row * DIM_;
    __nv_bfloat16* hrow = d_xh + (size_t)row * DIM_;
    __nv_bfloat16* lrow = d_xl + (size_t)row * DIM_;
    const int tid = threadIdx.x;

    float v[8];
#pragma unroll
    for (int i = 0; i < 2; i++) {
        float4 t = *(const float4*)&orow[tid * 8 + i * 4];
        v[i * 4 + 0] = t.x; v[i * 4 + 1] = t.y;
        v[i * 4 + 2] = t.z; v[i * 4 + 3] = t.w;
    }

    __shared__ float red[8];
    __shared__ float s_mu, s_inv;

    float lsum = 0.f;
#pragma unroll
    for (int i = 0; i < 8; i++) lsum += v[i];
#pragma unroll
    for (int off = 16; off > 0; off >>= 1) lsum += __shfl_xor_sync(0xffffffffu, lsum, off);
    if ((tid & 31) == 0) red[tid >> 5] = lsum;
    __syncthreads();
    if (tid == 0) {
        float s = 0.f;
#pragma unroll
        for (int w = 0; w < 8; w++) s += red[w];
        s_mu = s * (1.0f / DIM_);
    }
    __syncthreads();
    const float mu = s_mu;

    float lsq = 0.f;
#pragma unroll
    for (int i = 0; i < 8; i++) {
        float d = v[i] - mu;
        lsq += d * d;
    }
#pragma unroll
    for (int off = 16; off > 0; off >>= 1) lsq += __shfl_xor_sync(0xffffffffu, lsq, off);
    __syncthreads();
    if ((tid & 31) == 0) red[tid >> 5] = lsq;
    __syncthreads();
    if (tid == 0) {
        float s = 0.f;
#pragma unroll
        for (int w = 0; w < 8; w++) s += red[w];
        s_inv = rsqrtf(s * (1.0f / DIM_) + 1e-3f);
    }
    __syncthreads();
    const float inv = s_inv;

#pragma unroll
    for (int i = 0; i < 2; i++) {
        int c0 = tid * 8 + i * 4;
        float4 g4 = *(const float4*)&grow[c0];
        float4 gm = *(const float4*)&gamma[c0];
        float4 bt = *(const float4*)&beta[c0];
        float o0 = g4.x * ((v[i * 4 + 0] - mu) * inv * gm.x + bt.x);
        float o1 = g4.y * ((v[i * 4 + 1] - mu) * inv * gm.y + bt.y);
        float o2 = g4.z * ((v[i * 4 + 2] - mu) * inv * gm.z + bt.z);
        float o3 = g4.w * ((v[i * 4 + 3] - mu) * inv * gm.w + bt.w);
        __nv_bfloat16 h0 = __float2bfloat16(o0);
        __nv_bfloat16 h1 = __float2bfloat16(o1);
        __nv_bfloat16 h2 = __float2bfloat16(o2);
        __nv_bfloat16 h3 = __float2bfloat16(o3);
        __nv_bfloat16 l0 = __float2bfloat16(o0 - __bfloat162float(h0));
        __nv_bfloat16 l1 = __float2bfloat16(o1 - __bfloat162float(h1));
        __nv_bfloat16 l2 = __float2bfloat16(o2 - __bfloat162float(h2));
        __nv_bfloat16 l3 = __float2bfloat16(o3 - __bfloat162float(h3));
        __nv_bfloat162 hA; hA.x = h0; hA.y = h1;
        __nv_bfloat162 hB; hB.x = h2; hB.y = h3;
        __nv_bfloat162 lA; lA.x = l0; lA.y = l1;
        __nv_bfloat162 lB; lB.x = l2; lB.y = l3;
        *(__nv_bfloat162*)&hrow[c0]     = hA;
        *(__nv_bfloat162*)&hrow[c0 + 2] = hB;
        *(__nv_bfloat162*)&lrow[c0]     = lA;
        *(__nv_bfloat162*)&lrow[c0 + 2] = lB;
    }
}

// ---------------- launch ----------------
extern "C" void kernel_launch(void* const* d_in, const int* in_sizes, int n_in,
                              void* d_out, int out_size) {
    const float* x     = (const float*)d_in[0];
    const float* k     = (const float*)d_in[1];
    const float* v     = (const float*)d_in[2];
    const float* Wh    = (const float*)d_in[3];
    const float* wg_w  = (const float*)d_in[4];
    const float* wo_w  = (const float*)d_in[5];
    const float* gamma = (const float*)d_in[6];
    const float* beta  = (const float*)d_in[7];
    float* out = (float*)d_out;

    decay_kernel<<<H_, S_>>>();
    // splits for qkv + ff1 operands
    split_kernel<<<(BSTOT * (DIM_ / 4)) / 256, 256>>>(x, 0);
    split_kernel<<<(BSTOT * (DIM_ / 4)) / 256, 256>>>(k, 4);
    split_kernel<<<(BSTOT * (DIM_ / 4)) / 256, 256>>>(v, 5);
    whtrans_kernel<<<dim3(HD_ / 32, HD_ / 32, H_), dim3(32, 8)>>>(Wh);
    wtrans_kernel<<<dim3(DIM_ / 32, DIM_ / 32), dim3(32, 8)>>>(wg_w, 0);
    wtrans_kernel<<<dim3(DIM_ / 32, DIM_ / 32), dim3(32, 8)>>>(wo_w, 1);

    qkv_tensor_kernel<<<dim3(BSTOT / 128, H_, 3), 256>>>();
    vtrans_kernel<<<dim3(HD_ / 32, S_ / 32, H_ * B_), dim3(32, 8)>>>();
    bsum_kernel<<<dim3(H_ * B_, NSB), HD_>>>();
    sufscan_kernel<<<H_ * B_, HD_>>>();
    scores_tensor_kernel<<<dim3(NTRI, H_), 256>>>();

    ff_tensor_kernel<<<dim3(DIM_ / 128, BSTOT / 128), 256>>>(out, 0);  // d_G = relu(x@wg)
    ogemm_tensor_kernel<<<dim3(NSB, B_ * H_), 256>>>();
    gn_kernel<<<BSTOT, 256>>>(gamma, beta);                            // -> d_xh/d_xl
    ff_tensor_kernel<<<dim3(DIM_ / 128, BSTOT / 128), 256>>>(out, 1);  // out = G@wo
}

// round 13
// speedup vs baseline: 1.3934x; 1.3934x over previous
#include <cuda_runtime.h>
#include <cuda_bf16.h>
#include <math.h>
#include <cstdint>
#include <stdint.h>

#define B_    4
#define S_    1024
#define DIM_  2048
#define H_    16
#define HD_   128
#define BSTOT 4096   // B_*S_
#define NSB   8      // S_/128 blocks
#define NTRI  36     // lower-tri 128x128 tiles per head

// ---------------- scratch ----------------
__device__ float d_V[(size_t)H_*B_*S_*HD_];      // fp32 V (for suffix sums)
__device__ float d_O[(size_t)BSTOT*DIM_];
__device__ float d_G[(size_t)BSTOT*DIM_];        // relu(x@wg) fp32
__device__ float d_bsum[(size_t)H_*B_*NSB*HD_];
__device__ float d_suf[(size_t)H_*B_*NSB*HD_];
__device__ float d_rs[H_*S_];
__device__ float d_l2g[H_];
// bf16 hi/lo operand buffers
__device__ __nv_bfloat16 d_Qh[(size_t)H_*B_*S_*HD_];  // [h,b,s,e]
__device__ __nv_bfloat16 d_Ql[(size_t)H_*B_*S_*HD_];
__device__ __nv_bfloat16 d_Kh[(size_t)H_*B_*S_*HD_];  // [h,b,t,e]
__device__ __nv_bfloat16 d_Kl[(size_t)H_*B_*S_*HD_];
__device__ __nv_bfloat16 d_Vth[(size_t)H_*B_*HD_*S_]; // V^T [h,b,e,t]
__device__ __nv_bfloat16 d_Vtl[(size_t)H_*B_*HD_*S_];
__device__ __nv_bfloat16 d_Ahh[(size_t)H_*S_*S_];     // A [h,s,t] hi
__device__ __nv_bfloat16 d_Ahl[(size_t)H_*S_*S_];     // A lo
__device__ __nv_bfloat16 d_xh[(size_t)BSTOT*DIM_];    // x hi, later G*Y hi [m][k]
__device__ __nv_bfloat16 d_xl[(size_t)BSTOT*DIM_];
__device__ __nv_bfloat16 d_wgh[(size_t)DIM_*DIM_];    // wg^T [n][k]
__device__ __nv_bfloat16 d_wgl[(size_t)DIM_*DIM_];
__device__ __nv_bfloat16 d_woh[(size_t)DIM_*DIM_];
__device__ __nv_bfloat16 d_wol[(size_t)DIM_*DIM_];

// ---------------- decay tables ----------------
__global__ void decay_kernel() {
    int h = blockIdx.x;
    int j = threadIdx.x;
    double g  = 1.0 - exp2((double)(-5 - h));
    double r  = 1.0 / g;
    double rp = pow(r, (double)(j + 1));
    double Sj = (rp - 1.0) / (r - 1.0);
    d_rs[h * S_ + j] = (float)(1.0 / sqrt(Sj));
    if (j == 0) d_l2g[h] = (float)log2(g);
}

// ---------------- fp32 -> (hi,lo) bf16 split (x only) ----------------
__global__ void split_kernel(const float* __restrict__ srcParam) {
    const float* src = srcParam;
    __nv_bfloat16* hi = d_xh;
    __nv_bfloat16* lo = d_xl;
    size_t i = (size_t)(blockIdx.x) * blockDim.x + threadIdx.x;
    float4 v = ((const float4*)src)[i];
    __nv_bfloat16 h0 = __float2bfloat16(v.x);
    __nv_bfloat16 h1 = __float2bfloat16(v.y);
    __nv_bfloat16 h2 = __float2bfloat16(v.z);
    __nv_bfloat16 h3 = __float2bfloat16(v.w);
    __nv_bfloat16 l0 = __float2bfloat16(v.x - __bfloat162float(h0));
    __nv_bfloat16 l1 = __float2bfloat16(v.y - __bfloat162float(h1));
    __nv_bfloat16 l2 = __float2bfloat16(v.z - __bfloat162float(h2));
    __nv_bfloat16 l3 = __float2bfloat16(v.w - __bfloat162float(h3));
    __nv_bfloat162 hA; hA.x = h0; hA.y = h1;
    __nv_bfloat162 hB; hB.x = h2; hB.y = h3;
    __nv_bfloat162 lA; lA.x = l0; lA.y = l1;
    __nv_bfloat162 lB; lB.x = l2; lB.y = l3;
    *(__nv_bfloat162*)&hi[i * 4]     = hA;
    *(__nv_bfloat162*)&hi[i * 4 + 2] = hB;
    *(__nv_bfloat162*)&lo[i * 4]     = lA;
    *(__nv_bfloat162*)&lo[i * 4 + 2] = lB;
}

// ---------------- weight transpose + split ----
__global__ void wtrans_kernel(const float* __restrict__ w, int which) {
    __nv_bfloat16* hi = (which == 0) ? d_wgh : d_woh;
    __nv_bfloat16* lo = (which == 0) ? d_wgl : d_wol;
    __shared__ float tile[32][33];
    const int bx = blockIdx.x * 32;
    const int by = blockIdx.y * 32;
    const int tx = threadIdx.x;
    const int ty = threadIdx.y;
#pragma unroll
    for (int i = 0; i < 4; i++) {
        int r = ty * 4 + i;
        tile[r][tx] = w[(size_t)(by + r) * DIM_ + bx + tx];
    }
    __syncthreads();
#pragma unroll
    for (int i = 0; i < 4; i++) {
        int nl = ty * 4 + i;
        float vv = tile[tx][nl];
        __nv_bfloat16 hv = __float2bfloat16(vv);
        __nv_bfloat16 lv = __float2bfloat16(vv - __bfloat162float(hv));
        size_t idx = (size_t)(bx + nl) * DIM_ + by + tx;
        hi[idx] = hv;
        lo[idx] = lv;
    }
}

// ---------------- QKV projection: fp32 math, bf16 hi/lo outputs (R11) ----
__global__ void qkv_kernel(const float* __restrict__ x,
                           const float* __restrict__ kin,
                           const float* __restrict__ vin,
                           const float* __restrict__ Wh) {
    const int h     = blockIdx.y;
    const int which = blockIdx.z;
    const float* src = (which == 0) ? x : (which == 1) ? kin : vin;
    const int m0 = blockIdx.x * 64;

    __shared__ float Xs[32][68];
    __shared__ float Ws[32][128];

    const int tid = threadIdx.x;
    const int tx = tid & 15, ty = tid >> 4;
    float acc[4][8];
#pragma unroll
    for (int i = 0; i < 4; i++)
#pragma unroll
        for (int j = 0; j < 8; j++) acc[i][j] = 0.0f;

    for (int k0 = 0; k0 < HD_; k0 += 32) {
#pragma unroll
        for (int i = 0; i < 2; i++) {
            int idx = tid + i * 256;
            int r = idx >> 3, c4 = idx & 7;
            int row = m0 + r;
            int b = row >> 10, s = row & 1023;
            float4 vv = *(const float4*)&src[(size_t)(b * S_ + s) * DIM_ + h * HD_ + k0 + c4 * 4];
            Xs[c4 * 4 + 0][r] = vv.x;
            Xs[c4 * 4 + 1][r] = vv.y;
            Xs[c4 * 4 + 2][r] = vv.z;
            Xs[c4 * 4 + 3][r] = vv.w;
        }
#pragma unroll
        for (int i = 0; i < 4; i++) {
            int idx = tid + i * 256;
            int r = idx >> 5, c4 = idx & 31;
            *(float4*)&Ws[r][c4 * 4] =
                *(const float4*)&Wh[((size_t)h * HD_ + k0 + r) * HD_ + c4 * 4];
        }
        __syncthreads();
#pragma unroll
        for (int kk = 0; kk < 32; kk++) {
            float4 a4 = *(float4*)&Xs[kk][ty * 4];
            float a[4] = {a4.x, a4.y, a4.z, a4.w};
            float4 b0 = *(float4*)&Ws[kk][tx * 8];
            float4 b1 = *(float4*)&Ws[kk][tx * 8 + 4];
            float bb[8] = {b0.x, b0.y, b0.z, b0.w, b1.x, b1.y, b1.z, b1.w};
#pragma unroll
            for (int i = 0; i < 4; i++)
#pragma unroll
                for (int j = 0; j < 8; j++) acc[i][j] += a[i] * bb[j];
        }
        __syncthreads();
    }

    const int b = m0 >> 10;
    const int sl = m0 & 1023;
    if (which < 2) {
        __nv_bfloat16* hid = (which == 0) ? d_Qh : d_Kh;
        __nv_bfloat16* lod = (which == 0) ? d_Ql : d_Kl;
#pragma unroll
        for (int i = 0; i < 4; i++) {
            int s = sl + ty * 4 + i;
            __nv_bfloat16 hp[8], lp[8];
#pragma unroll
            for (int j = 0; j < 8; j++) {
                hp[j] = __float2bfloat16(acc[i][j]);
                lp[j] = __float2bfloat16(acc[i][j] - __bfloat162float(hp[j]));
            }
            size_t off = ((size_t)(h * B_ + b) * S_ + s) * HD_ + tx * 8;
            *(uint4*)&hid[off] = *(uint4*)hp;
            *(uint4*)&lod[off] = *(uint4*)lp;
        }
    } else {
#pragma unroll
        for (int i = 0; i < 4; i++) {
            int s = sl + ty * 4 + i;
            float* drow = d_V + ((size_t)(h * B_ + b) * S_ + s) * HD_ + tx * 8;
            float4 o0 = {acc[i][0], acc[i][1], acc[i][2], acc[i][3]};
            float4 o1 = {acc[i][4], acc[i][5], acc[i][6], acc[i][7]};
            *(float4*)&drow[0] = o0;
            *(float4*)&drow[4] = o1;
        }
        int s4 = sl + ty * 4;
#pragma unroll
        for (int j = 0; j < 8; j++) {
            int e = tx * 8 + j;
            __nv_bfloat16 hp[4], lp[4];
#pragma unroll
            for (int i = 0; i < 4; i++) {
                hp[i] = __float2bfloat16(acc[i][j]);
                lp[i] = __float2bfloat16(acc[i][j] - __bfloat162float(hp[i]));
            }
            size_t off = ((size_t)(h * B_ + b) * HD_ + e) * S_ + s4;
            *(uint2*)&d_Vth[off] = *(uint2*)hp;
            *(uint2*)&d_Vtl[off] = *(uint2*)lp;
        }
    }
}

// ---------------- suffix phase A ----------
__global__ void bsum_kernel() {
    const int hb = blockIdx.x;
    const int i  = blockIdx.y;
    const int e  = threadIdx.x;
    const float* blk = d_V + ((size_t)hb * S_ + i * 128) * HD_;
    float a0 = 0.f, a1 = 0.f, a2 = 0.f, a3 = 0.f;
#pragma unroll 8
    for (int t = 0; t < 128; t += 4) {
        a0 += blk[(t + 0) * HD_ + e];
        a1 += blk[(t + 1) * HD_ + e];
        a2 += blk[(t + 2) * HD_ + e];
        a3 += blk[(t + 3) * HD_ + e];
    }
    d_bsum[((size_t)hb * NSB + i) * HD_ + e] = (a0 + a1) + (a2 + a3);
}

// ---------------- suffix phase B ----
__global__ void sufscan_kernel() {
    const int hb = blockIdx.x;
    const int e  = threadIdx.x;
    float acc = 0.f;
#pragma unroll
    for (int i = NSB - 1; i >= 0; i--) {
        d_suf[((size_t)hb * NSB + i) * HD_ + e] = acc;
        acc += d_bsum[((size_t)hb * NSB + i) * HD_ + e];
    }
}

// ---------------- shared mma helpers ----------
#define T_LDS 40
__device__ __forceinline__ void ldsm4(unsigned int& r0, unsigned int& r1,
                                      unsigned int& r2, unsigned int& r3, unsigned int addr) {
    asm volatile("ldmatrix.sync.aligned.m8n8.x4.shared.b16 {%0,%1,%2,%3}, [%4];"
                 : "=r"(r0), "=r"(r1), "=r"(r2), "=r"(r3) : "r"(addr));
}
__device__ __forceinline__ void mma16816(float* c, const unsigned int* a, const unsigned int* b) {
    asm volatile("mma.sync.aligned.m16n8k16.row.col.f32.bf16.bf16.f32 "
                 "{%0,%1,%2,%3}, {%4,%5,%6,%7}, {%8,%9}, {%0,%1,%2,%3};"
                 : "+f"(c[0]), "+f"(c[1]), "+f"(c[2]), "+f"(c[3])
                 : "r"(a[0]), "r"(a[1]), "r"(a[2]), "r"(a[3]), "r"(b[0]), "r"(b[1]));
}

// ---------------- scores tensor kernel (R11-proven) ----------
__global__ __launch_bounds__(256, 2)
void scores_tensor_kernel() {
    const int h = blockIdx.y;
    int kidx = blockIdx.x;
    int si = 0;
    while ((si + 1) * (si + 2) / 2 <= kidx) si++;
    const int tj = kidx - si * (si + 1) / 2;
    const int s0 = si * 128, t0 = tj * 128;

    __shared__ __align__(16) unsigned short AsB[128 * T_LDS];
    __shared__ __align__(16) unsigned short BtB[128 * T_LDS];

    const int tid  = threadIdx.x;
    const int wid  = tid >> 5;
    const int lane = tid & 31;
    const int wm = wid & 3;
    const int wn = wid >> 2;

    const unsigned int asbase = (unsigned int)__cvta_generic_to_shared(AsB);
    const unsigned int bsbase = (unsigned int)__cvta_generic_to_shared(BtB);

    const __nv_bfloat16* APtr[3] = {d_Qh, d_Qh, d_Ql};
    const __nv_bfloat16* BPtr[3] = {d_Kh, d_Kl, d_Kh};

    float acc[2][8][4];
#pragma unroll
    for (int i = 0; i < 2; i++)
#pragma unroll
        for (int j = 0; j < 8; j++)
#pragma unroll
            for (int c = 0; c < 4; c++) acc[i][j][c] = 0.0f;

    const int a_r  = lane & 15;
    const int a_k8 = ((lane >> 4) & 1) * 8;
    const int b_r  = ((lane >> 4) << 3) + (lane & 7);
    const int b_k8 = ((lane >> 3) & 1) * 8;

    uint4 pa0, pa1, pb0, pb1;
    const int NITER = 48;

    {
        const __nv_bfloat16* Ag = APtr[0] + ((size_t)(h * B_) * S_ + s0) * HD_;
        const __nv_bfloat16* Bg = BPtr[0] + ((size_t)(h * B_) * S_ + t0) * HD_;
        int ia0 = tid, ia1 = tid + 256;
        pa0 = *(const uint4*)(Ag + (size_t)(ia0 >> 2) * HD_ + (ia0 & 3) * 8);
        pa1 = *(const uint4*)(Ag + (size_t)(ia1 >> 2) * HD_ + (ia1 & 3) * 8);
        pb0 = *(const uint4*)(Bg + (size_t)(ia0 >> 2) * HD_ + (ia0 & 3) * 8);
        pb1 = *(const uint4*)(Bg + (size_t)(ia1 >> 2) * HD_ + (ia1 & 3) * 8);
    }

    for (int it = 0; it < NITER; it++) {
        {
            int ia0 = tid, ia1 = tid + 256;
            *(uint4*)&AsB[(ia0 >> 2) * T_LDS + (ia0 & 3) * 8] = pa0;
            *(uint4*)&AsB[(ia1 >> 2) * T_LDS + (ia1 & 3) * 8] = pa1;
            *(uint4*)&BtB[(ia0 >> 2) * T_LDS + (ia0 & 3) * 8] = pb0;
            *(uint4*)&BtB[(ia1 >> 2) * T_LDS + (ia1 & 3) * 8] = pb1;
        }
        __syncthreads();

        if (it + 1 < NITER) {
            int nit = it + 1;
            int term = nit >> 4;
            int kk = (nit & 15) * 32;
            int b = kk >> 7, e0 = kk & 127;
            const __nv_bfloat16* Ag = APtr[term] + ((size_t)(h * B_ + b) * S_ + s0) * HD_ + e0;
            const __nv_bfloat16* Bg = BPtr[term] + ((size_t)(h * B_ + b) * S_ + t0) * HD_ + e0;
            int ia0 = tid, ia1 = tid + 256;
            pa0 = *(const uint4*)(Ag + (size_t)(ia0 >> 2) * HD_ + (ia0 & 3) * 8);
            pa1 = *(const uint4*)(Ag + (size_t)(ia1 >> 2) * HD_ + (ia1 & 3) * 8);
            pb0 = *(const uint4*)(Bg + (size_t)(ia0 >> 2) * HD_ + (ia0 & 3) * 8);
            pb1 = *(const uint4*)(Bg + (size_t)(ia1 >> 2) * HD_ + (ia1 & 3) * 8);
        }

#pragma unroll
        for (int ks = 0; ks < 2; ks++) {
            const int kb = ks * 16;
            unsigned int af[2][4];
#pragma unroll
            for (int mi = 0; mi < 2; mi++) {
                int row = wm * 32 + mi * 16 + a_r;
                unsigned int addr = asbase + (unsigned int)(row * T_LDS + kb + a_k8) * 2;
                ldsm4(af[mi][0], af[mi][1], af[mi][2], af[mi][3], addr);
            }
#pragma unroll
            for (int nj = 0; nj < 4; nj++) {
                int nrow = wn * 64 + nj * 16 + b_r;
                unsigned int addr = bsbase + (unsigned int)(nrow * T_LDS + kb + b_k8) * 2;
                unsigned int bf[4];
                ldsm4(bf[0], bf[1], bf[2], bf[3], addr);
#pragma unroll
                for (int mi = 0; mi < 2; mi++) {
                    mma16816(acc[mi][nj * 2 + 0], af[mi], &bf[0]);
                    mma16816(acc[mi][nj * 2 + 1], af[mi], &bf[2]);
                }
            }
        }
        __syncthreads();
    }

    const float l2g = d_l2g[h];
    const float inv_sqrt_hd = 0.08838834764831845f;
    __nv_bfloat16* Ahh = d_Ahh + (size_t)h * S_ * S_;
    __nv_bfloat16* Ahl = d_Ahl + (size_t)h * S_ * S_;
    const int qr = lane >> 2;
    const int qc = (lane & 3) * 2;
#pragma unroll
    for (int mi = 0; mi < 2; mi++) {
#pragma unroll
        for (int n8 = 0; n8 < 8; n8++) {
            int t1 = t0 + wn * 64 + n8 * 8 + qc;
            float rs1 = d_rs[h * S_ + t1];
            float rs2 = d_rs[h * S_ + t1 + 1];
#pragma unroll
            for (int half = 0; half < 2; half++) {
                int s = s0 + wm * 32 + mi * 16 + qr + half * 8;
                float a1 = acc[mi][n8][half * 2 + 0];
                float a2 = acc[mi][n8][half * 2 + 1];
                float v1 = (t1 > s) ? 1.0f
                   : fmaxf(fabsf(a1 * inv_sqrt_hd * exp2f((float)(t1 - s) * l2g) * rs1), 1.0f);
                float v2 = (t1 + 1 > s) ? 1.0f
                   : fmaxf(fabsf(a2 * inv_sqrt_hd * exp2f((float)(t1 + 1 - s) * l2g) * rs2), 1.0f);
                __nv_bfloat16 h1 = __float2bfloat16(v1);
                __nv_bfloat16 h2 = __float2bfloat16(v2);
                __nv_bfloat16 l1 = __float2bfloat16(v1 - __bfloat162float(h1));
                __nv_bfloat16 l2 = __float2bfloat16(v2 - __bfloat162float(h2));
                __nv_bfloat162 hp; hp.x = h1; hp.y = h2;
                __nv_bfloat162 lp; lp.x = l1; lp.y = l2;
                *(__nv_bfloat162*)&Ahh[(size_t)s * S_ + t1] = hp;
                *(__nv_bfloat162*)&Ahl[(size_t)s * S_ + t1] = lp;
            }
        }
    }
}

// ---------------- ogemm tensor kernel (R11-proven) ---------
__global__ __launch_bounds__(256, 2)
void ogemm_tensor_kernel() {
    const int bh = blockIdx.y;
    const int b = bh >> 4, h = bh & 15;
    const int si = blockIdx.x;
    const int s0 = si * 128;
    const int KT = (si + 1) * 4;

    __shared__ __align__(16) unsigned short AsB[128 * T_LDS];
    __shared__ __align__(16) unsigned short BtB[128 * T_LDS];

    const int tid  = threadIdx.x;
    const int wid  = tid >> 5;
    const int lane = tid & 31;
    const int wm = wid & 3;
    const int wn = wid >> 2;

    const unsigned int asbase = (unsigned int)__cvta_generic_to_shared(AsB);
    const unsigned int bsbase = (unsigned int)__cvta_generic_to_shared(BtB);

    const __nv_bfloat16* Abase_h = d_Ahh + (size_t)h * S_ * S_;
    const __nv_bfloat16* Abase_l = d_Ahl + (size_t)h * S_ * S_;
    const __nv_bfloat16* Vbase_h = d_Vth + (size_t)(h * B_ + b) * HD_ * S_;
    const __nv_bfloat16* Vbase_l = d_Vtl + (size_t)(h * B_ + b) * HD_ * S_;
    const __nv_bfloat16* APtr[3] = {Abase_h, Abase_h, Abase_l};
    const __nv_bfloat16* BPtr[3] = {Vbase_h, Vbase_l, Vbase_h};

    float acc[2][8][4];
#pragma unroll
    for (int i = 0; i < 2; i++)
#pragma unroll
        for (int j = 0; j < 8; j++)
#pragma unroll
            for (int c = 0; c < 4; c++) acc[i][j][c] = 0.0f;

    const int a_r  = lane & 15;
    const int a_k8 = ((lane >> 4) & 1) * 8;
    const int b_r  = ((lane >> 4) << 3) + (lane & 7);
    const int b_k8 = ((lane >> 3) & 1) * 8;

    uint4 pa0, pa1, pb0, pb1;
    const int NITER = 3 * KT;

    {
        const __nv_bfloat16* Ag = APtr[0] + (size_t)s0 * S_;
        const __nv_bfloat16* Bg = BPtr[0];
        int ia0 = tid, ia1 = tid + 256;
        pa0 = *(const uint4*)(Ag + (size_t)(ia0 >> 2) * S_ + (ia0 & 3) * 8);
        pa1 = *(const uint4*)(Ag + (size_t)(ia1 >> 2) * S_ + (ia1 & 3) * 8);
        pb0 = *(const uint4*)(Bg + (size_t)(ia0 >> 2) * S_ + (ia0 & 3) * 8);
        pb1 = *(const uint4*)(Bg + (size_t)(ia1 >> 2) * S_ + (ia1 & 3) * 8);
    }

    for (int it = 0; it < NITER; it++) {
        {
            int ia0 = tid, ia1 = tid + 256;
            *(uint4*)&AsB[(ia0 >> 2) * T_LDS + (ia0 & 3) * 8] = pa0;
            *(uint4*)&AsB[(ia1 >> 2) * T_LDS + (ia1 & 3) * 8] = pa1;
            *(uint4*)&BtB[(ia0 >> 2) * T_LDS + (ia0 & 3) * 8] = pb0;
            *(uint4*)&BtB[(ia1 >> 2) * T_LDS + (ia1 & 3) * 8] = pb1;
        }
        __syncthreads();

        if (it + 1 < NITER) {
            int nit = it + 1;
            int term = nit / KT;
            int kk = (nit - term * KT) * 32;
            const __nv_bfloat16* Ag = APtr[term] + (size_t)s0 * S_ + kk;
            const __nv_bfloat16* Bg = BPtr[term] + kk;
            int ia0 = tid, ia1 = tid + 256;
            pa0 = *(const uint4*)(Ag + (size_t)(ia0 >> 2) * S_ + (ia0 & 3) * 8);
            pa1 = *(const uint4*)(Ag + (size_t)(ia1 >> 2) * S_ + (ia1 & 3) * 8);
            pb0 = *(const uint4*)(Bg + (size_t)(ia0 >> 2) * S_ + (ia0 & 3) * 8);
            pb1 = *(const uint4*)(Bg + (size_t)(ia1 >> 2) * S_ + (ia1 & 3) * 8);
        }

#pragma unroll
        for (int ks = 0; ks < 2; ks++) {
            const int kb = ks * 16;
            unsigned int af[2][4];
#pragma unroll
            for (int mi = 0; mi < 2; mi++) {
                int row = wm * 32 + mi * 16 + a_r;
                unsigned int addr = asbase + (unsigned int)(row * T_LDS + kb + a_k8) * 2;
                ldsm4(af[mi][0], af[mi][1], af[mi][2], af[mi][3], addr);
            }
#pragma unroll
            for (int nj = 0; nj < 4; nj++) {
                int nrow = wn * 64 + nj * 16 + b_r;
                unsigned int addr = bsbase + (unsigned int)(nrow * T_LDS + kb + b_k8) * 2;
                unsigned int bf[4];
                ldsm4(bf[0], bf[1], bf[2], bf[3], addr);
#pragma unroll
                for (int mi = 0; mi < 2; mi++) {
                    mma16816(acc[mi][nj * 2 + 0], af[mi], &bf[0]);
                    mma16816(acc[mi][nj * 2 + 1], af[mi], &bf[2]);
                }
            }
        }
        __syncthreads();
    }

    const float* suf = d_suf + ((size_t)(h * B_ + b) * NSB + si) * HD_;
    const int qr = lane >> 2;
    const int qc = (lane & 3) * 2;
#pragma unroll
    for (int mi = 0; mi < 2; mi++) {
#pragma unroll
        for (int n8 = 0; n8 < 8; n8++) {
            int e = wn * 64 + n8 * 8 + qc;
            float sv1 = suf[e], sv2 = suf[e + 1];
            int s = s0 + wm * 32 + mi * 16 + qr;
            float2 v0; v0.x = acc[mi][n8][0] + sv1; v0.y = acc[mi][n8][1] + sv2;
            float2 v1; v1.x = acc[mi][n8][2] + sv1; v1.y = acc[mi][n8][3] + sv2;
            *(float2*)&d_O[(size_t)(b * S_ + s) * DIM_ + h * HD_ + e] = v0;
            *(float2*)&d_O[(size_t)(b * S_ + s + 8) * DIM_ + h * HD_ + e] = v1;
        }
    }
}

// ---------------- tensor-core FF GEMM (R10-proven) -----
#define FF_K   DIM_
__global__ __launch_bounds__(256, 2)
void ff_tensor_kernel(float* __restrict__ outParam, int mode) {
    const __nv_bfloat16* Ahp = d_xh;
    const __nv_bfloat16* Alp = d_xl;
    const __nv_bfloat16* Bhp = (mode == 0) ? d_wgh : d_woh;
    const __nv_bfloat16* Blp = (mode == 0) ? d_wgl : d_wol;
    float* Cm = (mode == 0) ? d_G : outParam;

    const int n0 = blockIdx.x * 128;
    const int m0 = blockIdx.y * 128;

    __shared__ __align__(16) unsigned short AsB[128 * T_LDS];
    __shared__ __align__(16) unsigned short BtB[128 * T_LDS];

    const int tid  = threadIdx.x;
    const int wid  = tid >> 5;
    const int lane = tid & 31;
    const int wm = wid & 3;
    const int wn = wid >> 2;

    const unsigned int asbase = (unsigned int)__cvta_generic_to_shared(AsB);
    const unsigned int bsbase = (unsigned int)__cvta_generic_to_shared(BtB);

    const __nv_bfloat16* APtr[3] = {Ahp, Ahp, Alp};
    const __nv_bfloat16* BPtr[3] = {Bhp, Blp, Bhp};

    float acc[2][8][4];
#pragma unroll
    for (int i = 0; i < 2; i++)
#pragma unroll
        for (int j = 0; j < 8; j++)
#pragma unroll
            for (int c = 0; c < 4; c++) acc[i][j][c] = 0.0f;

    const int a_r  = lane & 15;
    const int a_k8 = ((lane >> 4) & 1) * 8;
    const int b_r  = ((lane >> 4) << 3) + (lane & 7);
    const int b_k8 = ((lane >> 3) & 1) * 8;

    uint4 pa0, pa1, pb0, pb1;
    const int NITER = 3 * (FF_K / 32);

    {
        const __nv_bfloat16* Ag = APtr[0] + (size_t)m0 * FF_K;
        const __nv_bfloat16* Bg = BPtr[0] + (size_t)n0 * FF_K;
        int ia0 = tid, ia1 = tid + 256;
        pa0 = *(const uint4*)(Ag + (size_t)(ia0 >> 2) * FF_K + (ia0 & 3) * 8);
        pa1 = *(const uint4*)(Ag + (size_t)(ia1 >> 2) * FF_K + (ia1 & 3) * 8);
        pb0 = *(const uint4*)(Bg + (size_t)(ia0 >> 2) * FF_K + (ia0 & 3) * 8);
        pb1 = *(const uint4*)(Bg + (size_t)(ia1 >> 2) * FF_K + (ia1 & 3) * 8);
    }

    for (int it = 0; it < NITER; it++) {
        {
            int ia0 = tid, ia1 = tid + 256;
            *(uint4*)&AsB[(ia0 >> 2) * T_LDS + (ia0 & 3) * 8] = pa0;
            *(uint4*)&AsB[(ia1 >> 2) * T_LDS + (ia1 & 3) * 8] = pa1;
            *(uint4*)&BtB[(ia0 >> 2) * T_LDS + (ia0 & 3) * 8] = pb0;
            *(uint4*)&BtB[(ia1 >> 2) * T_LDS + (ia1 & 3) * 8] = pb1;
        }
        __syncthreads();

        if (it + 1 < NITER) {
            int nit = it + 1;
            int term = nit >> 6;
            int k0 = (nit & 63) * 32;
            const __nv_bfloat16* Ag = APtr[term] + (size_t)m0 * FF_K + k0;
            const __nv_bfloat16* Bg = BPtr[term] + (size_t)n0 * FF_K + k0;
            int ia0 = tid, ia1 = tid + 256;
            pa0 = *(const uint4*)(Ag + (size_t)(ia0 >> 2) * FF_K + (ia0 & 3) * 8);
            pa1 = *(const uint4*)(Ag + (size_t)(ia1 >> 2) * FF_K + (ia1 & 3) * 8);
            pb0 = *(const uint4*)(Bg + (size_t)(ia0 >> 2) * FF_K + (ia0 & 3) * 8);
            pb1 = *(const uint4*)(Bg + (size_t)(ia1 >> 2) * FF_K + (ia1 & 3) * 8);
        }

#pragma unroll
        for (int ks = 0; ks < 2; ks++) {
            const int kb = ks * 16;
            unsigned int af[2][4];
#pragma unroll
            for (int mi = 0; mi < 2; mi++) {
                int row = wm * 32 + mi * 16 + a_r;
                unsigned int addr = asbase + (unsigned int)(row * T_LDS + kb + a_k8) * 2;
                ldsm4(af[mi][0], af[mi][1], af[mi][2], af[mi][3], addr);
            }
#pragma unroll
            for (int nj = 0; nj < 4; nj++) {
                int nrow = wn * 64 + nj * 16 + b_r;
                unsigned int addr = bsbase + (unsigned int)(nrow * T_LDS + kb + b_k8) * 2;
                unsigned int bf[4];
                ldsm4(bf[0], bf[1], bf[2], bf[3], addr);
#pragma unroll
                for (int mi = 0; mi < 2; mi++) {
                    mma16816(acc[mi][nj * 2 + 0], af[mi], &bf[0]);
                    mma16816(acc[mi][nj * 2 + 1], af[mi], &bf[2]);
                }
            }
        }
        __syncthreads();
    }

    const int qr = lane >> 2;
    const int qc = (lane & 3) * 2;
#pragma unroll
    for (int mi = 0; mi < 2; mi++) {
#pragma unroll
        for (int n8 = 0; n8 < 8; n8++) {
            int m = m0 + wm * 32 + mi * 16 + qr;
            int n = n0 + wn * 64 + n8 * 8 + qc;
            float2 v0; v0.x = acc[mi][n8][0]; v0.y = acc[mi][n8][1];
            float2 v1; v1.x = acc[mi][n8][2]; v1.y = acc[mi][n8][3];
            if (mode == 0) {
                v0.x = fmaxf(v0.x, 0.f); v0.y = fmaxf(v0.y, 0.f);
                v1.x = fmaxf(v1.x, 0.f); v1.y = fmaxf(v1.y, 0.f);
            }
            *(float2*)&Cm[(size_t)m * DIM_ + n] = v0;
            *(float2*)&Cm[(size_t)(m + 8) * DIM_ + n] = v1;
        }
    }
}

// ---------------- layernorm + gate mul, fused bf16 hi/lo output ----------
// reads d_O (LN source) and d_G (gate); writes G*Y split into d_xh/d_xl
__global__ void gn_kernel(const float* __restrict__ gamma,
                          const float* __restrict__ beta) {
    const int row = blockIdx.x;
    const float* orow = d_O + (size_t)row * DIM_;
    const float* grow = d_G + (size_t)row * DIM_;
    __nv_bfloat16* hrow = d_xh + (size_t)row * DIM_;
    __nv_bfloat16* lrow = d_xl + (size_t)row * DIM_;
    const int tid = threadIdx.x;

    float v[8];
#pragma unroll
    for (int i = 0; i < 2; i++) {
        float4 t = *(const float4*)&orow[tid * 8 + i * 4];
        v[i * 4 + 0] = t.x; v[i * 4 + 1] = t.y;
        v[i * 4 + 2] = t.z; v[i * 4 + 3] = t.w;
    }

    __shared__ float red[8];
    __shared__ float s_mu, s_inv;

    float lsum = 0.f;
#pragma unroll
    for (int i = 0; i < 8; i++) lsum += v[i];
#pragma unroll
    for (int off = 16; off > 0; off >>= 1) lsum += __shfl_xor_sync(0xffffffffu, lsum, off);
    if ((tid & 31) == 0) red[tid >> 5] = lsum;
    __syncthreads();
    if (tid == 0) {
        float s = 0.f;
#pragma unroll
        for (int w = 0; w < 8; w++) s += red[w];
        s_mu = s * (1.0f / DIM_);
    }
    __syncthreads();
    const float mu = s_mu;

    float lsq = 0.f;
#pragma unroll
    for (int i = 0; i < 8; i++) {
        float d = v[i] - mu;
        lsq += d * d;
    }
#pragma unroll
    for (int off = 16; off > 0; off >>= 1) lsq += __shfl_xor_sync(0xffffffffu, lsq, off);
    __syncthreads();
    if ((tid & 31) == 0) red[tid >> 5] = lsq;
    __syncthreads();
    if (tid == 0) {
        float s = 0.f;
#pragma unroll
        for (int w = 0; w < 8; w++) s += red[w];
        s_inv = rsqrtf(s * (1.0f / DIM_) + 1e-3f);
    }
    __syncthreads();
    const float inv = s_inv;

#pragma unroll
    for (int i = 0; i < 2; i++) {
        int c0 = tid * 8 + i * 4;
        float4 g4 = *(const float4*)&grow[c0];
        float4 gm = *(const float4*)&gamma[c0];
        float4 bt = *(const float4*)&beta[c0];
        float o0 = g4.x * ((v[i * 4 + 0] - mu) * inv * gm.x + bt.x);
        float o1 = g4.y * ((v[i * 4 + 1] - mu) * inv * gm.y + bt.y);
        float o2 = g4.z * ((v[i * 4 + 2] - mu) * inv * gm.z + bt.z);
        float o3 = g4.w * ((v[i * 4 + 3] - mu) * inv * gm.w + bt.w);
        __nv_bfloat16 h0 = __float2bfloat16(o0);
        __nv_bfloat16 h1 = __float2bfloat16(o1);
        __nv_bfloat16 h2 = __float2bfloat16(o2);
        __nv_bfloat16 h3 = __float2bfloat16(o3);
        __nv_bfloat16 l0 = __float2bfloat16(o0 - __bfloat162float(h0));
        __nv_bfloat16 l1 = __float2bfloat16(o1 - __bfloat162float(h1));
        __nv_bfloat16 l2 = __float2bfloat16(o2 - __bfloat162float(h2));
        __nv_bfloat16 l3 = __float2bfloat16(o3 - __bfloat162float(h3));
        __nv_bfloat162 hA; hA.x = h0; hA.y = h1;
        __nv_bfloat162 hB; hB.x = h2; hB.y = h3;
        __nv_bfloat162 lA; lA.x = l0; lA.y = l1;
        __nv_bfloat162 lB; lB.x = l2; lB.y = l3;
        *(__nv_bfloat162*)&hrow[c0]     = hA;
        *(__nv_bfloat162*)&hrow[c0 + 2] = hB;
        *(__nv_bfloat162*)&lrow[c0]     = lA;
        *(__nv_bfloat162*)&lrow[c0 + 2] = lB;
    }
}

// ---------------- launch ----------------
extern "C" void kernel_launch(void* const* d_in, const int* in_sizes, int n_in,
                              void* d_out, int out_size) {
    const float* x     = (const float*)d_in[0];
    const float* k     = (const float*)d_in[1];
    const float* v     = (const float*)d_in[2];
    const float* Wh    = (const float*)d_in[3];
    const float* wg_w  = (const float*)d_in[4];
    const float* wo_w  = (const float*)d_in[5];
    const float* gamma = (const float*)d_in[6];
    const float* beta  = (const float*)d_in[7];
    float* out = (float*)d_out;

    decay_kernel<<<H_, S_>>>();
    qkv_kernel<<<dim3(BSTOT / 64, H_, 3), 256>>>(x, k, v, Wh);
    bsum_kernel<<<dim3(H_ * B_, NSB), HD_>>>();
    sufscan_kernel<<<H_ * B_, HD_>>>();
    scores_tensor_kernel<<<dim3(NTRI, H_), 256>>>();

    wtrans_kernel<<<dim3(DIM_ / 32, DIM_ / 32), dim3(32, 8)>>>(wg_w, 0);
    wtrans_kernel<<<dim3(DIM_ / 32, DIM_ / 32), dim3(32, 8)>>>(wo_w, 1);
    split_kernel<<<(BSTOT * (DIM_ / 4)) / 256, 256>>>(x);

    ff_tensor_kernel<<<dim3(DIM_ / 128, BSTOT / 128), 256>>>(out, 0);  // d_G = relu(x@wg)
    ogemm_tensor_kernel<<<dim3(NSB, B_ * H_), 256>>>();
    gn_kernel<<<BSTOT, 256>>>(gamma, beta);                            // -> d_xh/d_xl
    ff_tensor_kernel<<<dim3(DIM_ / 128, BSTOT / 128), 256>>>(out, 1);  // out = G@wo
}

// round 14
// speedup vs baseline: 1.5336x; 1.1006x over previous
#include <cuda_runtime.h>
#include <cuda_bf16.h>
#include <math.h>
#include <cstdint>
#include <stdint.h>

#define B_    4
#define S_    1024
#define DIM_  2048
#define H_    16
#define HD_   128
#define BSTOT 4096   // B_*S_
#define NSB   8      // S_/128 blocks
#define NTRI  36     // lower-tri 128x128 tiles per head

// ---------------- scratch ----------------
__device__ float d_V[(size_t)H_*B_*S_*HD_];      // fp32 V (for suffix sums)
__device__ float d_O[(size_t)BSTOT*DIM_];
__device__ float d_G[(size_t)BSTOT*DIM_];        // relu(x@wg) fp32
__device__ float d_bsum[(size_t)H_*B_*NSB*HD_];
__device__ float d_suf[(size_t)H_*B_*NSB*HD_];
__device__ float d_rs[H_*S_];
__device__ float d_l2g[H_];
// bf16 hi/lo operand buffers
__device__ __nv_bfloat16 d_Qh[(size_t)H_*B_*S_*HD_];  // [h,b,s,e]
__device__ __nv_bfloat16 d_Ql[(size_t)H_*B_*S_*HD_];
__device__ __nv_bfloat16 d_Kh[(size_t)H_*B_*S_*HD_];  // [h,b,t,e]
__device__ __nv_bfloat16 d_Kl[(size_t)H_*B_*S_*HD_];
__device__ __nv_bfloat16 d_Vth[(size_t)H_*B_*HD_*S_]; // V^T [h,b,e,t]
__device__ __nv_bfloat16 d_Vtl[(size_t)H_*B_*HD_*S_];
__device__ __nv_bfloat16 d_Ahh[(size_t)H_*S_*S_];     // A [h,s,t] hi
__device__ __nv_bfloat16 d_Ahl[(size_t)H_*S_*S_];     // A lo
__device__ __nv_bfloat16 d_xh[(size_t)BSTOT*DIM_];    // x hi, later G*Y hi [m][k]
__device__ __nv_bfloat16 d_xl[(size_t)BSTOT*DIM_];
__device__ __nv_bfloat16 d_wgh[(size_t)DIM_*DIM_];    // wg^T [n][k]
__device__ __nv_bfloat16 d_wgl[(size_t)DIM_*DIM_];
__device__ __nv_bfloat16 d_woh[(size_t)DIM_*DIM_];
__device__ __nv_bfloat16 d_wol[(size_t)DIM_*DIM_];

// ---------------- decay tables ----------------
__global__ void decay_kernel() {
    int h = blockIdx.x;
    int j = threadIdx.x;
    double g  = 1.0 - exp2((double)(-5 - h));
    double r  = 1.0 / g;
    double rp = pow(r, (double)(j + 1));
    double Sj = (rp - 1.0) / (r - 1.0);
    d_rs[h * S_ + j] = (float)(1.0 / sqrt(Sj));
    if (j == 0) d_l2g[h] = (float)log2(g);
}

// ---------------- fp32 -> (hi,lo) bf16 split (x only) ----------------
__global__ void split_kernel(const float* __restrict__ srcParam) {
    const float* src = srcParam;
    __nv_bfloat16* hi = d_xh;
    __nv_bfloat16* lo = d_xl;
    size_t i = (size_t)(blockIdx.x) * blockDim.x + threadIdx.x;
    float4 v = ((const float4*)src)[i];
    __nv_bfloat16 h0 = __float2bfloat16(v.x);
    __nv_bfloat16 h1 = __float2bfloat16(v.y);
    __nv_bfloat16 h2 = __float2bfloat16(v.z);
    __nv_bfloat16 h3 = __float2bfloat16(v.w);
    __nv_bfloat16 l0 = __float2bfloat16(v.x - __bfloat162float(h0));
    __nv_bfloat16 l1 = __float2bfloat16(v.y - __bfloat162float(h1));
    __nv_bfloat16 l2 = __float2bfloat16(v.z - __bfloat162float(h2));
    __nv_bfloat16 l3 = __float2bfloat16(v.w - __bfloat162float(h3));
    __nv_bfloat162 hA; hA.x = h0; hA.y = h1;
    __nv_bfloat162 hB; hB.x = h2; hB.y = h3;
    __nv_bfloat162 lA; lA.x = l0; lA.y = l1;
    __nv_bfloat162 lB; lB.x = l2; lB.y = l3;
    *(__nv_bfloat162*)&hi[i * 4]     = hA;
    *(__nv_bfloat162*)&hi[i * 4 + 2] = hB;
    *(__nv_bfloat162*)&lo[i * 4]     = lA;
    *(__nv_bfloat162*)&lo[i * 4 + 2] = lB;
}

// ---------------- weight transpose + split ----
__global__ void wtrans_kernel(const float* __restrict__ w, int which) {
    __nv_bfloat16* hi = (which == 0) ? d_wgh : d_woh;
    __nv_bfloat16* lo = (which == 0) ? d_wgl : d_wol;
    __shared__ float tile[32][33];
    const int bx = blockIdx.x * 32;
    const int by = blockIdx.y * 32;
    const int tx = threadIdx.x;
    const int ty = threadIdx.y;
#pragma unroll
    for (int i = 0; i < 4; i++) {
        int r = ty * 4 + i;
        tile[r][tx] = w[(size_t)(by + r) * DIM_ + bx + tx];
    }
    __syncthreads();
#pragma unroll
    for (int i = 0; i < 4; i++) {
        int nl = ty * 4 + i;
        float vv = tile[tx][nl];
        __nv_bfloat16 hv = __float2bfloat16(vv);
        __nv_bfloat16 lv = __float2bfloat16(vv - __bfloat162float(hv));
        size_t idx = (size_t)(bx + nl) * DIM_ + by + tx;
        hi[idx] = hv;
        lo[idx] = lv;
    }
}

// ---------------- QKV projection: fp32 math, bf16 hi/lo outputs (R11) ----
__global__ void qkv_kernel(const float* __restrict__ x,
                           const float* __restrict__ kin,
                           const float* __restrict__ vin,
                           const float* __restrict__ Wh) {
    const int h     = blockIdx.y;
    const int which = blockIdx.z;
    const float* src = (which == 0) ? x : (which == 1) ? kin : vin;
    const int m0 = blockIdx.x * 64;

    __shared__ float Xs[32][68];
    __shared__ float Ws[32][128];

    const int tid = threadIdx.x;
    const int tx = tid & 15, ty = tid >> 4;
    float acc[4][8];
#pragma unroll
    for (int i = 0; i < 4; i++)
#pragma unroll
        for (int j = 0; j < 8; j++) acc[i][j] = 0.0f;

    for (int k0 = 0; k0 < HD_; k0 += 32) {
#pragma unroll
        for (int i = 0; i < 2; i++) {
            int idx = tid + i * 256;
            int r = idx >> 3, c4 = idx & 7;
            int row = m0 + r;
            int b = row >> 10, s = row & 1023;
            float4 vv = *(const float4*)&src[(size_t)(b * S_ + s) * DIM_ + h * HD_ + k0 + c4 * 4];
            Xs[c4 * 4 + 0][r] = vv.x;
            Xs[c4 * 4 + 1][r] = vv.y;
            Xs[c4 * 4 + 2][r] = vv.z;
            Xs[c4 * 4 + 3][r] = vv.w;
        }
#pragma unroll
        for (int i = 0; i < 4; i++) {
            int idx = tid + i * 256;
            int r = idx >> 5, c4 = idx & 31;
            *(float4*)&Ws[r][c4 * 4] =
                *(const float4*)&Wh[((size_t)h * HD_ + k0 + r) * HD_ + c4 * 4];
        }
        __syncthreads();
#pragma unroll
        for (int kk = 0; kk < 32; kk++) {
            float4 a4 = *(float4*)&Xs[kk][ty * 4];
            float a[4] = {a4.x, a4.y, a4.z, a4.w};
            float4 b0 = *(float4*)&Ws[kk][tx * 8];
            float4 b1 = *(float4*)&Ws[kk][tx * 8 + 4];
            float bb[8] = {b0.x, b0.y, b0.z, b0.w, b1.x, b1.y, b1.z, b1.w};
#pragma unroll
            for (int i = 0; i < 4; i++)
#pragma unroll
                for (int j = 0; j < 8; j++) acc[i][j] += a[i] * bb[j];
        }
        __syncthreads();
    }

    const int b = m0 >> 10;
    const int sl = m0 & 1023;
    if (which < 2) {
        __nv_bfloat16* hid = (which == 0) ? d_Qh : d_Kh;
        __nv_bfloat16* lod = (which == 0) ? d_Ql : d_Kl;
#pragma unroll
        for (int i = 0; i < 4; i++) {
            int s = sl + ty * 4 + i;
            __nv_bfloat16 hp[8], lp[8];
#pragma unroll
            for (int j = 0; j < 8; j++) {
                hp[j] = __float2bfloat16(acc[i][j]);
                lp[j] = __float2bfloat16(acc[i][j] - __bfloat162float(hp[j]));
            }
            size_t off = ((size_t)(h * B_ + b) * S_ + s) * HD_ + tx * 8;
            *(uint4*)&hid[off] = *(uint4*)hp;
            *(uint4*)&lod[off] = *(uint4*)lp;
        }
    } else {
#pragma unroll
        for (int i = 0; i < 4; i++) {
            int s = sl + ty * 4 + i;
            float* drow = d_V + ((size_t)(h * B_ + b) * S_ + s) * HD_ + tx * 8;
            float4 o0 = {acc[i][0], acc[i][1], acc[i][2], acc[i][3]};
            float4 o1 = {acc[i][4], acc[i][5], acc[i][6], acc[i][7]};
            *(float4*)&drow[0] = o0;
            *(float4*)&drow[4] = o1;
        }
        int s4 = sl + ty * 4;
#pragma unroll
        for (int j = 0; j < 8; j++) {
            int e = tx * 8 + j;
            __nv_bfloat16 hp[4], lp[4];
#pragma unroll
            for (int i = 0; i < 4; i++) {
                hp[i] = __float2bfloat16(acc[i][j]);
                lp[i] = __float2bfloat16(acc[i][j] - __bfloat162float(hp[i]));
            }
            size_t off = ((size_t)(h * B_ + b) * HD_ + e) * S_ + s4;
            *(uint2*)&d_Vth[off] = *(uint2*)hp;
            *(uint2*)&d_Vtl[off] = *(uint2*)lp;
        }
    }
}

// ---------------- suffix phase A ----------
__global__ void bsum_kernel() {
    const int hb = blockIdx.x;
    const int i  = blockIdx.y;
    const int e  = threadIdx.x;
    const float* blk = d_V + ((size_t)hb * S_ + i * 128) * HD_;
    float a0 = 0.f, a1 = 0.f, a2 = 0.f, a3 = 0.f;
#pragma unroll 8
    for (int t = 0; t < 128; t += 4) {
        a0 += blk[(t + 0) * HD_ + e];
        a1 += blk[(t + 1) * HD_ + e];
        a2 += blk[(t + 2) * HD_ + e];
        a3 += blk[(t + 3) * HD_ + e];
    }
    d_bsum[((size_t)hb * NSB + i) * HD_ + e] = (a0 + a1) + (a2 + a3);
}

// ---------------- suffix phase B ----
__global__ void sufscan_kernel() {
    const int hb = blockIdx.x;
    const int e  = threadIdx.x;
    float acc = 0.f;
#pragma unroll
    for (int i = NSB - 1; i >= 0; i--) {
        d_suf[((size_t)hb * NSB + i) * HD_ + e] = acc;
        acc += d_bsum[((size_t)hb * NSB + i) * HD_ + e];
    }
}

// ---------------- shared mma helpers ----------
#define T_LDS 40
__device__ __forceinline__ void ldsm4(unsigned int& r0, unsigned int& r1,
                                      unsigned int& r2, unsigned int& r3, unsigned int addr) {
    asm volatile("ldmatrix.sync.aligned.m8n8.x4.shared.b16 {%0,%1,%2,%3}, [%4];"
                 : "=r"(r0), "=r"(r1), "=r"(r2), "=r"(r3) : "r"(addr));
}
__device__ __forceinline__ void mma16816(float* c, const unsigned int* a, const unsigned int* b) {
    asm volatile("mma.sync.aligned.m16n8k16.row.col.f32.bf16.bf16.f32 "
                 "{%0,%1,%2,%3}, {%4,%5,%6,%7}, {%8,%9}, {%0,%1,%2,%3};"
                 : "+f"(c[0]), "+f"(c[1]), "+f"(c[2]), "+f"(c[3])
                 : "r"(a[0]), "r"(a[1]), "r"(a[2]), "r"(a[3]), "r"(b[0]), "r"(b[1]));
}
__device__ __forceinline__ void cpa16(unsigned int dst, const void* src) {
    asm volatile("cp.async.cg.shared.global [%0], [%1], 16;" :: "r"(dst), "l"(src));
}

// ---------------- scores tensor kernel (R11-proven) ----------
__global__ __launch_bounds__(256, 2)
void scores_tensor_kernel() {
    const int h = blockIdx.y;
    int kidx = blockIdx.x;
    int si = 0;
    while ((si + 1) * (si + 2) / 2 <= kidx) si++;
    const int tj = kidx - si * (si + 1) / 2;
    const int s0 = si * 128, t0 = tj * 128;

    __shared__ __align__(16) unsigned short AsB[128 * T_LDS];
    __shared__ __align__(16) unsigned short BtB[128 * T_LDS];

    const int tid  = threadIdx.x;
    const int wid  = tid >> 5;
    const int lane = tid & 31;
    const int wm = wid & 3;
    const int wn = wid >> 2;

    const unsigned int asbase = (unsigned int)__cvta_generic_to_shared(AsB);
    const unsigned int bsbase = (unsigned int)__cvta_generic_to_shared(BtB);

    const __nv_bfloat16* APtr[3] = {d_Qh, d_Qh, d_Ql};
    const __nv_bfloat16* BPtr[3] = {d_Kh, d_Kl, d_Kh};

    float acc[2][8][4];
#pragma unroll
    for (int i = 0; i < 2; i++)
#pragma unroll
        for (int j = 0; j < 8; j++)
#pragma unroll
            for (int c = 0; c < 4; c++) acc[i][j][c] = 0.0f;

    const int a_r  = lane & 15;
    const int a_k8 = ((lane >> 4) & 1) * 8;
    const int b_r  = ((lane >> 4) << 3) + (lane & 7);
    const int b_k8 = ((lane >> 3) & 1) * 8;

    uint4 pa0, pa1, pb0, pb1;
    const int NITER = 48;

    {
        const __nv_bfloat16* Ag = APtr[0] + ((size_t)(h * B_) * S_ + s0) * HD_;
        const __nv_bfloat16* Bg = BPtr[0] + ((size_t)(h * B_) * S_ + t0) * HD_;
        int ia0 = tid, ia1 = tid + 256;
        pa0 = *(const uint4*)(Ag + (size_t)(ia0 >> 2) * HD_ + (ia0 & 3) * 8);
        pa1 = *(const uint4*)(Ag + (size_t)(ia1 >> 2) * HD_ + (ia1 & 3) * 8);
        pb0 = *(const uint4*)(Bg + (size_t)(ia0 >> 2) * HD_ + (ia0 & 3) * 8);
        pb1 = *(const uint4*)(Bg + (size_t)(ia1 >> 2) * HD_ + (ia1 & 3) * 8);
    }

    for (int it = 0; it < NITER; it++) {
        {
            int ia0 = tid, ia1 = tid + 256;
            *(uint4*)&AsB[(ia0 >> 2) * T_LDS + (ia0 & 3) * 8] = pa0;
            *(uint4*)&AsB[(ia1 >> 2) * T_LDS + (ia1 & 3) * 8] = pa1;
            *(uint4*)&BtB[(ia0 >> 2) * T_LDS + (ia0 & 3) * 8] = pb0;
            *(uint4*)&BtB[(ia1 >> 2) * T_LDS + (ia1 & 3) * 8] = pb1;
        }
        __syncthreads();

        if (it + 1 < NITER) {
            int nit = it + 1;
            int term = nit >> 4;
            int kk = (nit & 15) * 32;
            int b = kk >> 7, e0 = kk & 127;
            const __nv_bfloat16* Ag = APtr[term] + ((size_t)(h * B_ + b) * S_ + s0) * HD_ + e0;
            const __nv_bfloat16* Bg = BPtr[term] + ((size_t)(h * B_ + b) * S_ + t0) * HD_ + e0;
            int ia0 = tid, ia1 = tid + 256;
            pa0 = *(const uint4*)(Ag + (size_t)(ia0 >> 2) * HD_ + (ia0 & 3) * 8);
            pa1 = *(const uint4*)(Ag + (size_t)(ia1 >> 2) * HD_ + (ia1 & 3) * 8);
            pb0 = *(const uint4*)(Bg + (size_t)(ia0 >> 2) * HD_ + (ia0 & 3) * 8);
            pb1 = *(const uint4*)(Bg + (size_t)(ia1 >> 2) * HD_ + (ia1 & 3) * 8);
        }

#pragma unroll
        for (int ks = 0; ks < 2; ks++) {
            const int kb = ks * 16;
            unsigned int af[2][4];
#pragma unroll
            for (int mi = 0; mi < 2; mi++) {
                int row = wm * 32 + mi * 16 + a_r;
                unsigned int addr = asbase + (unsigned int)(row * T_LDS + kb + a_k8) * 2;
                ldsm4(af[mi][0], af[mi][1], af[mi][2], af[mi][3], addr);
            }
#pragma unroll
            for (int nj = 0; nj < 4; nj++) {
                int nrow = wn * 64 + nj * 16 + b_r;
                unsigned int addr = bsbase + (unsigned int)(nrow * T_LDS + kb + b_k8) * 2;
                unsigned int bf[4];
                ldsm4(bf[0], bf[1], bf[2], bf[3], addr);
#pragma unroll
                for (int mi = 0; mi < 2; mi++) {
                    mma16816(acc[mi][nj * 2 + 0], af[mi], &bf[0]);
                    mma16816(acc[mi][nj * 2 + 1], af[mi], &bf[2]);
                }
            }
        }
        __syncthreads();
    }

    const float l2g = d_l2g[h];
    const float inv_sqrt_hd = 0.08838834764831845f;
    __nv_bfloat16* Ahh = d_Ahh + (size_t)h * S_ * S_;
    __nv_bfloat16* Ahl = d_Ahl + (size_t)h * S_ * S_;
    const int qr = lane >> 2;
    const int qc = (lane & 3) * 2;
#pragma unroll
    for (int mi = 0; mi < 2; mi++) {
#pragma unroll
        for (int n8 = 0; n8 < 8; n8++) {
            int t1 = t0 + wn * 64 + n8 * 8 + qc;
            float rs1 = d_rs[h * S_ + t1];
            float rs2 = d_rs[h * S_ + t1 + 1];
#pragma unroll
            for (int half = 0; half < 2; half++) {
                int s = s0 + wm * 32 + mi * 16 + qr + half * 8;
                float a1 = acc[mi][n8][half * 2 + 0];
                float a2 = acc[mi][n8][half * 2 + 1];
                float v1 = (t1 > s) ? 1.0f
                   : fmaxf(fabsf(a1 * inv_sqrt_hd * exp2f((float)(t1 - s) * l2g) * rs1), 1.0f);
                float v2 = (t1 + 1 > s) ? 1.0f
                   : fmaxf(fabsf(a2 * inv_sqrt_hd * exp2f((float)(t1 + 1 - s) * l2g) * rs2), 1.0f);
                __nv_bfloat16 h1 = __float2bfloat16(v1);
                __nv_bfloat16 h2 = __float2bfloat16(v2);
                __nv_bfloat16 l1 = __float2bfloat16(v1 - __bfloat162float(h1));
                __nv_bfloat16 l2 = __float2bfloat16(v2 - __bfloat162float(h2));
                __nv_bfloat162 hp; hp.x = h1; hp.y = h2;
                __nv_bfloat162 lp; lp.x = l1; lp.y = l2;
                *(__nv_bfloat162*)&Ahh[(size_t)s * S_ + t1] = hp;
                *(__nv_bfloat162*)&Ahl[(size_t)s * S_ + t1] = lp;
            }
        }
    }
}

// ---------------- ogemm tensor kernel (R11-proven) ---------
__global__ __launch_bounds__(256, 2)
void ogemm_tensor_kernel() {
    const int bh = blockIdx.y;
    const int b = bh >> 4, h = bh & 15;
    const int si = blockIdx.x;
    const int s0 = si * 128;
    const int KT = (si + 1) * 4;

    __shared__ __align__(16) unsigned short AsB[128 * T_LDS];
    __shared__ __align__(16) unsigned short BtB[128 * T_LDS];

    const int tid  = threadIdx.x;
    const int wid  = tid >> 5;
    const int lane = tid & 31;
    const int wm = wid & 3;
    const int wn = wid >> 2;

    const unsigned int asbase = (unsigned int)__cvta_generic_to_shared(AsB);
    const unsigned int bsbase = (unsigned int)__cvta_generic_to_shared(BtB);

    const __nv_bfloat16* Abase_h = d_Ahh + (size_t)h * S_ * S_;
    const __nv_bfloat16* Abase_l = d_Ahl + (size_t)h * S_ * S_;
    const __nv_bfloat16* Vbase_h = d_Vth + (size_t)(h * B_ + b) * HD_ * S_;
    const __nv_bfloat16* Vbase_l = d_Vtl + (size_t)(h * B_ + b) * HD_ * S_;
    const __nv_bfloat16* APtr[3] = {Abase_h, Abase_h, Abase_l};
    const __nv_bfloat16* BPtr[3] = {Vbase_h, Vbase_l, Vbase_h};

    float acc[2][8][4];
#pragma unroll
    for (int i = 0; i < 2; i++)
#pragma unroll
        for (int j = 0; j < 8; j++)
#pragma unroll
            for (int c = 0; c < 4; c++) acc[i][j][c] = 0.0f;

    const int a_r  = lane & 15;
    const int a_k8 = ((lane >> 4) & 1) * 8;
    const int b_r  = ((lane >> 4) << 3) + (lane & 7);
    const int b_k8 = ((lane >> 3) & 1) * 8;

    uint4 pa0, pa1, pb0, pb1;
    const int NITER = 3 * KT;

    {
        const __nv_bfloat16* Ag = APtr[0] + (size_t)s0 * S_;
        const __nv_bfloat16* Bg = BPtr[0];
        int ia0 = tid, ia1 = tid + 256;
        pa0 = *(const uint4*)(Ag + (size_t)(ia0 >> 2) * S_ + (ia0 & 3) * 8);
        pa1 = *(const uint4*)(Ag + (size_t)(ia1 >> 2) * S_ + (ia1 & 3) * 8);
        pb0 = *(const uint4*)(Bg + (size_t)(ia0 >> 2) * S_ + (ia0 & 3) * 8);
        pb1 = *(const uint4*)(Bg + (size_t)(ia1 >> 2) * S_ + (ia1 & 3) * 8);
    }

    for (int it = 0; it < NITER; it++) {
        {
            int ia0 = tid, ia1 = tid + 256;
            *(uint4*)&AsB[(ia0 >> 2) * T_LDS + (ia0 & 3) * 8] = pa0;
            *(uint4*)&AsB[(ia1 >> 2) * T_LDS + (ia1 & 3) * 8] = pa1;
            *(uint4*)&BtB[(ia0 >> 2) * T_LDS + (ia0 & 3) * 8] = pb0;
            *(uint4*)&BtB[(ia1 >> 2) * T_LDS + (ia1 & 3) * 8] = pb1;
        }
        __syncthreads();

        if (it + 1 < NITER) {
            int nit = it + 1;
            int term = nit / KT;
            int kk = (nit - term * KT) * 32;
            const __nv_bfloat16* Ag = APtr[term] + (size_t)s0 * S_ + kk;
            const __nv_bfloat16* Bg = BPtr[term] + kk;
            int ia0 = tid, ia1 = tid + 256;
            pa0 = *(const uint4*)(Ag + (size_t)(ia0 >> 2) * S_ + (ia0 & 3) * 8);
            pa1 = *(const uint4*)(Ag + (size_t)(ia1 >> 2) * S_ + (ia1 & 3) * 8);
            pb0 = *(const uint4*)(Bg + (size_t)(ia0 >> 2) * S_ + (ia0 & 3) * 8);
            pb1 = *(const uint4*)(Bg + (size_t)(ia1 >> 2) * S_ + (ia1 & 3) * 8);
        }

#pragma unroll
        for (int ks = 0; ks < 2; ks++) {
            const int kb = ks * 16;
            unsigned int af[2][4];
#pragma unroll
            for (int mi = 0; mi < 2; mi++) {
                int row = wm * 32 + mi * 16 + a_r;
                unsigned int addr = asbase + (unsigned int)(row * T_LDS + kb + a_k8) * 2;
                ldsm4(af[mi][0], af[mi][1], af[mi][2], af[mi][3], addr);
            }
#pragma unroll
            for (int nj = 0; nj < 4; nj++) {
                int nrow = wn * 64 + nj * 16 + b_r;
                unsigned int addr = bsbase + (unsigned int)(nrow * T_LDS + kb + b_k8) * 2;
                unsigned int bf[4];
                ldsm4(bf[0], bf[1], bf[2], bf[3], addr);
#pragma unroll
                for (int mi = 0; mi < 2; mi++) {
                    mma16816(acc[mi][nj * 2 + 0], af[mi], &bf[0]);
                    mma16816(acc[mi][nj * 2 + 1], af[mi], &bf[2]);
                }
            }
        }
        __syncthreads();
    }

    const float* suf = d_suf + ((size_t)(h * B_ + b) * NSB + si) * HD_;
    const int qr = lane >> 2;
    const int qc = (lane & 3) * 2;
#pragma unroll
    for (int mi = 0; mi < 2; mi++) {
#pragma unroll
        for (int n8 = 0; n8 < 8; n8++) {
            int e = wn * 64 + n8 * 8 + qc;
            float sv1 = suf[e], sv2 = suf[e + 1];
            int s = s0 + wm * 32 + mi * 16 + qr;
            float2 v0; v0.x = acc[mi][n8][0] + sv1; v0.y = acc[mi][n8][1] + sv2;
            float2 v1; v1.x = acc[mi][n8][2] + sv1; v1.y = acc[mi][n8][3] + sv2;
            *(float2*)&d_O[(size_t)(b * S_ + s) * DIM_ + h * HD_ + e] = v0;
            *(float2*)&d_O[(size_t)(b * S_ + s + 8) * DIM_ + h * HD_ + e] = v1;
        }
    }
}

// ---------------- tensor-core FF GEMM: 3-stage cp.async pipeline ---------
#define FF_K    DIM_
#define STG_B   (128 * T_LDS * 2)        // bytes per operand per stage (10240)
#define STAGE_B (2 * STG_B)              // bytes per stage (A+B) = 20480
#define FF_SMEM (3 * STAGE_B)            // 61440 bytes dynamic

__global__ __launch_bounds__(256, 2)
void ff_tensor_kernel(float* __restrict__ outParam, int mode) {
    extern __shared__ __align__(16) unsigned char ff_smem[];

    const __nv_bfloat16* Ahp = d_xh;
    const __nv_bfloat16* Alp = d_xl;
    const __nv_bfloat16* Bhp = (mode == 0) ? d_wgh : d_woh;
    const __nv_bfloat16* Blp = (mode == 0) ? d_wgl : d_wol;
    float* Cm = (mode == 0) ? d_G : outParam;

    const int n0 = blockIdx.x * 128;
    const int m0 = blockIdx.y * 128;

    const int tid  = threadIdx.x;
    const int wid  = tid >> 5;
    const int lane = tid & 31;
    const int wm = wid & 3;
    const int wn = wid >> 2;

    const unsigned int smbase = (unsigned int)__cvta_generic_to_shared(ff_smem);

    const __nv_bfloat16* APtr[3] = {Ahp, Ahp, Alp};
    const __nv_bfloat16* BPtr[3] = {Bhp, Blp, Bhp};

    float acc[2][8][4];
#pragma unroll
    for (int i = 0; i < 2; i++)
#pragma unroll
        for (int j = 0; j < 8; j++)
#pragma unroll
            for (int c = 0; c < 4; c++) acc[i][j][c] = 0.0f;

    const int a_r  = lane & 15;
    const int a_k8 = ((lane >> 4) & 1) * 8;
    const int b_r  = ((lane >> 4) << 3) + (lane & 7);
    const int b_k8 = ((lane >> 3) & 1) * 8;

    const int NITER = 3 * (FF_K / 32);
    const int ia0 = tid, ia1 = tid + 256;
    // smem byte offsets of this thread's 4 staged vectors (within a stage)
    const unsigned int sa0 = (unsigned int)((ia0 >> 2) * T_LDS + (ia0 & 3) * 8) * 2;
    const unsigned int sa1 = (unsigned int)((ia1 >> 2) * T_LDS + (ia1 & 3) * 8) * 2;

    // issue stage j into ring slot j%3
    auto stage = [&](int j) {
        int term = j >> 6;
        int k0 = (j & 63) * 32;
        const __nv_bfloat16* Ag = APtr[term] + (size_t)m0 * FF_K + k0;
        const __nv_bfloat16* Bg = BPtr[term] + (size_t)n0 * FF_K + k0;
        unsigned int abase = smbase + (j % 3) * STAGE_B;
        unsigned int bbase = abase + STG_B;
        cpa16(abase + sa0, Ag + (size_t)(ia0 >> 2) * FF_K + (ia0 & 3) * 8);
        cpa16(abase + sa1, Ag + (size_t)(ia1 >> 2) * FF_K + (ia1 & 3) * 8);
        cpa16(bbase + sa0, Bg + (size_t)(ia0 >> 2) * FF_K + (ia0 & 3) * 8);
        cpa16(bbase + sa1, Bg + (size_t)(ia1 >> 2) * FF_K + (ia1 & 3) * 8);
        asm volatile("cp.async.commit_group;");
    };

    stage(0);
    stage(1);

    for (int it = 0; it < NITER; it++) {
        if (it + 1 < NITER) { asm volatile("cp.async.wait_group 1;"); }
        else                { asm volatile("cp.async.wait_group 0;"); }
        __syncthreads();
        if (it + 2 < NITER) stage(it + 2);

        const unsigned int asb = smbase + (it % 3) * STAGE_B;
        const unsigned int bsb = asb + STG_B;
#pragma unroll
        for (int ks = 0; ks < 2; ks++) {
            const int kb = ks * 16;
            unsigned int af[2][4];
#pragma unroll
            for (int mi = 0; mi < 2; mi++) {
                int row = wm * 32 + mi * 16 + a_r;
                unsigned int addr = asb + (unsigned int)(row * T_LDS + kb + a_k8) * 2;
                ldsm4(af[mi][0], af[mi][1], af[mi][2], af[mi][3], addr);
            }
#pragma unroll
            for (int nj = 0; nj < 4; nj++) {
                int nrow = wn * 64 + nj * 16 + b_r;
                unsigned int addr = bsb + (unsigned int)(nrow * T_LDS + kb + b_k8) * 2;
                unsigned int bf[4];
                ldsm4(bf[0], bf[1], bf[2], bf[3], addr);
#pragma unroll
                for (int mi = 0; mi < 2; mi++) {
                    mma16816(acc[mi][nj * 2 + 0], af[mi], &bf[0]);
                    mma16816(acc[mi][nj * 2 + 1], af[mi], &bf[2]);
                }
            }
        }
    }

    const int qr = lane >> 2;
    const int qc = (lane & 3) * 2;
#pragma unroll
    for (int mi = 0; mi < 2; mi++) {
#pragma unroll
        for (int n8 = 0; n8 < 8; n8++) {
            int m = m0 + wm * 32 + mi * 16 + qr;
            int n = n0 + wn * 64 + n8 * 8 + qc;
            float2 v0; v0.x = acc[mi][n8][0]; v0.y = acc[mi][n8][1];
            float2 v1; v1.x = acc[mi][n8][2]; v1.y = acc[mi][n8][3];
            if (mode == 0) {
                v0.x = fmaxf(v0.x, 0.f); v0.y = fmaxf(v0.y, 0.f);
                v1.x = fmaxf(v1.x, 0.f); v1.y = fmaxf(v1.y, 0.f);
            }
            *(float2*)&Cm[(size_t)m * DIM_ + n] = v0;
            *(float2*)&Cm[(size_t)(m + 8) * DIM_ + n] = v1;
        }
    }
}

// ---------------- layernorm + gate mul, fused bf16 hi/lo output ----------
__global__ void gn_kernel(const float* __restrict__ gamma,
                          const float* __restrict__ beta) {
    const int row = blockIdx.x;
    const float* orow = d_O + (size_t)row * DIM_;
    const float* grow = d_G + (size_t)row * DIM_;
    __nv_bfloat16* hrow = d_xh + (size_t)row * DIM_;
    __nv_bfloat16* lrow = d_xl + (size_t)row * DIM_;
    const int tid = threadIdx.x;

    float v[8];
#pragma unroll
    for (int i = 0; i < 2; i++) {
        float4 t = *(const float4*)&orow[tid * 8 + i * 4];
        v[i * 4 + 0] = t.x; v[i * 4 + 1] = t.y;
        v[i * 4 + 2] = t.z; v[i * 4 + 3] = t.w;
    }

    __shared__ float red[8];
    __shared__ float s_mu, s_inv;

    float lsum = 0.f;
#pragma unroll
    for (int i = 0; i < 8; i++) lsum += v[i];
#pragma unroll
    for (int off = 16; off > 0; off >>= 1) lsum += __shfl_xor_sync(0xffffffffu, lsum, off);
    if ((tid & 31) == 0) red[tid >> 5] = lsum;
    __syncthreads();
    if (tid == 0) {
        float s = 0.f;
#pragma unroll
        for (int w = 0; w < 8; w++) s += red[w];
        s_mu = s * (1.0f / DIM_);
    }
    __syncthreads();
    const float mu = s_mu;

    float lsq = 0.f;
#pragma unroll
    for (int i = 0; i < 8; i++) {
        float d = v[i] - mu;
        lsq += d * d;
    }
#pragma unroll
    for (int off = 16; off > 0; off >>= 1) lsq += __shfl_xor_sync(0xffffffffu, lsq, off);
    __syncthreads();
    if ((tid & 31) == 0) red[tid >> 5] = lsq;
    __syncthreads();
    if (tid == 0) {
        float s = 0.f;
#pragma unroll
        for (int w = 0; w < 8; w++) s += red[w];
        s_inv = rsqrtf(s * (1.0f / DIM_) + 1e-3f);
    }
    __syncthreads();
    const float inv = s_inv;

#pragma unroll
    for (int i = 0; i < 2; i++) {
        int c0 = tid * 8 + i * 4;
        float4 g4 = *(const float4*)&grow[c0];
        float4 gm = *(const float4*)&gamma[c0];
        float4 bt = *(const float4*)&beta[c0];
        float o0 = g4.x * ((v[i * 4 + 0] - mu) * inv * gm.x + bt.x);
        float o1 = g4.y * ((v[i * 4 + 1] - mu) * inv * gm.y + bt.y);
        float o2 = g4.z * ((v[i * 4 + 2] - mu) * inv * gm.z + bt.z);
        float o3 = g4.w * ((v[i * 4 + 3] - mu) * inv * gm.w + bt.w);
        __nv_bfloat16 h0 = __float2bfloat16(o0);
        __nv_bfloat16 h1 = __float2bfloat16(o1);
        __nv_bfloat16 h2 = __float2bfloat16(o2);
        __nv_bfloat16 h3 = __float2bfloat16(o3);
        __nv_bfloat16 l0 = __float2bfloat16(o0 - __bfloat162float(h0));
        __nv_bfloat16 l1 = __float2bfloat16(o1 - __bfloat162float(h1));
        __nv_bfloat16 l2 = __float2bfloat16(o2 - __bfloat162float(h2));
        __nv_bfloat16 l3 = __float2bfloat16(o3 - __bfloat162float(h3));
        __nv_bfloat162 hA; hA.x = h0; hA.y = h1;
        __nv_bfloat162 hB; hB.x = h2; hB.y = h3;
        __nv_bfloat162 lA; lA.x = l0; lA.y = l1;
        __nv_bfloat162 lB; lB.x = l2; lB.y = l3;
        *(__nv_bfloat162*)&hrow[c0]     = hA;
        *(__nv_bfloat162*)&hrow[c0 + 2] = hB;
        *(__nv_bfloat162*)&lrow[c0]     = lA;
        *(__nv_bfloat162*)&lrow[c0 + 2] = lB;
    }
}

// ---------------- launch ----------------
extern "C" void kernel_launch(void* const* d_in, const int* in_sizes, int n_in,
                              void* d_out, int out_size) {
    const float* x     = (const float*)d_in[0];
    const float* k     = (const float*)d_in[1];
    const float* v     = (const float*)d_in[2];
    const float* Wh    = (const float*)d_in[3];
    const float* wg_w  = (const float*)d_in[4];
    const float* wo_w  = (const float*)d_in[5];
    const float* gamma = (const float*)d_in[6];
    const float* beta  = (const float*)d_in[7];
    float* out = (float*)d_out;

    cudaFuncSetAttribute(ff_tensor_kernel,
                         cudaFuncAttributeMaxDynamicSharedMemorySize, FF_SMEM);

    decay_kernel<<<H_, S_>>>();
    qkv_kernel<<<dim3(BSTOT / 64, H_, 3), 256>>>(x, k, v, Wh);
    bsum_kernel<<<dim3(H_ * B_, NSB), HD_>>>();
    sufscan_kernel<<<H_ * B_, HD_>>>();
    scores_tensor_kernel<<<dim3(NTRI, H_), 256>>>();

    wtrans_kernel<<<dim3(DIM_ / 32, DIM_ / 32), dim3(32, 8)>>>(wg_w, 0);
    wtrans_kernel<<<dim3(DIM_ / 32, DIM_ / 32), dim3(32, 8)>>>(wo_w, 1);
    split_kernel<<<(BSTOT * (DIM_ / 4)) / 256, 256>>>(x);

    ff_tensor_kernel<<<dim3(DIM_ / 128, BSTOT / 128), 256, FF_SMEM>>>(out, 0);
    ogemm_tensor_kernel<<<dim3(NSB, B_ * H_), 256>>>();
    gn_kernel<<<BSTOT, 256>>>(gamma, beta);
    ff_tensor_kernel<<<dim3(DIM_ / 128, BSTOT / 128), 256, FF_SMEM>>>(out, 1);
}

// round 15
// speedup vs baseline: 1.5695x; 1.0234x over previous
#include <cuda_runtime.h>
#include <cuda_bf16.h>
#include <math.h>
#include <cstdint>
#include <stdint.h>

#define B_    4
#define S_    1024
#define DIM_  2048
#define H_    16
#define HD_   128
#define BSTOT 4096   // B_*S_
#define NSB   8      // S_/128 blocks
#define NTRI  36     // lower-tri 128x128 tiles per head

// ---------------- scratch ----------------
__device__ float d_V[(size_t)H_*B_*S_*HD_];      // fp32 V (for suffix sums)
__device__ float d_O[(size_t)BSTOT*DIM_];
__device__ float d_G[(size_t)BSTOT*DIM_];        // relu(x@wg) fp32
__device__ float d_bsum[(size_t)H_*B_*NSB*HD_];
__device__ float d_suf[(size_t)H_*B_*NSB*HD_];
__device__ float d_rs[H_*S_];
__device__ float d_l2g[H_];
// bf16 hi/lo operand buffers
__device__ __nv_bfloat16 d_Qh[(size_t)H_*B_*S_*HD_];  // [h,b,s,e]
__device__ __nv_bfloat16 d_Ql[(size_t)H_*B_*S_*HD_];
__device__ __nv_bfloat16 d_Kh[(size_t)H_*B_*S_*HD_];  // [h,b,t,e]
__device__ __nv_bfloat16 d_Kl[(size_t)H_*B_*S_*HD_];
__device__ __nv_bfloat16 d_Vth[(size_t)H_*B_*HD_*S_]; // V^T [h,b,e,t]
__device__ __nv_bfloat16 d_Vtl[(size_t)H_*B_*HD_*S_];
__device__ __nv_bfloat16 d_Ahh[(size_t)H_*S_*S_];     // A [h,s,t] hi
__device__ __nv_bfloat16 d_Ahl[(size_t)H_*S_*S_];     // A lo
__device__ __nv_bfloat16 d_xh[(size_t)BSTOT*DIM_];    // x hi, later G*Y hi [m][k]
__device__ __nv_bfloat16 d_xl[(size_t)BSTOT*DIM_];
__device__ __nv_bfloat16 d_wgh[(size_t)DIM_*DIM_];    // wg^T [n][k]
__device__ __nv_bfloat16 d_wgl[(size_t)DIM_*DIM_];
__device__ __nv_bfloat16 d_woh[(size_t)DIM_*DIM_];
__device__ __nv_bfloat16 d_wol[(size_t)DIM_*DIM_];

// ---------------- decay tables ----------------
__global__ void decay_kernel() {
    int h = blockIdx.x;
    int j = threadIdx.x;
    double g  = 1.0 - exp2((double)(-5 - h));
    double r  = 1.0 / g;
    double rp = pow(r, (double)(j + 1));
    double Sj = (rp - 1.0) / (r - 1.0);
    d_rs[h * S_ + j] = (float)(1.0 / sqrt(Sj));
    if (j == 0) d_l2g[h] = (float)log2(g);
}

// ---------------- fp32 -> (hi,lo) bf16 split (x only) ----------------
__global__ void split_kernel(const float* __restrict__ srcParam) {
    const float* src = srcParam;
    __nv_bfloat16* hi = d_xh;
    __nv_bfloat16* lo = d_xl;
    size_t i = (size_t)(blockIdx.x) * blockDim.x + threadIdx.x;
    float4 v = ((const float4*)src)[i];
    __nv_bfloat16 h0 = __float2bfloat16(v.x);
    __nv_bfloat16 h1 = __float2bfloat16(v.y);
    __nv_bfloat16 h2 = __float2bfloat16(v.z);
    __nv_bfloat16 h3 = __float2bfloat16(v.w);
    __nv_bfloat16 l0 = __float2bfloat16(v.x - __bfloat162float(h0));
    __nv_bfloat16 l1 = __float2bfloat16(v.y - __bfloat162float(h1));
    __nv_bfloat16 l2 = __float2bfloat16(v.z - __bfloat162float(h2));
    __nv_bfloat16 l3 = __float2bfloat16(v.w - __bfloat162float(h3));
    __nv_bfloat162 hA; hA.x = h0; hA.y = h1;
    __nv_bfloat162 hB; hB.x = h2; hB.y = h3;
    __nv_bfloat162 lA; lA.x = l0; lA.y = l1;
    __nv_bfloat162 lB; lB.x = l2; lB.y = l3;
    *(__nv_bfloat162*)&hi[i * 4]     = hA;
    *(__nv_bfloat162*)&hi[i * 4 + 2] = hB;
    *(__nv_bfloat162*)&lo[i * 4]     = lA;
    *(__nv_bfloat162*)&lo[i * 4 + 2] = lB;
}

// ---------------- weight transpose + split ----
__global__ void wtrans_kernel(const float* __restrict__ w, int which) {
    __nv_bfloat16* hi = (which == 0) ? d_wgh : d_woh;
    __nv_bfloat16* lo = (which == 0) ? d_wgl : d_wol;
    __shared__ float tile[32][33];
    const int bx = blockIdx.x * 32;
    const int by = blockIdx.y * 32;
    const int tx = threadIdx.x;
    const int ty = threadIdx.y;
#pragma unroll
    for (int i = 0; i < 4; i++) {
        int r = ty * 4 + i;
        tile[r][tx] = w[(size_t)(by + r) * DIM_ + bx + tx];
    }
    __syncthreads();
#pragma unroll
    for (int i = 0; i < 4; i++) {
        int nl = ty * 4 + i;
        float vv = tile[tx][nl];
        __nv_bfloat16 hv = __float2bfloat16(vv);
        __nv_bfloat16 lv = __float2bfloat16(vv - __bfloat162float(hv));
        size_t idx = (size_t)(bx + nl) * DIM_ + by + tx;
        hi[idx] = hv;
        lo[idx] = lv;
    }
}

// ---------------- QKV projection: fp32 math, bf16 hi/lo outputs (R11) ----
__global__ void qkv_kernel(const float* __restrict__ x,
                           const float* __restrict__ kin,
                           const float* __restrict__ vin,
                           const float* __restrict__ Wh) {
    const int h     = blockIdx.y;
    const int which = blockIdx.z;
    const float* src = (which == 0) ? x : (which == 1) ? kin : vin;
    const int m0 = blockIdx.x * 64;

    __shared__ float Xs[32][68];
    __shared__ float Ws[32][128];

    const int tid = threadIdx.x;
    const int tx = tid & 15, ty = tid >> 4;
    float acc[4][8];
#pragma unroll
    for (int i = 0; i < 4; i++)
#pragma unroll
        for (int j = 0; j < 8; j++) acc[i][j] = 0.0f;

    for (int k0 = 0; k0 < HD_; k0 += 32) {
#pragma unroll
        for (int i = 0; i < 2; i++) {
            int idx = tid + i * 256;
            int r = idx >> 3, c4 = idx & 7;
            int row = m0 + r;
            int b = row >> 10, s = row & 1023;
            float4 vv = *(const float4*)&src[(size_t)(b * S_ + s) * DIM_ + h * HD_ + k0 + c4 * 4];
            Xs[c4 * 4 + 0][r] = vv.x;
            Xs[c4 * 4 + 1][r] = vv.y;
            Xs[c4 * 4 + 2][r] = vv.z;
            Xs[c4 * 4 + 3][r] = vv.w;
        }
#pragma unroll
        for (int i = 0; i < 4; i++) {
            int idx = tid + i * 256;
            int r = idx >> 5, c4 = idx & 31;
            *(float4*)&Ws[r][c4 * 4] =
                *(const float4*)&Wh[((size_t)h * HD_ + k0 + r) * HD_ + c4 * 4];
        }
        __syncthreads();
#pragma unroll
        for (int kk = 0; kk < 32; kk++) {
            float4 a4 = *(float4*)&Xs[kk][ty * 4];
            float a[4] = {a4.x, a4.y, a4.z, a4.w};
            float4 b0 = *(float4*)&Ws[kk][tx * 8];
            float4 b1 = *(float4*)&Ws[kk][tx * 8 + 4];
            float bb[8] = {b0.x, b0.y, b0.z, b0.w, b1.x, b1.y, b1.z, b1.w};
#pragma unroll
            for (int i = 0; i < 4; i++)
#pragma unroll
                for (int j = 0; j < 8; j++) acc[i][j] += a[i] * bb[j];
        }
        __syncthreads();
    }

    const int b = m0 >> 10;
    const int sl = m0 & 1023;
    if (which < 2) {
        __nv_bfloat16* hid = (which == 0) ? d_Qh : d_Kh;
        __nv_bfloat16* lod = (which == 0) ? d_Ql : d_Kl;
#pragma unroll
        for (int i = 0; i < 4; i++) {
            int s = sl + ty * 4 + i;
            __nv_bfloat16 hp[8], lp[8];
#pragma unroll
            for (int j = 0; j < 8; j++) {
                hp[j] = __float2bfloat16(acc[i][j]);
                lp[j] = __float2bfloat16(acc[i][j] - __bfloat162float(hp[j]));
            }
            size_t off = ((size_t)(h * B_ + b) * S_ + s) * HD_ + tx * 8;
            *(uint4*)&hid[off] = *(uint4*)hp;
            *(uint4*)&lod[off] = *(uint4*)lp;
        }
    } else {
#pragma unroll
        for (int i = 0; i < 4; i++) {
            int s = sl + ty * 4 + i;
            float* drow = d_V + ((size_t)(h * B_ + b) * S_ + s) * HD_ + tx * 8;
            float4 o0 = {acc[i][0], acc[i][1], acc[i][2], acc[i][3]};
            float4 o1 = {acc[i][4], acc[i][5], acc[i][6], acc[i][7]};
            *(float4*)&drow[0] = o0;
            *(float4*)&drow[4] = o1;
        }
        int s4 = sl + ty * 4;
#pragma unroll
        for (int j = 0; j < 8; j++) {
            int e = tx * 8 + j;
            __nv_bfloat16 hp[4], lp[4];
#pragma unroll
            for (int i = 0; i < 4; i++) {
                hp[i] = __float2bfloat16(acc[i][j]);
                lp[i] = __float2bfloat16(acc[i][j] - __bfloat162float(hp[i]));
            }
            size_t off = ((size_t)(h * B_ + b) * HD_ + e) * S_ + s4;
            *(uint2*)&d_Vth[off] = *(uint2*)hp;
            *(uint2*)&d_Vtl[off] = *(uint2*)lp;
        }
    }
}

// ---------------- suffix phase A ----------
__global__ void bsum_kernel() {
    const int hb = blockIdx.x;
    const int i  = blockIdx.y;
    const int e  = threadIdx.x;
    const float* blk = d_V + ((size_t)hb * S_ + i * 128) * HD_;
    float a0 = 0.f, a1 = 0.f, a2 = 0.f, a3 = 0.f;
#pragma unroll 8
    for (int t = 0; t < 128; t += 4) {
        a0 += blk[(t + 0) * HD_ + e];
        a1 += blk[(t + 1) * HD_ + e];
        a2 += blk[(t + 2) * HD_ + e];
        a3 += blk[(t + 3) * HD_ + e];
    }
    d_bsum[((size_t)hb * NSB + i) * HD_ + e] = (a0 + a1) + (a2 + a3);
}

// ---------------- suffix phase B ----
__global__ void sufscan_kernel() {
    const int hb = blockIdx.x;
    const int e  = threadIdx.x;
    float acc = 0.f;
#pragma unroll
    for (int i = NSB - 1; i >= 0; i--) {
        d_suf[((size_t)hb * NSB + i) * HD_ + e] = acc;
        acc += d_bsum[((size_t)hb * NSB + i) * HD_ + e];
    }
}

// ---------------- shared mma helpers ----------
#define T_LDS   40
#define STG_B   (128 * T_LDS * 2)        // bytes per operand per stage (10240)
#define STAGE_B (2 * STG_B)              // bytes per stage (A+B) = 20480
#define PIPE_SMEM (3 * STAGE_B)          // 61440 bytes dynamic

__device__ __forceinline__ void ldsm4(unsigned int& r0, unsigned int& r1,
                                      unsigned int& r2, unsigned int& r3, unsigned int addr) {
    asm volatile("ldmatrix.sync.aligned.m8n8.x4.shared.b16 {%0,%1,%2,%3}, [%4];"
                 : "=r"(r0), "=r"(r1), "=r"(r2), "=r"(r3) : "r"(addr));
}
__device__ __forceinline__ void mma16816(float* c, const unsigned int* a, const unsigned int* b) {
    asm volatile("mma.sync.aligned.m16n8k16.row.col.f32.bf16.bf16.f32 "
                 "{%0,%1,%2,%3}, {%4,%5,%6,%7}, {%8,%9}, {%0,%1,%2,%3};"
                 : "+f"(c[0]), "+f"(c[1]), "+f"(c[2]), "+f"(c[3])
                 : "r"(a[0]), "r"(a[1]), "r"(a[2]), "r"(a[3]), "r"(b[0]), "r"(b[1]));
}
__device__ __forceinline__ void cpa16(unsigned int dst, const void* src) {
    asm volatile("cp.async.cg.shared.global [%0], [%1], 16;" :: "r"(dst), "l"(src));
}

// ---------------- scores tensor kernel: 3-stage cp.async pipeline ----------
__global__ __launch_bounds__(256, 2)
void scores_tensor_kernel() {
    extern __shared__ __align__(16) unsigned char p_smem[];
    const int h = blockIdx.y;
    int kidx = blockIdx.x;
    int si = 0;
    while ((si + 1) * (si + 2) / 2 <= kidx) si++;
    const int tj = kidx - si * (si + 1) / 2;
    const int s0 = si * 128, t0 = tj * 128;

    const int tid  = threadIdx.x;
    const int wid  = tid >> 5;
    const int lane = tid & 31;
    const int wm = wid & 3;
    const int wn = wid >> 2;

    const unsigned int smbase = (unsigned int)__cvta_generic_to_shared(p_smem);

    const __nv_bfloat16* APtr[3] = {d_Qh, d_Qh, d_Ql};
    const __nv_bfloat16* BPtr[3] = {d_Kh, d_Kl, d_Kh};

    float acc[2][8][4];
#pragma unroll
    for (int i = 0; i < 2; i++)
#pragma unroll
        for (int j = 0; j < 8; j++)
#pragma unroll
            for (int c = 0; c < 4; c++) acc[i][j][c] = 0.0f;

    const int a_r  = lane & 15;
    const int a_k8 = ((lane >> 4) & 1) * 8;
    const int b_r  = ((lane >> 4) << 3) + (lane & 7);
    const int b_k8 = ((lane >> 3) & 1) * 8;

    const int NITER = 48;
    const int ia0 = tid, ia1 = tid + 256;
    const unsigned int sa0 = (unsigned int)((ia0 >> 2) * T_LDS + (ia0 & 3) * 8) * 2;
    const unsigned int sa1 = (unsigned int)((ia1 >> 2) * T_LDS + (ia1 & 3) * 8) * 2;

    auto stage = [&](int j) {
        int term = j >> 4;
        int kk = (j & 15) * 32;
        int b = kk >> 7, e0 = kk & 127;
        const __nv_bfloat16* Ag = APtr[term] + ((size_t)(h * B_ + b) * S_ + s0) * HD_ + e0;
        const __nv_bfloat16* Bg = BPtr[term] + ((size_t)(h * B_ + b) * S_ + t0) * HD_ + e0;
        unsigned int abase = smbase + (j % 3) * STAGE_B;
        unsigned int bbase = abase + STG_B;
        cpa16(abase + sa0, Ag + (size_t)(ia0 >> 2) * HD_ + (ia0 & 3) * 8);
        cpa16(abase + sa1, Ag + (size_t)(ia1 >> 2) * HD_ + (ia1 & 3) * 8);
        cpa16(bbase + sa0, Bg + (size_t)(ia0 >> 2) * HD_ + (ia0 & 3) * 8);
        cpa16(bbase + sa1, Bg + (size_t)(ia1 >> 2) * HD_ + (ia1 & 3) * 8);
        asm volatile("cp.async.commit_group;");
    };

    stage(0);
    stage(1);

    for (int it = 0; it < NITER; it++) {
        if (it + 1 < NITER) { asm volatile("cp.async.wait_group 1;"); }
        else                { asm volatile("cp.async.wait_group 0;"); }
        __syncthreads();
        if (it + 2 < NITER) stage(it + 2);

        const unsigned int asb = smbase + (it % 3) * STAGE_B;
        const unsigned int bsb = asb + STG_B;
#pragma unroll
        for (int ks = 0; ks < 2; ks++) {
            const int kb = ks * 16;
            unsigned int af[2][4];
#pragma unroll
            for (int mi = 0; mi < 2; mi++) {
                int row = wm * 32 + mi * 16 + a_r;
                unsigned int addr = asb + (unsigned int)(row * T_LDS + kb + a_k8) * 2;
                ldsm4(af[mi][0], af[mi][1], af[mi][2], af[mi][3], addr);
            }
#pragma unroll
            for (int nj = 0; nj < 4; nj++) {
                int nrow = wn * 64 + nj * 16 + b_r;
                unsigned int addr = bsb + (unsigned int)(nrow * T_LDS + kb + b_k8) * 2;
                unsigned int bf[4];
                ldsm4(bf[0], bf[1], bf[2], bf[3], addr);
#pragma unroll
                for (int mi = 0; mi < 2; mi++) {
                    mma16816(acc[mi][nj * 2 + 0], af[mi], &bf[0]);
                    mma16816(acc[mi][nj * 2 + 1], af[mi], &bf[2]);
                }
            }
        }
    }

    const float l2g = d_l2g[h];
    const float inv_sqrt_hd = 0.08838834764831845f;
    __nv_bfloat16* Ahh = d_Ahh + (size_t)h * S_ * S_;
    __nv_bfloat16* Ahl = d_Ahl + (size_t)h * S_ * S_;
    const int qr = lane >> 2;
    const int qc = (lane & 3) * 2;
#pragma unroll
    for (int mi = 0; mi < 2; mi++) {
#pragma unroll
        for (int n8 = 0; n8 < 8; n8++) {
            int t1 = t0 + wn * 64 + n8 * 8 + qc;
            float rs1 = d_rs[h * S_ + t1];
            float rs2 = d_rs[h * S_ + t1 + 1];
#pragma unroll
            for (int half = 0; half < 2; half++) {
                int s = s0 + wm * 32 + mi * 16 + qr + half * 8;
                float a1 = acc[mi][n8][half * 2 + 0];
                float a2 = acc[mi][n8][half * 2 + 1];
                float v1 = (t1 > s) ? 1.0f
                   : fmaxf(fabsf(a1 * inv_sqrt_hd * exp2f((float)(t1 - s) * l2g) * rs1), 1.0f);
                float v2 = (t1 + 1 > s) ? 1.0f
                   : fmaxf(fabsf(a2 * inv_sqrt_hd * exp2f((float)(t1 + 1 - s) * l2g) * rs2), 1.0f);
                __nv_bfloat16 h1 = __float2bfloat16(v1);
                __nv_bfloat16 h2 = __float2bfloat16(v2);
                __nv_bfloat16 l1 = __float2bfloat16(v1 - __bfloat162float(h1));
                __nv_bfloat16 l2 = __float2bfloat16(v2 - __bfloat162float(h2));
                __nv_bfloat162 hp; hp.x = h1; hp.y = h2;
                __nv_bfloat162 lp; lp.x = l1; lp.y = l2;
                *(__nv_bfloat162*)&Ahh[(size_t)s * S_ + t1] = hp;
                *(__nv_bfloat162*)&Ahl[(size_t)s * S_ + t1] = lp;
            }
        }
    }
}

// ---------------- ogemm tensor kernel: 3-stage cp.async pipeline ---------
__global__ __launch_bounds__(256, 2)
void ogemm_tensor_kernel() {
    extern __shared__ __align__(16) unsigned char p_smem[];
    const int bh = blockIdx.y;
    const int b = bh >> 4, h = bh & 15;
    const int si = blockIdx.x;
    const int s0 = si * 128;
    const int KT = (si + 1) * 4;

    const int tid  = threadIdx.x;
    const int wid  = tid >> 5;
    const int lane = tid & 31;
    const int wm = wid & 3;
    const int wn = wid >> 2;

    const unsigned int smbase = (unsigned int)__cvta_generic_to_shared(p_smem);

    const __nv_bfloat16* Abase_h = d_Ahh + (size_t)h * S_ * S_;
    const __nv_bfloat16* Abase_l = d_Ahl + (size_t)h * S_ * S_;
    const __nv_bfloat16* Vbase_h = d_Vth + (size_t)(h * B_ + b) * HD_ * S_;
    const __nv_bfloat16* Vbase_l = d_Vtl + (size_t)(h * B_ + b) * HD_ * S_;
    const __nv_bfloat16* APtr[3] = {Abase_h, Abase_h, Abase_l};
    const __nv_bfloat16* BPtr[3] = {Vbase_h, Vbase_l, Vbase_h};

    float acc[2][8][4];
#pragma unroll
    for (int i = 0; i < 2; i++)
#pragma unroll
        for (int j = 0; j < 8; j++)
#pragma unroll
            for (int c = 0; c < 4; c++) acc[i][j][c] = 0.0f;

    const int a_r  = lane & 15;
    const int a_k8 = ((lane >> 4) & 1) * 8;
    const int b_r  = ((lane >> 4) << 3) + (lane & 7);
    const int b_k8 = ((lane >> 3) & 1) * 8;

    const int NITER = 3 * KT;
    const int ia0 = tid, ia1 = tid + 256;
    const unsigned int sa0 = (unsigned int)((ia0 >> 2) * T_LDS + (ia0 & 3) * 8) * 2;
    const unsigned int sa1 = (unsigned int)((ia1 >> 2) * T_LDS + (ia1 & 3) * 8) * 2;

    auto stage = [&](int j) {
        int term = j / KT;
        int kk = (j - term * KT) * 32;
        const __nv_bfloat16* Ag = APtr[term] + (size_t)s0 * S_ + kk;
        const __nv_bfloat16* Bg = BPtr[term] + kk;
        unsigned int abase = smbase + (j % 3) * STAGE_B;
        unsigned int bbase = abase + STG_B;
        cpa16(abase + sa0, Ag + (size_t)(ia0 >> 2) * S_ + (ia0 & 3) * 8);
        cpa16(abase + sa1, Ag + (size_t)(ia1 >> 2) * S_ + (ia1 & 3) * 8);
        cpa16(bbase + sa0, Bg + (size_t)(ia0 >> 2) * S_ + (ia0 & 3) * 8);
        cpa16(bbase + sa1, Bg + (size_t)(ia1 >> 2) * S_ + (ia1 & 3) * 8);
        asm volatile("cp.async.commit_group;");
    };

    stage(0);
    if (NITER > 1) stage(1);

    for (int it = 0; it < NITER; it++) {
        if (it + 1 < NITER) { asm volatile("cp.async.wait_group 1;"); }
        else                { asm volatile("cp.async.wait_group 0;"); }
        __syncthreads();
        if (it + 2 < NITER) stage(it + 2);

        const unsigned int asb = smbase + (it % 3) * STAGE_B;
        const unsigned int bsb = asb + STG_B;
#pragma unroll
        for (int ks = 0; ks < 2; ks++) {
            const int kb = ks * 16;
            unsigned int af[2][4];
#pragma unroll
            for (int mi = 0; mi < 2; mi++) {
                int row = wm * 32 + mi * 16 + a_r;
                unsigned int addr = asb + (unsigned int)(row * T_LDS + kb + a_k8) * 2;
                ldsm4(af[mi][0], af[mi][1], af[mi][2], af[mi][3], addr);
            }
#pragma unroll
            for (int nj = 0; nj < 4; nj++) {
                int nrow = wn * 64 + nj * 16 + b_r;
                unsigned int addr = bsb + (unsigned int)(nrow * T_LDS + kb + b_k8) * 2;
                unsigned int bf[4];
                ldsm4(bf[0], bf[1], bf[2], bf[3], addr);
#pragma unroll
                for (int mi = 0; mi < 2; mi++) {
                    mma16816(acc[mi][nj * 2 + 0], af[mi], &bf[0]);
                    mma16816(acc[mi][nj * 2 + 1], af[mi], &bf[2]);
                }
            }
        }
    }

    const float* suf = d_suf + ((size_t)(h * B_ + b) * NSB + si) * HD_;
    const int qr = lane >> 2;
    const int qc = (lane & 3) * 2;
#pragma unroll
    for (int mi = 0; mi < 2; mi++) {
#pragma unroll
        for (int n8 = 0; n8 < 8; n8++) {
            int e = wn * 64 + n8 * 8 + qc;
            float sv1 = suf[e], sv2 = suf[e + 1];
            int s = s0 + wm * 32 + mi * 16 + qr;
            float2 v0; v0.x = acc[mi][n8][0] + sv1; v0.y = acc[mi][n8][1] + sv2;
            float2 v1; v1.x = acc[mi][n8][2] + sv1; v1.y = acc[mi][n8][3] + sv2;
            *(float2*)&d_O[(size_t)(b * S_ + s) * DIM_ + h * HD_ + e] = v0;
            *(float2*)&d_O[(size_t)(b * S_ + s + 8) * DIM_ + h * HD_ + e] = v1;
        }
    }
}

// ---------------- tensor-core FF GEMM: 3-stage cp.async pipeline (R14) ---
#define FF_K    DIM_
__global__ __launch_bounds__(256, 2)
void ff_tensor_kernel(float* __restrict__ outParam, int mode) {
    extern __shared__ __align__(16) unsigned char p_smem[];

    const __nv_bfloat16* Ahp = d_xh;
    const __nv_bfloat16* Alp = d_xl;
    const __nv_bfloat16* Bhp = (mode == 0) ? d_wgh : d_woh;
    const __nv_bfloat16* Blp = (mode == 0) ? d_wgl : d_wol;
    float* Cm = (mode == 0) ? d_G : outParam;

    const int n0 = blockIdx.x * 128;
    const int m0 = blockIdx.y * 128;

    const int tid  = threadIdx.x;
    const int wid  = tid >> 5;
    const int lane = tid & 31;
    const int wm = wid & 3;
    const int wn = wid >> 2;

    const unsigned int smbase = (unsigned int)__cvta_generic_to_shared(p_smem);

    const __nv_bfloat16* APtr[3] = {Ahp, Ahp, Alp};
    const __nv_bfloat16* BPtr[3] = {Bhp, Blp, Bhp};

    float acc[2][8][4];
#pragma unroll
    for (int i = 0; i < 2; i++)
#pragma unroll
        for (int j = 0; j < 8; j++)
#pragma unroll
            for (int c = 0; c < 4; c++) acc[i][j][c] = 0.0f;

    const int a_r  = lane & 15;
    const int a_k8 = ((lane >> 4) & 1) * 8;
    const int b_r  = ((lane >> 4) << 3) + (lane & 7);
    const int b_k8 = ((lane >> 3) & 1) * 8;

    const int NITER = 3 * (FF_K / 32);
    const int ia0 = tid, ia1 = tid + 256;
    const unsigned int sa0 = (unsigned int)((ia0 >> 2) * T_LDS + (ia0 & 3) * 8) * 2;
    const unsigned int sa1 = (unsigned int)((ia1 >> 2) * T_LDS + (ia1 & 3) * 8) * 2;

    auto stage = [&](int j) {
        int term = j >> 6;
        int k0 = (j & 63) * 32;
        const __nv_bfloat16* Ag = APtr[term] + (size_t)m0 * FF_K + k0;
        const __nv_bfloat16* Bg = BPtr[term] + (size_t)n0 * FF_K + k0;
        unsigned int abase = smbase + (j % 3) * STAGE_B;
        unsigned int bbase = abase + STG_B;
        cpa16(abase + sa0, Ag + (size_t)(ia0 >> 2) * FF_K + (ia0 & 3) * 8);
        cpa16(abase + sa1, Ag + (size_t)(ia1 >> 2) * FF_K + (ia1 & 3) * 8);
        cpa16(bbase + sa0, Bg + (size_t)(ia0 >> 2) * FF_K + (ia0 & 3) * 8);
        cpa16(bbase + sa1, Bg + (size_t)(ia1 >> 2) * FF_K + (ia1 & 3) * 8);
        asm volatile("cp.async.commit_group;");
    };

    stage(0);
    stage(1);

    for (int it = 0; it < NITER; it++) {
        if (it + 1 < NITER) { asm volatile("cp.async.wait_group 1;"); }
        else                { asm volatile("cp.async.wait_group 0;"); }
        __syncthreads();
        if (it + 2 < NITER) stage(it + 2);

        const unsigned int asb = smbase + (it % 3) * STAGE_B;
        const unsigned int bsb = asb + STG_B;
#pragma unroll
        for (int ks = 0; ks < 2; ks++) {
            const int kb = ks * 16;
            unsigned int af[2][4];
#pragma unroll
            for (int mi = 0; mi < 2; mi++) {
                int row = wm * 32 + mi * 16 + a_r;
                unsigned int addr = asb + (unsigned int)(row * T_LDS + kb + a_k8) * 2;
                ldsm4(af[mi][0], af[mi][1], af[mi][2], af[mi][3], addr);
            }
#pragma unroll
            for (int nj = 0; nj < 4; nj++) {
                int nrow = wn * 64 + nj * 16 + b_r;
                unsigned int addr = bsb + (unsigned int)(nrow * T_LDS + kb + b_k8) * 2;
                unsigned int bf[4];
                ldsm4(bf[0], bf[1], bf[2], bf[3], addr);
#pragma unroll
                for (int mi = 0; mi < 2; mi++) {
                    mma16816(acc[mi][nj * 2 + 0], af[mi], &bf[0]);
                    mma16816(acc[mi][nj * 2 + 1], af[mi], &bf[2]);
                }
            }
        }
    }

    const int qr = lane >> 2;
    const int qc = (lane & 3) * 2;
#pragma unroll
    for (int mi = 0; mi < 2; mi++) {
#pragma unroll
        for (int n8 = 0; n8 < 8; n8++) {
            int m = m0 + wm * 32 + mi * 16 + qr;
            int n = n0 + wn * 64 + n8 * 8 + qc;
            float2 v0; v0.x = acc[mi][n8][0]; v0.y = acc[mi][n8][1];
            float2 v1; v1.x = acc[mi][n8][2]; v1.y = acc[mi][n8][3];
            if (mode == 0) {
                v0.x = fmaxf(v0.x, 0.f); v0.y = fmaxf(v0.y, 0.f);
                v1.x = fmaxf(v1.x, 0.f); v1.y = fmaxf(v1.y, 0.f);
            }
            *(float2*)&Cm[(size_t)m * DIM_ + n] = v0;
            *(float2*)&Cm[(size_t)(m + 8) * DIM_ + n] = v1;
        }
    }
}

// ---------------- layernorm + gate mul, fused bf16 hi/lo output ----------
__global__ void gn_kernel(const float* __restrict__ gamma,
                          const float* __restrict__ beta) {
    const int row = blockIdx.x;
    const float* orow = d_O + (size_t)row * DIM_;
    const float* grow = d_G + (size_t)row * DIM_;
    __nv_bfloat16* hrow = d_xh + (size_t)row * DIM_;
    __nv_bfloat16* lrow = d_xl + (size_t)row * DIM_;
    const int tid = threadIdx.x;

    float v[8];
#pragma unroll
    for (int i = 0; i < 2; i++) {
        float4 t = *(const float4*)&orow[tid * 8 + i * 4];
        v[i * 4 + 0] = t.x; v[i * 4 + 1] = t.y;
        v[i * 4 + 2] = t.z; v[i * 4 + 3] = t.w;
    }

    __shared__ float red[8];
    __shared__ float s_mu, s_inv;

    float lsum = 0.f;
#pragma unroll
    for (int i = 0; i < 8; i++) lsum += v[i];
#pragma unroll
    for (int off = 16; off > 0; off >>= 1) lsum += __shfl_xor_sync(0xffffffffu, lsum, off);
    if ((tid & 31) == 0) red[tid >> 5] = lsum;
    __syncthreads();
    if (tid == 0) {
        float s = 0.f;
#pragma unroll
        for (int w = 0; w < 8; w++) s += red[w];
        s_mu = s * (1.0f / DIM_);
    }
    __syncthreads();
    const float mu = s_mu;

    float lsq = 0.f;
#pragma unroll
    for (int i = 0; i < 8; i++) {
        float d = v[i] - mu;
        lsq += d * d;
    }
#pragma unroll
    for (int off = 16; off > 0; off >>= 1) lsq += __shfl_xor_sync(0xffffffffu, lsq, off);
    __syncthreads();
    if ((tid & 31) == 0) red[tid >> 5] = lsq;
    __syncthreads();
    if (tid == 0) {
        float s = 0.f;
#pragma unroll
        for (int w = 0; w < 8; w++) s += red[w];
        s_inv = rsqrtf(s * (1.0f / DIM_) + 1e-3f);
    }
    __syncthreads();
    const float inv = s_inv;

#pragma unroll
    for (int i = 0; i < 2; i++) {
        int c0 = tid * 8 + i * 4;
        float4 g4 = *(const float4*)&grow[c0];
        float4 gm = *(const float4*)&gamma[c0];
        float4 bt = *(const float4*)&beta[c0];
        float o0 = g4.x * ((v[i * 4 + 0] - mu) * inv * gm.x + bt.x);
        float o1 = g4.y * ((v[i * 4 + 1] - mu) * inv * gm.y + bt.y);
        float o2 = g4.z * ((v[i * 4 + 2] - mu) * inv * gm.z + bt.z);
        float o3 = g4.w * ((v[i * 4 + 3] - mu) * inv * gm.w + bt.w);
        __nv_bfloat16 h0 = __float2bfloat16(o0);
        __nv_bfloat16 h1 = __float2bfloat16(o1);
        __nv_bfloat16 h2 = __float2bfloat16(o2);
        __nv_bfloat16 h3 = __float2bfloat16(o3);
        __nv_bfloat16 l0 = __float2bfloat16(o0 - __bfloat162float(h0));
        __nv_bfloat16 l1 = __float2bfloat16(o1 - __bfloat162float(h1));
        __nv_bfloat16 l2 = __float2bfloat16(o2 - __bfloat162float(h2));
        __nv_bfloat16 l3 = __float2bfloat16(o3 - __bfloat162float(h3));
        __nv_bfloat162 hA; hA.x = h0; hA.y = h1;
        __nv_bfloat162 hB; hB.x = h2; hB.y = h3;
        __nv_bfloat162 lA; lA.x = l0; lA.y = l1;
        __nv_bfloat162 lB; lB.x = l2; lB.y = l3;
        *(__nv_bfloat162*)&hrow[c0]     = hA;
        *(__nv_bfloat162*)&hrow[c0 + 2] = hB;
        *(__nv_bfloat162*)&lrow[c0]     = lA;
        *(__nv_bfloat162*)&lrow[c0 + 2] = lB;
    }
}

// ---------------- launch ----------------
extern "C" void kernel_launch(void* const* d_in, const int* in_sizes, int n_in,
                              void* d_out, int out_size) {
    const float* x     = (const float*)d_in[0];
    const float* k     = (const float*)d_in[1];
    const float* v     = (const float*)d_in[2];
    const float* Wh    = (const float*)d_in[3];
    const float* wg_w  = (const float*)d_in[4];
    const float* wo_w  = (const float*)d_in[5];
    const float* gamma = (const float*)d_in[6];
    const float* beta  = (const float*)d_in[7];
    float* out = (float*)d_out;

    cudaFuncSetAttribute(ff_tensor_kernel,
                         cudaFuncAttributeMaxDynamicSharedMemorySize, PIPE_SMEM);
    cudaFuncSetAttribute(scores_tensor_kernel,
                         cudaFuncAttributeMaxDynamicSharedMemorySize, PIPE_SMEM);
    cudaFuncSetAttribute(ogemm_tensor_kernel,
                         cudaFuncAttributeMaxDynamicSharedMemorySize, PIPE_SMEM);

    decay_kernel<<<H_, S_>>>();
    qkv_kernel<<<dim3(BSTOT / 64, H_, 3), 256>>>(x, k, v, Wh);
    bsum_kernel<<<dim3(H_ * B_, NSB), HD_>>>();
    sufscan_kernel<<<H_ * B_, HD_>>>();
    scores_tensor_kernel<<<dim3(NTRI, H_), 256, PIPE_SMEM>>>();

    wtrans_kernel<<<dim3(DIM_ / 32, DIM_ / 32), dim3(32, 8)>>>(wg_w, 0);
    wtrans_kernel<<<dim3(DIM_ / 32, DIM_ / 32), dim3(32, 8)>>>(wo_w, 1);
    split_kernel<<<(BSTOT * (DIM_ / 4)) / 256, 256>>>(x);

    ff_tensor_kernel<<<dim3(DIM_ / 128, BSTOT / 128), 256, PIPE_SMEM>>>(out, 0);
    ogemm_tensor_kernel<<<dim3(NSB, B_ * H_), 256, PIPE_SMEM>>>();
    gn_kernel<<<BSTOT, 256>>>(gamma, beta);
    ff_tensor_kernel<<<dim3(DIM_ / 128, BSTOT / 128), 256, PIPE_SMEM>>>(out, 1);
}

// round 16
// speedup vs baseline: 1.6646x; 1.0606x over previous
#include <cuda_runtime.h>
#include <cuda_bf16.h>
#include <math.h>
#include <cstdint>
#include <stdint.h>

#define B_    4
#define S_    1024
#define DIM_  2048
#define H_    16
#define HD_   128
#define BSTOT 4096   // B_*S_
#define NSB   8      // S_/128 blocks
#define NTRI  36     // lower-tri 128x128 tiles per head

// ---------------- scratch ----------------
__device__ float d_V[(size_t)H_*B_*S_*HD_];      // fp32 V (for suffix sums)
__device__ float d_O[(size_t)BSTOT*DIM_];
__device__ float d_G[(size_t)BSTOT*DIM_];        // relu(x@wg) fp32
__device__ float d_bsum[(size_t)H_*B_*NSB*HD_];
__device__ float d_suf[(size_t)H_*B_*NSB*HD_];
__device__ float d_rs[H_*S_];
__device__ float d_l2g[H_];
// bf16 hi/lo operand buffers
__device__ __nv_bfloat16 d_Qh[(size_t)H_*B_*S_*HD_];  // [h,b,s,e]
__device__ __nv_bfloat16 d_Ql[(size_t)H_*B_*S_*HD_];
__device__ __nv_bfloat16 d_Kh[(size_t)H_*B_*S_*HD_];  // [h,b,t,e]
__device__ __nv_bfloat16 d_Kl[(size_t)H_*B_*S_*HD_];
__device__ __nv_bfloat16 d_Vth[(size_t)H_*B_*HD_*S_]; // V^T [h,b,e,t]
__device__ __nv_bfloat16 d_Vtl[(size_t)H_*B_*HD_*S_];
__device__ __nv_bfloat16 d_Ahh[(size_t)H_*S_*S_];     // A [h,s,t] hi
__device__ __nv_bfloat16 d_Ahl[(size_t)H_*S_*S_];     // A lo
__device__ __nv_bfloat16 d_xh[(size_t)BSTOT*DIM_];    // x hi, later G*Y hi [m][k]
__device__ __nv_bfloat16 d_xl[(size_t)BSTOT*DIM_];
__device__ __nv_bfloat16 d_wgh[(size_t)DIM_*DIM_];    // wg^T [n][k]
__device__ __nv_bfloat16 d_wgl[(size_t)DIM_*DIM_];
__device__ __nv_bfloat16 d_woh[(size_t)DIM_*DIM_];
__device__ __nv_bfloat16 d_wol[(size_t)DIM_*DIM_];

// ---------------- decay tables ----------------
__global__ void decay_kernel() {
    int h = blockIdx.x;
    int j = threadIdx.x;
    double g  = 1.0 - exp2((double)(-5 - h));
    double r  = 1.0 / g;
    double rp = pow(r, (double)(j + 1));
    double Sj = (rp - 1.0) / (r - 1.0);
    d_rs[h * S_ + j] = (float)(1.0 / sqrt(Sj));
    if (j == 0) d_l2g[h] = (float)log2(g);
}

// ---------------- fp32 -> (hi,lo) bf16 split (x only) ----------------
__global__ void split_kernel(const float* __restrict__ srcParam) {
    const float* src = srcParam;
    __nv_bfloat16* hi = d_xh;
    __nv_bfloat16* lo = d_xl;
    size_t i = (size_t)(blockIdx.x) * blockDim.x + threadIdx.x;
    float4 v = ((const float4*)src)[i];
    __nv_bfloat16 h0 = __float2bfloat16(v.x);
    __nv_bfloat16 h1 = __float2bfloat16(v.y);
    __nv_bfloat16 h2 = __float2bfloat16(v.z);
    __nv_bfloat16 h3 = __float2bfloat16(v.w);
    __nv_bfloat16 l0 = __float2bfloat16(v.x - __bfloat162float(h0));
    __nv_bfloat16 l1 = __float2bfloat16(v.y - __bfloat162float(h1));
    __nv_bfloat16 l2 = __float2bfloat16(v.z - __bfloat162float(h2));
    __nv_bfloat16 l3 = __float2bfloat16(v.w - __bfloat162float(h3));
    __nv_bfloat162 hA; hA.x = h0; hA.y = h1;
    __nv_bfloat162 hB; hB.x = h2; hB.y = h3;
    __nv_bfloat162 lA; lA.x = l0; lA.y = l1;
    __nv_bfloat162 lB; lB.x = l2; lB.y = l3;
    *(__nv_bfloat162*)&hi[i * 4]     = hA;
    *(__nv_bfloat162*)&hi[i * 4 + 2] = hB;
    *(__nv_bfloat162*)&lo[i * 4]     = lA;
    *(__nv_bfloat162*)&lo[i * 4 + 2] = lB;
}

// ---------------- weight transpose + split ----
__global__ void wtrans_kernel(const float* __restrict__ w, int which) {
    __nv_bfloat16* hi = (which == 0) ? d_wgh : d_woh;
    __nv_bfloat16* lo = (which == 0) ? d_wgl : d_wol;
    __shared__ float tile[32][33];
    const int bx = blockIdx.x * 32;
    const int by = blockIdx.y * 32;
    const int tx = threadIdx.x;
    const int ty = threadIdx.y;
#pragma unroll
    for (int i = 0; i < 4; i++) {
        int r = ty * 4 + i;
        tile[r][tx] = w[(size_t)(by + r) * DIM_ + bx + tx];
    }
    __syncthreads();
#pragma unroll
    for (int i = 0; i < 4; i++) {
        int nl = ty * 4 + i;
        float vv = tile[tx][nl];
        __nv_bfloat16 hv = __float2bfloat16(vv);
        __nv_bfloat16 lv = __float2bfloat16(vv - __bfloat162float(hv));
        size_t idx = (size_t)(bx + nl) * DIM_ + by + tx;
        hi[idx] = hv;
        lo[idx] = lv;
    }
}

// ---------------- QKV projection: 128x128 tile, 8x8 micro (R5-ff shape) --
__global__ __launch_bounds__(256, 2)
void qkv_kernel(const float* __restrict__ x,
                const float* __restrict__ kin,
                const float* __restrict__ vin,
                const float* __restrict__ Wh) {
    const int h     = blockIdx.y;
    const int which = blockIdx.z;
    const float* src = (which == 0) ? x : (which == 1) ? kin : vin;
    const int m0 = blockIdx.x * 128;

    __shared__ float Xs[16][136];
    __shared__ float Ws[16][128];

    const int tid = threadIdx.x;
    const int tx = tid & 15, ty = tid >> 4;
    float acc[8][8];
#pragma unroll
    for (int i = 0; i < 8; i++)
#pragma unroll
        for (int j = 0; j < 8; j++) acc[i][j] = 0.0f;

    const int b = m0 >> 10;
    const int sl = m0 & 1023;
    const float* srow = src + (size_t)(b * S_ + sl) * DIM_ + h * HD_;

    for (int k0 = 0; k0 < HD_; k0 += 16) {
        // X tile: 128 rows x 16 cols, transposed
#pragma unroll
        for (int i = 0; i < 2; i++) {
            int idx = tid + i * 256;          // 0..511
            int r = idx >> 2, c4 = idx & 3;
            float4 vv = *(const float4*)&srow[(size_t)r * DIM_ + k0 + c4 * 4];
            Xs[c4 * 4 + 0][r] = vv.x;
            Xs[c4 * 4 + 1][r] = vv.y;
            Xs[c4 * 4 + 2][r] = vv.z;
            Xs[c4 * 4 + 3][r] = vv.w;
        }
        // W tile: 16 rows x 128 cols, direct
#pragma unroll
        for (int i = 0; i < 2; i++) {
            int idx = tid + i * 256;
            int r = idx >> 5, c4 = idx & 31;
            *(float4*)&Ws[r][c4 * 4] =
                *(const float4*)&Wh[((size_t)h * HD_ + k0 + r) * HD_ + c4 * 4];
        }
        __syncthreads();
#pragma unroll
        for (int kk = 0; kk < 16; kk++) {
            float4 a0 = *(float4*)&Xs[kk][ty * 8];
            float4 a1 = *(float4*)&Xs[kk][ty * 8 + 4];
            float4 b0 = *(float4*)&Ws[kk][tx * 8];
            float4 b1 = *(float4*)&Ws[kk][tx * 8 + 4];
            float a[8]  = {a0.x, a0.y, a0.z, a0.w, a1.x, a1.y, a1.z, a1.w};
            float bb[8] = {b0.x, b0.y, b0.z, b0.w, b1.x, b1.y, b1.z, b1.w};
#pragma unroll
            for (int i = 0; i < 8; i++)
#pragma unroll
                for (int j = 0; j < 8; j++) acc[i][j] += a[i] * bb[j];
        }
        __syncthreads();
    }

    if (which < 2) {
        __nv_bfloat16* hid = (which == 0) ? d_Qh : d_Kh;
        __nv_bfloat16* lod = (which == 0) ? d_Ql : d_Kl;
#pragma unroll
        for (int i = 0; i < 8; i++) {
            int s = sl + ty * 8 + i;
            __nv_bfloat16 hp[8], lp[8];
#pragma unroll
            for (int j = 0; j < 8; j++) {
                hp[j] = __float2bfloat16(acc[i][j]);
                lp[j] = __float2bfloat16(acc[i][j] - __bfloat162float(hp[j]));
            }
            size_t off = ((size_t)(h * B_ + b) * S_ + s) * HD_ + tx * 8;
            *(uint4*)&hid[off] = *(uint4*)hp;
            *(uint4*)&lod[off] = *(uint4*)lp;
        }
    } else {
#pragma unroll
        for (int i = 0; i < 8; i++) {
            int s = sl + ty * 8 + i;
            float* drow = d_V + ((size_t)(h * B_ + b) * S_ + s) * HD_ + tx * 8;
            float4 o0 = {acc[i][0], acc[i][1], acc[i][2], acc[i][3]};
            float4 o1 = {acc[i][4], acc[i][5], acc[i][6], acc[i][7]};
            *(float4*)&drow[0] = o0;
            *(float4*)&drow[4] = o1;
        }
        // V^T: 8 consecutive s per thread -> single uint4 per (e, hi/lo)
        int s8 = sl + ty * 8;
#pragma unroll
        for (int j = 0; j < 8; j++) {
            int e = tx * 8 + j;
            __nv_bfloat16 hp[8], lp[8];
#pragma unroll
            for (int i = 0; i < 8; i++) {
                hp[i] = __float2bfloat16(acc[i][j]);
                lp[i] = __float2bfloat16(acc[i][j] - __bfloat162float(hp[i]));
            }
            size_t off = ((size_t)(h * B_ + b) * HD_ + e) * S_ + s8;
            *(uint4*)&d_Vth[off] = *(uint4*)hp;
            *(uint4*)&d_Vtl[off] = *(uint4*)lp;
        }
    }
}

// ---------------- suffix phase A ----------
__global__ void bsum_kernel() {
    const int hb = blockIdx.x;
    const int i  = blockIdx.y;
    const int e  = threadIdx.x;
    const float* blk = d_V + ((size_t)hb * S_ + i * 128) * HD_;
    float a0 = 0.f, a1 = 0.f, a2 = 0.f, a3 = 0.f;
#pragma unroll 8
    for (int t = 0; t < 128; t += 4) {
        a0 += blk[(t + 0) * HD_ + e];
        a1 += blk[(t + 1) * HD_ + e];
        a2 += blk[(t + 2) * HD_ + e];
        a3 += blk[(t + 3) * HD_ + e];
    }
    d_bsum[((size_t)hb * NSB + i) * HD_ + e] = (a0 + a1) + (a2 + a3);
}

// ---------------- suffix phase B ----
__global__ void sufscan_kernel() {
    const int hb = blockIdx.x;
    const int e  = threadIdx.x;
    float acc = 0.f;
#pragma unroll
    for (int i = NSB - 1; i >= 0; i--) {
        d_suf[((size_t)hb * NSB + i) * HD_ + e] = acc;
        acc += d_bsum[((size_t)hb * NSB + i) * HD_ + e];
    }
}

// ---------------- shared mma helpers ----------
#define T_LDS   40
#define STG_B   (128 * T_LDS * 2)
#define STAGE_B (2 * STG_B)
#define PIPE_SMEM (3 * STAGE_B)

__device__ __forceinline__ void ldsm4(unsigned int& r0, unsigned int& r1,
                                      unsigned int& r2, unsigned int& r3, unsigned int addr) {
    asm volatile("ldmatrix.sync.aligned.m8n8.x4.shared.b16 {%0,%1,%2,%3}, [%4];"
                 : "=r"(r0), "=r"(r1), "=r"(r2), "=r"(r3) : "r"(addr));
}
__device__ __forceinline__ void mma16816(float* c, const unsigned int* a, const unsigned int* b) {
    asm volatile("mma.sync.aligned.m16n8k16.row.col.f32.bf16.bf16.f32 "
                 "{%0,%1,%2,%3}, {%4,%5,%6,%7}, {%8,%9}, {%0,%1,%2,%3};"
                 : "+f"(c[0]), "+f"(c[1]), "+f"(c[2]), "+f"(c[3])
                 : "r"(a[0]), "r"(a[1]), "r"(a[2]), "r"(a[3]), "r"(b[0]), "r"(b[1]));
}
__device__ __forceinline__ void cpa16(unsigned int dst, const void* src) {
    asm volatile("cp.async.cg.shared.global [%0], [%1], 16;" :: "r"(dst), "l"(src));
}

// ---------------- scores tensor kernel: 3-stage cp.async pipeline ----------
__global__ __launch_bounds__(256, 2)
void scores_tensor_kernel() {
    extern __shared__ __align__(16) unsigned char p_smem[];
    const int h = blockIdx.y;
    int kidx = blockIdx.x;
    int si = 0;
    while ((si + 1) * (si + 2) / 2 <= kidx) si++;
    const int tj = kidx - si * (si + 1) / 2;
    const int s0 = si * 128, t0 = tj * 128;

    const int tid  = threadIdx.x;
    const int wid  = tid >> 5;
    const int lane = tid & 31;
    const int wm = wid & 3;
    const int wn = wid >> 2;

    const unsigned int smbase = (unsigned int)__cvta_generic_to_shared(p_smem);

    const __nv_bfloat16* APtr[3] = {d_Qh, d_Qh, d_Ql};
    const __nv_bfloat16* BPtr[3] = {d_Kh, d_Kl, d_Kh};

    float acc[2][8][4];
#pragma unroll
    for (int i = 0; i < 2; i++)
#pragma unroll
        for (int j = 0; j < 8; j++)
#pragma unroll
            for (int c = 0; c < 4; c++) acc[i][j][c] = 0.0f;

    const int a_r  = lane & 15;
    const int a_k8 = ((lane >> 4) & 1) * 8;
    const int b_r  = ((lane >> 4) << 3) + (lane & 7);
    const int b_k8 = ((lane >> 3) & 1) * 8;

    const int NITER = 48;
    const int ia0 = tid, ia1 = tid + 256;
    const unsigned int sa0 = (unsigned int)((ia0 >> 2) * T_LDS + (ia0 & 3) * 8) * 2;
    const unsigned int sa1 = (unsigned int)((ia1 >> 2) * T_LDS + (ia1 & 3) * 8) * 2;

    auto stage = [&](int j) {
        int term = j >> 4;
        int kk = (j & 15) * 32;
        int b = kk >> 7, e0 = kk & 127;
        const __nv_bfloat16* Ag = APtr[term] + ((size_t)(h * B_ + b) * S_ + s0) * HD_ + e0;
        const __nv_bfloat16* Bg = BPtr[term] + ((size_t)(h * B_ + b) * S_ + t0) * HD_ + e0;
        unsigned int abase = smbase + (j % 3) * STAGE_B;
        unsigned int bbase = abase + STG_B;
        cpa16(abase + sa0, Ag + (size_t)(ia0 >> 2) * HD_ + (ia0 & 3) * 8);
        cpa16(abase + sa1, Ag + (size_t)(ia1 >> 2) * HD_ + (ia1 & 3) * 8);
        cpa16(bbase + sa0, Bg + (size_t)(ia0 >> 2) * HD_ + (ia0 & 3) * 8);
        cpa16(bbase + sa1, Bg + (size_t)(ia1 >> 2) * HD_ + (ia1 & 3) * 8);
        asm volatile("cp.async.commit_group;");
    };

    stage(0);
    stage(1);

    for (int it = 0; it < NITER; it++) {
        if (it + 1 < NITER) { asm volatile("cp.async.wait_group 1;"); }
        else                { asm volatile("cp.async.wait_group 0;"); }
        __syncthreads();
        if (it + 2 < NITER) stage(it + 2);

        const unsigned int asb = smbase + (it % 3) * STAGE_B;
        const unsigned int bsb = asb + STG_B;
#pragma unroll
        for (int ks = 0; ks < 2; ks++) {
            const int kb = ks * 16;
            unsigned int af[2][4];
#pragma unroll
            for (int mi = 0; mi < 2; mi++) {
                int row = wm * 32 + mi * 16 + a_r;
                unsigned int addr = asb + (unsigned int)(row * T_LDS + kb + a_k8) * 2;
                ldsm4(af[mi][0], af[mi][1], af[mi][2], af[mi][3], addr);
            }
#pragma unroll
            for (int nj = 0; nj < 4; nj++) {
                int nrow = wn * 64 + nj * 16 + b_r;
                unsigned int addr = bsb + (unsigned int)(nrow * T_LDS + kb + b_k8) * 2;
                unsigned int bf[4];
                ldsm4(bf[0], bf[1], bf[2], bf[3], addr);
#pragma unroll
                for (int mi = 0; mi < 2; mi++) {
                    mma16816(acc[mi][nj * 2 + 0], af[mi], &bf[0]);
                    mma16816(acc[mi][nj * 2 + 1], af[mi], &bf[2]);
                }
            }
        }
    }

    const float l2g = d_l2g[h];
    const float inv_sqrt_hd = 0.08838834764831845f;
    __nv_bfloat16* Ahh = d_Ahh + (size_t)h * S_ * S_;
    __nv_bfloat16* Ahl = d_Ahl + (size_t)h * S_ * S_;
    const int qr = lane >> 2;
    const int qc = (lane & 3) * 2;
#pragma unroll
    for (int mi = 0; mi < 2; mi++) {
#pragma unroll
        for (int n8 = 0; n8 < 8; n8++) {
            int t1 = t0 + wn * 64 + n8 * 8 + qc;
            float rs1 = d_rs[h * S_ + t1];
            float rs2 = d_rs[h * S_ + t1 + 1];
#pragma unroll
            for (int half = 0; half < 2; half++) {
                int s = s0 + wm * 32 + mi * 16 + qr + half * 8;
                float a1 = acc[mi][n8][half * 2 + 0];
                float a2 = acc[mi][n8][half * 2 + 1];
                float v1 = (t1 > s) ? 1.0f
                   : fmaxf(fabsf(a1 * inv_sqrt_hd * exp2f((float)(t1 - s) * l2g) * rs1), 1.0f);
                float v2 = (t1 + 1 > s) ? 1.0f
                   : fmaxf(fabsf(a2 * inv_sqrt_hd * exp2f((float)(t1 + 1 - s) * l2g) * rs2), 1.0f);
                __nv_bfloat16 h1 = __float2bfloat16(v1);
                __nv_bfloat16 h2 = __float2bfloat16(v2);
                __nv_bfloat16 l1 = __float2bfloat16(v1 - __bfloat162float(h1));
                __nv_bfloat16 l2 = __float2bfloat16(v2 - __bfloat162float(h2));
                __nv_bfloat162 hp; hp.x = h1; hp.y = h2;
                __nv_bfloat162 lp; lp.x = l1; lp.y = l2;
                *(__nv_bfloat162*)&Ahh[(size_t)s * S_ + t1] = hp;
                *(__nv_bfloat162*)&Ahl[(size_t)s * S_ + t1] = lp;
            }
        }
    }
}

// ---------------- ogemm tensor kernel: cp.async pipeline, big tiles first -
__global__ __launch_bounds__(256, 2)
void ogemm_tensor_kernel() {
    extern __shared__ __align__(16) unsigned char p_smem[];
    const int bh = blockIdx.y;
    const int b = bh >> 4, h = bh & 15;
    const int si = NSB - 1 - blockIdx.x;     // big tiles scheduled first
    const int s0 = si * 128;
    const int KT = (si + 1) * 4;

    const int tid  = threadIdx.x;
    const int wid  = tid >> 5;
    const int lane = tid & 31;
    const int wm = wid & 3;
    const int wn = wid >> 2;

    const unsigned int smbase = (unsigned int)__cvta_generic_to_shared(p_smem);

    const __nv_bfloat16* Abase_h = d_Ahh + (size_t)h * S_ * S_;
    const __nv_bfloat16* Abase_l = d_Ahl + (size_t)h * S_ * S_;
    const __nv_bfloat16* Vbase_h = d_Vth + (size_t)(h * B_ + b) * HD_ * S_;
    const __nv_bfloat16* Vbase_l = d_Vtl + (size_t)(h * B_ + b) * HD_ * S_;
    const __nv_bfloat16* APtr[3] = {Abase_h, Abase_h, Abase_l};
    const __nv_bfloat16* BPtr[3] = {Vbase_h, Vbase_l, Vbase_h};

    float acc[2][8][4];
#pragma unroll
    for (int i = 0; i < 2; i++)
#pragma unroll
        for (int j = 0; j < 8; j++)
#pragma unroll
            for (int c = 0; c < 4; c++) acc[i][j][c] = 0.0f;

    const int a_r  = lane & 15;
    const int a_k8 = ((lane >> 4) & 1) * 8;
    const int b_r  = ((lane >> 4) << 3) + (lane & 7);
    const int b_k8 = ((lane >> 3) & 1) * 8;

    const int NITER = 3 * KT;
    const int ia0 = tid, ia1 = tid + 256;
    const unsigned int sa0 = (unsigned int)((ia0 >> 2) * T_LDS + (ia0 & 3) * 8) * 2;
    const unsigned int sa1 = (unsigned int)((ia1 >> 2) * T_LDS + (ia1 & 3) * 8) * 2;

    auto stage = [&](int j) {
        int term = j / KT;
        int kk = (j - term * KT) * 32;
        const __nv_bfloat16* Ag = APtr[term] + (size_t)s0 * S_ + kk;
        const __nv_bfloat16* Bg = BPtr[term] + kk;
        unsigned int abase = smbase + (j % 3) * STAGE_B;
        unsigned int bbase = abase + STG_B;
        cpa16(abase + sa0, Ag + (size_t)(ia0 >> 2) * S_ + (ia0 & 3) * 8);
        cpa16(abase + sa1, Ag + (size_t)(ia1 >> 2) * S_ + (ia1 & 3) * 8);
        cpa16(bbase + sa0, Bg + (size_t)(ia0 >> 2) * S_ + (ia0 & 3) * 8);
        cpa16(bbase + sa1, Bg + (size_t)(ia1 >> 2) * S_ + (ia1 & 3) * 8);
        asm volatile("cp.async.commit_group;");
    };

    stage(0);
    if (NITER > 1) stage(1);

    for (int it = 0; it < NITER; it++) {
        if (it + 1 < NITER) { asm volatile("cp.async.wait_group 1;"); }
        else                { asm volatile("cp.async.wait_group 0;"); }
        __syncthreads();
        if (it + 2 < NITER) stage(it + 2);

        const unsigned int asb = smbase + (it % 3) * STAGE_B;
        const unsigned int bsb = asb + STG_B;
#pragma unroll
        for (int ks = 0; ks < 2; ks++) {
            const int kb = ks * 16;
            unsigned int af[2][4];
#pragma unroll
            for (int mi = 0; mi < 2; mi++) {
                int row = wm * 32 + mi * 16 + a_r;
                unsigned int addr = asb + (unsigned int)(row * T_LDS + kb + a_k8) * 2;
                ldsm4(af[mi][0], af[mi][1], af[mi][2], af[mi][3], addr);
            }
#pragma unroll
            for (int nj = 0; nj < 4; nj++) {
                int nrow = wn * 64 + nj * 16 + b_r;
                unsigned int addr = bsb + (unsigned int)(nrow * T_LDS + kb + b_k8) * 2;
                unsigned int bf[4];
                ldsm4(bf[0], bf[1], bf[2], bf[3], addr);
#pragma unroll
                for (int mi = 0; mi < 2; mi++) {
                    mma16816(acc[mi][nj * 2 + 0], af[mi], &bf[0]);
                    mma16816(acc[mi][nj * 2 + 1], af[mi], &bf[2]);
                }
            }
        }
    }

    const float* suf = d_suf + ((size_t)(h * B_ + b) * NSB + si) * HD_;
    const int qr = lane >> 2;
    const int qc = (lane & 3) * 2;
#pragma unroll
    for (int mi = 0; mi < 2; mi++) {
#pragma unroll
        for (int n8 = 0; n8 < 8; n8++) {
            int e = wn * 64 + n8 * 8 + qc;
            float sv1 = suf[e], sv2 = suf[e + 1];
            int s = s0 + wm * 32 + mi * 16 + qr;
            float2 v0; v0.x = acc[mi][n8][0] + sv1; v0.y = acc[mi][n8][1] + sv2;
            float2 v1; v1.x = acc[mi][n8][2] + sv1; v1.y = acc[mi][n8][3] + sv2;
            *(float2*)&d_O[(size_t)(b * S_ + s) * DIM_ + h * HD_ + e] = v0;
            *(float2*)&d_O[(size_t)(b * S_ + s + 8) * DIM_ + h * HD_ + e] = v1;
        }
    }
}

// ---------------- tensor-core FF GEMM: 3-stage cp.async pipeline (R14) ---
#define FF_K    DIM_
__global__ __launch_bounds__(256, 2)
void ff_tensor_kernel(float* __restrict__ outParam, int mode) {
    extern __shared__ __align__(16) unsigned char p_smem[];

    const __nv_bfloat16* Ahp = d_xh;
    const __nv_bfloat16* Alp = d_xl;
    const __nv_bfloat16* Bhp = (mode == 0) ? d_wgh : d_woh;
    const __nv_bfloat16* Blp = (mode == 0) ? d_wgl : d_wol;
    float* Cm = (mode == 0) ? d_G : outParam;

    const int n0 = blockIdx.x * 128;
    const int m0 = blockIdx.y * 128;

    const int tid  = threadIdx.x;
    const int wid  = tid >> 5;
    const int lane = tid & 31;
    const int wm = wid & 3;
    const int wn = wid >> 2;

    const unsigned int smbase = (unsigned int)__cvta_generic_to_shared(p_smem);

    const __nv_bfloat16* APtr[3] = {Ahp, Ahp, Alp};
    const __nv_bfloat16* BPtr[3] = {Bhp, Blp, Bhp};

    float acc[2][8][4];
#pragma unroll
    for (int i = 0; i < 2; i++)
#pragma unroll
        for (int j = 0; j < 8; j++)
#pragma unroll
            for (int c = 0; c < 4; c++) acc[i][j][c] = 0.0f;

    const int a_r  = lane & 15;
    const int a_k8 = ((lane >> 4) & 1) * 8;
    const int b_r  = ((lane >> 4) << 3) + (lane & 7);
    const int b_k8 = ((lane >> 3) & 1) * 8;

    const int NITER = 3 * (FF_K / 32);
    const int ia0 = tid, ia1 = tid + 256;
    const unsigned int sa0 = (unsigned int)((ia0 >> 2) * T_LDS + (ia0 & 3) * 8) * 2;
    const unsigned int sa1 = (unsigned int)((ia1 >> 2) * T_LDS + (ia1 & 3) * 8) * 2;

    auto stage = [&](int j) {
        int term = j >> 6;
        int k0 = (j & 63) * 32;
        const __nv_bfloat16* Ag = APtr[term] + (size_t)m0 * FF_K + k0;
        const __nv_bfloat16* Bg = BPtr[term] + (size_t)n0 * FF_K + k0;
        unsigned int abase = smbase + (j % 3) * STAGE_B;
        unsigned int bbase = abase + STG_B;
        cpa16(abase + sa0, Ag + (size_t)(ia0 >> 2) * FF_K + (ia0 & 3) * 8);
        cpa16(abase + sa1, Ag + (size_t)(ia1 >> 2) * FF_K + (ia1 & 3) * 8);
        cpa16(bbase + sa0, Bg + (size_t)(ia0 >> 2) * FF_K + (ia0 & 3) * 8);
        cpa16(bbase + sa1, Bg + (size_t)(ia1 >> 2) * FF_K + (ia1 & 3) * 8);
        asm volatile("cp.async.commit_group;");
    };

    stage(0);
    stage(1);

    for (int it = 0; it < NITER; it++) {
        if (it + 1 < NITER) { asm volatile("cp.async.wait_group 1;"); }
        else                { asm volatile("cp.async.wait_group 0;"); }
        __syncthreads();
        if (it + 2 < NITER) stage(it + 2);

        const unsigned int asb = smbase + (it % 3) * STAGE_B;
        const unsigned int bsb = asb + STG_B;
#pragma unroll
        for (int ks = 0; ks < 2; ks++) {
            const int kb = ks * 16;
            unsigned int af[2][4];
#pragma unroll
            for (int mi = 0; mi < 2; mi++) {
                int row = wm * 32 + mi * 16 + a_r;
                unsigned int addr = asb + (unsigned int)(row * T_LDS + kb + a_k8) * 2;
                ldsm4(af[mi][0], af[mi][1], af[mi][2], af[mi][3], addr);
            }
#pragma unroll
            for (int nj = 0; nj < 4; nj++) {
                int nrow = wn * 64 + nj * 16 + b_r;
                unsigned int addr = bsb + (unsigned int)(nrow * T_LDS + kb + b_k8) * 2;
                unsigned int bf[4];
                ldsm4(bf[0], bf[1], bf[2], bf[3], addr);
#pragma unroll
                for (int mi = 0; mi < 2; mi++) {
                    mma16816(acc[mi][nj * 2 + 0], af[mi], &bf[0]);
                    mma16816(acc[mi][nj * 2 + 1], af[mi], &bf[2]);
                }
            }
        }
    }

    const int qr = lane >> 2;
    const int qc = (lane & 3) * 2;
#pragma unroll
    for (int mi = 0; mi < 2; mi++) {
#pragma unroll
        for (int n8 = 0; n8 < 8; n8++) {
            int m = m0 + wm * 32 + mi * 16 + qr;
            int n = n0 + wn * 64 + n8 * 8 + qc;
            float2 v0; v0.x = acc[mi][n8][0]; v0.y = acc[mi][n8][1];
            float2 v1; v1.x = acc[mi][n8][2]; v1.y = acc[mi][n8][3];
            if (mode == 0) {
                v0.x = fmaxf(v0.x, 0.f); v0.y = fmaxf(v0.y, 0.f);
                v1.x = fmaxf(v1.x, 0.f); v1.y = fmaxf(v1.y, 0.f);
            }
            *(float2*)&Cm[(size_t)m * DIM_ + n] = v0;
            *(float2*)&Cm[(size_t)(m + 8) * DIM_ + n] = v1;
        }
    }
}

// ---------------- layernorm + gate mul, fused bf16 hi/lo output ----------
__global__ void gn_kernel(const float* __restrict__ gamma,
                          const float* __restrict__ beta) {
    const int row = blockIdx.x;
    const float* orow = d_O + (size_t)row * DIM_;
    const float* grow = d_G + (size_t)row * DIM_;
    __nv_bfloat16* hrow = d_xh + (size_t)row * DIM_;
    __nv_bfloat16* lrow = d_xl + (size_t)row * DIM_;
    const int tid = threadIdx.x;

    float v[8];
#pragma unroll
    for (int i = 0; i < 2; i++) {
        float4 t = *(const float4*)&orow[tid * 8 + i * 4];
        v[i * 4 + 0] = t.x; v[i * 4 + 1] = t.y;
        v[i * 4 + 2] = t.z; v[i * 4 + 3] = t.w;
    }

    __shared__ float red[8];
    __shared__ float s_mu, s_inv;

    float lsum = 0.f;
#pragma unroll
    for (int i = 0; i < 8; i++) lsum += v[i];
#pragma unroll
    for (int off = 16; off > 0; off >>= 1) lsum += __shfl_xor_sync(0xffffffffu, lsum, off);
    if ((tid & 31) == 0) red[tid >> 5] = lsum;
    __syncthreads();
    if (tid == 0) {
        float s = 0.f;
#pragma unroll
        for (int w = 0; w < 8; w++) s += red[w];
        s_mu = s * (1.0f / DIM_);
    }
    __syncthreads();
    const float mu = s_mu;

    float lsq = 0.f;
#pragma unroll
    for (int i = 0; i < 8; i++) {
        float d = v[i] - mu;
        lsq += d * d;
    }
#pragma unroll
    for (int off = 16; off > 0; off >>= 1) lsq += __shfl_xor_sync(0xffffffffu, lsq, off);
    __syncthreads();
    if ((tid & 31) == 0) red[tid >> 5] = lsq;
    __syncthreads();
    if (tid == 0) {
        float s = 0.f;
#pragma unroll
        for (int w = 0; w < 8; w++) s += red[w];
        s_inv = rsqrtf(s * (1.0f / DIM_) + 1e-3f);
    }
    __syncthreads();
    const float inv = s_inv;

#pragma unroll
    for (int i = 0; i < 2; i++) {
        int c0 = tid * 8 + i * 4;
        float4 g4 = *(const float4*)&grow[c0];
        float4 gm = *(const float4*)&gamma[c0];
        float4 bt = *(const float4*)&beta[c0];
        float o0 = g4.x * ((v[i * 4 + 0] - mu) * inv * gm.x + bt.x);
        float o1 = g4.y * ((v[i * 4 + 1] - mu) * inv * gm.y + bt.y);
        float o2 = g4.z * ((v[i * 4 + 2] - mu) * inv * gm.z + bt.z);
        float o3 = g4.w * ((v[i * 4 + 3] - mu) * inv * gm.w + bt.w);
        __nv_bfloat16 h0 = __float2bfloat16(o0);
        __nv_bfloat16 h1 = __float2bfloat16(o1);
        __nv_bfloat16 h2 = __float2bfloat16(o2);
        __nv_bfloat16 h3 = __float2bfloat16(o3);
        __nv_bfloat16 l0 = __float2bfloat16(o0 - __bfloat162float(h0));
        __nv_bfloat16 l1 = __float2bfloat16(o1 - __bfloat162float(h1));
        __nv_bfloat16 l2 = __float2bfloat16(o2 - __bfloat162float(h2));
        __nv_bfloat16 l3 = __float2bfloat16(o3 - __bfloat162float(h3));
        __nv_bfloat162 hA; hA.x = h0; hA.y = h1;
        __nv_bfloat162 hB; hB.x = h2; hB.y = h3;
        __nv_bfloat162 lA; lA.x = l0; lA.y = l1;
        __nv_bfloat162 lB; lB.x = l2; lB.y = l3;
        *(__nv_bfloat162*)&hrow[c0]     = hA;
        *(__nv_bfloat162*)&hrow[c0 + 2] = hB;
        *(__nv_bfloat162*)&lrow[c0]     = lA;
        *(__nv_bfloat162*)&lrow[c0 + 2] = lB;
    }
}

// ---------------- launch ----------------
extern "C" void kernel_launch(void* const* d_in, const int* in_sizes, int n_in,
                              void* d_out, int out_size) {
    const float* x     = (const float*)d_in[0];
    const float* k     = (const float*)d_in[1];
    const float* v     = (const float*)d_in[2];
    const float* Wh    = (const float*)d_in[3];
    const float* wg_w  = (const float*)d_in[4];
    const float* wo_w  = (const float*)d_in[5];
    const float* gamma = (const float*)d_in[6];
    const float* beta  = (const float*)d_in[7];
    float* out = (float*)d_out;

    cudaFuncSetAttribute(ff_tensor_kernel,
                         cudaFuncAttributeMaxDynamicSharedMemorySize, PIPE_SMEM);
    cudaFuncSetAttribute(scores_tensor_kernel,
                         cudaFuncAttributeMaxDynamicSharedMemorySize, PIPE_SMEM);
    cudaFuncSetAttribute(ogemm_tensor_kernel,
                         cudaFuncAttributeMaxDynamicSharedMemorySize, PIPE_SMEM);

    decay_kernel<<<H_, S_>>>();
    qkv_kernel<<<dim3(BSTOT / 128, H_, 3), 256>>>(x, k, v, Wh);
    bsum_kernel<<<dim3(H_ * B_, NSB), HD_>>>();
    sufscan_kernel<<<H_ * B_, HD_>>>();
    scores_tensor_kernel<<<dim3(NTRI, H_), 256, PIPE_SMEM>>>();

    wtrans_kernel<<<dim3(DIM_ / 32, DIM_ / 32), dim3(32, 8)>>>(wg_w, 0);
    wtrans_kernel<<<dim3(DIM_ / 32, DIM_ / 32), dim3(32, 8)>>>(wo_w, 1);
    split_kernel<<<(BSTOT * (DIM_ / 4)) / 256, 256>>>(x);

    ff_tensor_kernel<<<dim3(DIM_ / 128, BSTOT / 128), 256, PIPE_SMEM>>>(out, 0);
    ogemm_tensor_kernel<<<dim3(NSB, B_ * H_), 256, PIPE_SMEM>>>();
    gn_kernel<<<BSTOT, 256>>>(gamma, beta);
    ff_tensor_kernel<<<dim3(DIM_ / 128, BSTOT / 128), 256, PIPE_SMEM>>>(out, 1);
}

// round 17
// speedup vs baseline: 1.7094x; 1.0269x over previous
#include <cuda_runtime.h>
#include <cuda_bf16.h>
#include <math.h>
#include <cstdint>
#include <stdint.h>

#define B_    4
#define S_    1024
#define DIM_  2048
#define H_    16
#define HD_   128
#define BSTOT 4096   // B_*S_
#define NSB   8      // S_/128 blocks
#define NTRI  36     // lower-tri 128x128 tiles per head

// ---------------- scratch ----------------
__device__ float d_V[(size_t)H_*B_*S_*HD_];      // fp32 V (for suffix sums)
__device__ float d_O[(size_t)BSTOT*DIM_];
__device__ float d_G[(size_t)BSTOT*DIM_];        // relu(x@wg) fp32
__device__ float d_bsum[(size_t)H_*B_*NSB*HD_];
__device__ float d_suf[(size_t)H_*B_*NSB*HD_];
__device__ float d_rs[H_*S_];
__device__ float d_l2g[H_];
// bf16 hi/lo operand buffers
__device__ __nv_bfloat16 d_Qh[(size_t)H_*B_*S_*HD_];  // [h,b,s,e]
__device__ __nv_bfloat16 d_Ql[(size_t)H_*B_*S_*HD_];
__device__ __nv_bfloat16 d_Kh[(size_t)H_*B_*S_*HD_];  // [h,b,t,e]
__device__ __nv_bfloat16 d_Kl[(size_t)H_*B_*S_*HD_];
__device__ __nv_bfloat16 d_Vth[(size_t)H_*B_*HD_*S_]; // V^T [h,b,e,t]
__device__ __nv_bfloat16 d_Vtl[(size_t)H_*B_*HD_*S_];
__device__ __nv_bfloat16 d_Ahh[(size_t)H_*S_*S_];     // A [h,s,t] hi
__device__ __nv_bfloat16 d_Ahl[(size_t)H_*S_*S_];     // A lo
__device__ __nv_bfloat16 d_xh[(size_t)BSTOT*DIM_];    // x hi, later G*Y hi [m][k]
__device__ __nv_bfloat16 d_xl[(size_t)BSTOT*DIM_];
__device__ __nv_bfloat16 d_wgh[(size_t)DIM_*DIM_];    // wg^T [n][k]
__device__ __nv_bfloat16 d_wgl[(size_t)DIM_*DIM_];
__device__ __nv_bfloat16 d_woh[(size_t)DIM_*DIM_];
__device__ __nv_bfloat16 d_wol[(size_t)DIM_*DIM_];

// ---------------- decay tables ----------------
__global__ void decay_kernel() {
    int h = blockIdx.x;
    int j = threadIdx.x;
    double g  = 1.0 - exp2((double)(-5 - h));
    double r  = 1.0 / g;
    double rp = pow(r, (double)(j + 1));
    double Sj = (rp - 1.0) / (r - 1.0);
    d_rs[h * S_ + j] = (float)(1.0 / sqrt(Sj));
    if (j == 0) d_l2g[h] = (float)log2(g);
}

// ---------------- fp32 -> (hi,lo) bf16 split (x only) ----------------
__global__ void split_kernel(const float* __restrict__ srcParam) {
    const float* src = srcParam;
    __nv_bfloat16* hi = d_xh;
    __nv_bfloat16* lo = d_xl;
    size_t i = (size_t)(blockIdx.x) * blockDim.x + threadIdx.x;
    float4 v = ((const float4*)src)[i];
    __nv_bfloat16 h0 = __float2bfloat16(v.x);
    __nv_bfloat16 h1 = __float2bfloat16(v.y);
    __nv_bfloat16 h2 = __float2bfloat16(v.z);
    __nv_bfloat16 h3 = __float2bfloat16(v.w);
    __nv_bfloat16 l0 = __float2bfloat16(v.x - __bfloat162float(h0));
    __nv_bfloat16 l1 = __float2bfloat16(v.y - __bfloat162float(h1));
    __nv_bfloat16 l2 = __float2bfloat16(v.z - __bfloat162float(h2));
    __nv_bfloat16 l3 = __float2bfloat16(v.w - __bfloat162float(h3));
    __nv_bfloat162 hA; hA.x = h0; hA.y = h1;
    __nv_bfloat162 hB; hB.x = h2; hB.y = h3;
    __nv_bfloat162 lA; lA.x = l0; lA.y = l1;
    __nv_bfloat162 lB; lB.x = l2; lB.y = l3;
    *(__nv_bfloat162*)&hi[i * 4]     = hA;
    *(__nv_bfloat162*)&hi[i * 4 + 2] = hB;
    *(__nv_bfloat162*)&lo[i * 4]     = lA;
    *(__nv_bfloat162*)&lo[i * 4 + 2] = lB;
}

// ---------------- weight transpose + split ----
__global__ void wtrans_kernel(const float* __restrict__ wg,
                              const float* __restrict__ wo) {
    const int which = blockIdx.z;
    const float* w = (which == 0) ? wg : wo;
    __nv_bfloat16* hi = (which == 0) ? d_wgh : d_woh;
    __nv_bfloat16* lo = (which == 0) ? d_wgl : d_wol;
    __shared__ float tile[32][33];
    const int bx = blockIdx.x * 32;
    const int by = blockIdx.y * 32;
    const int tx = threadIdx.x;
    const int ty = threadIdx.y;
#pragma unroll
    for (int i = 0; i < 4; i++) {
        int r = ty * 4 + i;
        tile[r][tx] = w[(size_t)(by + r) * DIM_ + bx + tx];
    }
    __syncthreads();
#pragma unroll
    for (int i = 0; i < 4; i++) {
        int nl = ty * 4 + i;
        float vv = tile[tx][nl];
        __nv_bfloat16 hv = __float2bfloat16(vv);
        __nv_bfloat16 lv = __float2bfloat16(vv - __bfloat162float(hv));
        size_t idx = (size_t)(bx + nl) * DIM_ + by + tx;
        hi[idx] = hv;
        lo[idx] = lv;
    }
}

// ---------------- QKV projection: 128x128 tile, K-chunk 32 --------------
__global__ __launch_bounds__(256, 2)
void qkv_kernel(const float* __restrict__ x,
                const float* __restrict__ kin,
                const float* __restrict__ vin,
                const float* __restrict__ Wh) {
    const int h     = blockIdx.y;
    const int which = blockIdx.z;
    const float* src = (which == 0) ? x : (which == 1) ? kin : vin;
    const int m0 = blockIdx.x * 128;

    __shared__ float Xs[32][136];
    __shared__ float Ws[32][128];

    const int tid = threadIdx.x;
    const int tx = tid & 15, ty = tid >> 4;
    float acc[8][8];
#pragma unroll
    for (int i = 0; i < 8; i++)
#pragma unroll
        for (int j = 0; j < 8; j++) acc[i][j] = 0.0f;

    const int b = m0 >> 10;
    const int sl = m0 & 1023;
    const float* srow = src + (size_t)(b * S_ + sl) * DIM_ + h * HD_;

    for (int k0 = 0; k0 < HD_; k0 += 32) {
        // X tile: 128 rows x 32 cols, transposed (1024 float4s, 4 per thread)
#pragma unroll
        for (int i = 0; i < 4; i++) {
            int idx = tid + i * 256;          // 0..1023
            int r = idx >> 3, c4 = idx & 7;
            float4 vv = *(const float4*)&srow[(size_t)r * DIM_ + k0 + c4 * 4];
            Xs[c4 * 4 + 0][r] = vv.x;
            Xs[c4 * 4 + 1][r] = vv.y;
            Xs[c4 * 4 + 2][r] = vv.z;
            Xs[c4 * 4 + 3][r] = vv.w;
        }
        // W tile: 32 rows x 128 cols, direct
#pragma unroll
        for (int i = 0; i < 4; i++) {
            int idx = tid + i * 256;
            int r = idx >> 5, c4 = idx & 31;
            *(float4*)&Ws[r][c4 * 4] =
                *(const float4*)&Wh[((size_t)h * HD_ + k0 + r) * HD_ + c4 * 4];
        }
        __syncthreads();
#pragma unroll
        for (int kk = 0; kk < 32; kk++) {
            float4 a0 = *(float4*)&Xs[kk][ty * 8];
            float4 a1 = *(float4*)&Xs[kk][ty * 8 + 4];
            float4 b0 = *(float4*)&Ws[kk][tx * 8];
            float4 b1 = *(float4*)&Ws[kk][tx * 8 + 4];
            float a[8]  = {a0.x, a0.y, a0.z, a0.w, a1.x, a1.y, a1.z, a1.w};
            float bb[8] = {b0.x, b0.y, b0.z, b0.w, b1.x, b1.y, b1.z, b1.w};
#pragma unroll
            for (int i = 0; i < 8; i++)
#pragma unroll
                for (int j = 0; j < 8; j++) acc[i][j] += a[i] * bb[j];
        }
        __syncthreads();
    }

    if (which < 2) {
        __nv_bfloat16* hid = (which == 0) ? d_Qh : d_Kh;
        __nv_bfloat16* lod = (which == 0) ? d_Ql : d_Kl;
#pragma unroll
        for (int i = 0; i < 8; i++) {
            int s = sl + ty * 8 + i;
            __nv_bfloat16 hp[8], lp[8];
#pragma unroll
            for (int j = 0; j < 8; j++) {
                hp[j] = __float2bfloat16(acc[i][j]);
                lp[j] = __float2bfloat16(acc[i][j] - __bfloat162float(hp[j]));
            }
            size_t off = ((size_t)(h * B_ + b) * S_ + s) * HD_ + tx * 8;
            *(uint4*)&hid[off] = *(uint4*)hp;
            *(uint4*)&lod[off] = *(uint4*)lp;
        }
    } else {
#pragma unroll
        for (int i = 0; i < 8; i++) {
            int s = sl + ty * 8 + i;
            float* drow = d_V + ((size_t)(h * B_ + b) * S_ + s) * HD_ + tx * 8;
            float4 o0 = {acc[i][0], acc[i][1], acc[i][2], acc[i][3]};
            float4 o1 = {acc[i][4], acc[i][5], acc[i][6], acc[i][7]};
            *(float4*)&drow[0] = o0;
            *(float4*)&drow[4] = o1;
        }
        int s8 = sl + ty * 8;
#pragma unroll
        for (int j = 0; j < 8; j++) {
            int e = tx * 8 + j;
            __nv_bfloat16 hp[8], lp[8];
#pragma unroll
            for (int i = 0; i < 8; i++) {
                hp[i] = __float2bfloat16(acc[i][j]);
                lp[i] = __float2bfloat16(acc[i][j] - __bfloat162float(hp[i]));
            }
            size_t off = ((size_t)(h * B_ + b) * HD_ + e) * S_ + s8;
            *(uint4*)&d_Vth[off] = *(uint4*)hp;
            *(uint4*)&d_Vtl[off] = *(uint4*)lp;
        }
    }
}

// ---------------- suffix phase A ----------
__global__ void bsum_kernel() {
    const int hb = blockIdx.x;
    const int i  = blockIdx.y;
    const int e  = threadIdx.x;
    const float* blk = d_V + ((size_t)hb * S_ + i * 128) * HD_;
    float a0 = 0.f, a1 = 0.f, a2 = 0.f, a3 = 0.f;
#pragma unroll 8
    for (int t = 0; t < 128; t += 4) {
        a0 += blk[(t + 0) * HD_ + e];
        a1 += blk[(t + 1) * HD_ + e];
        a2 += blk[(t + 2) * HD_ + e];
        a3 += blk[(t + 3) * HD_ + e];
    }
    d_bsum[((size_t)hb * NSB + i) * HD_ + e] = (a0 + a1) + (a2 + a3);
}

// ---------------- suffix phase B ----
__global__ void sufscan_kernel() {
    const int hb = blockIdx.x;
    const int e  = threadIdx.x;
    float acc = 0.f;
#pragma unroll
    for (int i = NSB - 1; i >= 0; i--) {
        d_suf[((size_t)hb * NSB + i) * HD_ + e] = acc;
        acc += d_bsum[((size_t)hb * NSB + i) * HD_ + e];
    }
}

// ---------------- shared mma helpers ----------
#define T_LDS    40
#define STG_B    (128 * T_LDS * 2)       // 10240 B per operand chunk
#define STAGE_B  (2 * STG_B)             // 20480 (2-operand stage)
#define PIPE_SMEM (3 * STAGE_B)          // 61440 (scores/ogemm)
#define FF_ST1_B (3 * STG_B)             // 30720 (3-operand stage)
#define FF_SMEM  (3 * FF_ST1_B)          // 92160 (ff)

__device__ __forceinline__ void ldsm4(unsigned int& r0, unsigned int& r1,
                                      unsigned int& r2, unsigned int& r3, unsigned int addr) {
    asm volatile("ldmatrix.sync.aligned.m8n8.x4.shared.b16 {%0,%1,%2,%3}, [%4];"
                 : "=r"(r0), "=r"(r1), "=r"(r2), "=r"(r3) : "r"(addr));
}
__device__ __forceinline__ void mma16816(float* c, const unsigned int* a, const unsigned int* b) {
    asm volatile("mma.sync.aligned.m16n8k16.row.col.f32.bf16.bf16.f32 "
                 "{%0,%1,%2,%3}, {%4,%5,%6,%7}, {%8,%9}, {%0,%1,%2,%3};"
                 : "+f"(c[0]), "+f"(c[1]), "+f"(c[2]), "+f"(c[3])
                 : "r"(a[0]), "r"(a[1]), "r"(a[2]), "r"(a[3]), "r"(b[0]), "r"(b[1]));
}
__device__ __forceinline__ void cpa16(unsigned int dst, const void* src) {
    asm volatile("cp.async.cg.shared.global [%0], [%1], 16;" :: "r"(dst), "l"(src));
}

// ---------------- scores tensor kernel: 3-stage cp.async pipeline ----------
__global__ __launch_bounds__(256, 2)
void scores_tensor_kernel() {
    extern __shared__ __align__(16) unsigned char p_smem[];
    const int h = blockIdx.y;
    int kidx = blockIdx.x;
    int si = 0;
    while ((si + 1) * (si + 2) / 2 <= kidx) si++;
    const int tj = kidx - si * (si + 1) / 2;
    const int s0 = si * 128, t0 = tj * 128;

    const int tid  = threadIdx.x;
    const int wid  = tid >> 5;
    const int lane = tid & 31;
    const int wm = wid & 3;
    const int wn = wid >> 2;

    const unsigned int smbase = (unsigned int)__cvta_generic_to_shared(p_smem);

    const __nv_bfloat16* APtr[3] = {d_Qh, d_Qh, d_Ql};
    const __nv_bfloat16* BPtr[3] = {d_Kh, d_Kl, d_Kh};

    float acc[2][8][4];
#pragma unroll
    for (int i = 0; i < 2; i++)
#pragma unroll
        for (int j = 0; j < 8; j++)
#pragma unroll
            for (int c = 0; c < 4; c++) acc[i][j][c] = 0.0f;

    const int a_r  = lane & 15;
    const int a_k8 = ((lane >> 4) & 1) * 8;
    const int b_r  = ((lane >> 4) << 3) + (lane & 7);
    const int b_k8 = ((lane >> 3) & 1) * 8;

    const int NITER = 48;
    const int ia0 = tid, ia1 = tid + 256;
    const unsigned int sa0 = (unsigned int)((ia0 >> 2) * T_LDS + (ia0 & 3) * 8) * 2;
    const unsigned int sa1 = (unsigned int)((ia1 >> 2) * T_LDS + (ia1 & 3) * 8) * 2;

    auto stage = [&](int j) {
        int term = j >> 4;
        int kk = (j & 15) * 32;
        int b = kk >> 7, e0 = kk & 127;
        const __nv_bfloat16* Ag = APtr[term] + ((size_t)(h * B_ + b) * S_ + s0) * HD_ + e0;
        const __nv_bfloat16* Bg = BPtr[term] + ((size_t)(h * B_ + b) * S_ + t0) * HD_ + e0;
        unsigned int abase = smbase + (j % 3) * STAGE_B;
        unsigned int bbase = abase + STG_B;
        cpa16(abase + sa0, Ag + (size_t)(ia0 >> 2) * HD_ + (ia0 & 3) * 8);
        cpa16(abase + sa1, Ag + (size_t)(ia1 >> 2) * HD_ + (ia1 & 3) * 8);
        cpa16(bbase + sa0, Bg + (size_t)(ia0 >> 2) * HD_ + (ia0 & 3) * 8);
        cpa16(bbase + sa1, Bg + (size_t)(ia1 >> 2) * HD_ + (ia1 & 3) * 8);
        asm volatile("cp.async.commit_group;");
    };

    stage(0);
    stage(1);

    for (int it = 0; it < NITER; it++) {
        if (it + 1 < NITER) { asm volatile("cp.async.wait_group 1;"); }
        else                { asm volatile("cp.async.wait_group 0;"); }
        __syncthreads();
        if (it + 2 < NITER) stage(it + 2);

        const unsigned int asb = smbase + (it % 3) * STAGE_B;
        const unsigned int bsb = asb + STG_B;
#pragma unroll
        for (int ks = 0; ks < 2; ks++) {
            const int kb = ks * 16;
            unsigned int af[2][4];
#pragma unroll
            for (int mi = 0; mi < 2; mi++) {
                int row = wm * 32 + mi * 16 + a_r;
                unsigned int addr = asb + (unsigned int)(row * T_LDS + kb + a_k8) * 2;
                ldsm4(af[mi][0], af[mi][1], af[mi][2], af[mi][3], addr);
            }
#pragma unroll
            for (int nj = 0; nj < 4; nj++) {
                int nrow = wn * 64 + nj * 16 + b_r;
                unsigned int addr = bsb + (unsigned int)(nrow * T_LDS + kb + b_k8) * 2;
                unsigned int bf[4];
                ldsm4(bf[0], bf[1], bf[2], bf[3], addr);
#pragma unroll
                for (int mi = 0; mi < 2; mi++) {
                    mma16816(acc[mi][nj * 2 + 0], af[mi], &bf[0]);
                    mma16816(acc[mi][nj * 2 + 1], af[mi], &bf[2]);
                }
            }
        }
    }

    const float l2g = d_l2g[h];
    const float inv_sqrt_hd = 0.08838834764831845f;
    __nv_bfloat16* Ahh = d_Ahh + (size_t)h * S_ * S_;
    __nv_bfloat16* Ahl = d_Ahl + (size_t)h * S_ * S_;
    const int qr = lane >> 2;
    const int qc = (lane & 3) * 2;
#pragma unroll
    for (int mi = 0; mi < 2; mi++) {
#pragma unroll
        for (int n8 = 0; n8 < 8; n8++) {
            int t1 = t0 + wn * 64 + n8 * 8 + qc;
            float rs1 = d_rs[h * S_ + t1];
            float rs2 = d_rs[h * S_ + t1 + 1];
#pragma unroll
            for (int half = 0; half < 2; half++) {
                int s = s0 + wm * 32 + mi * 16 + qr + half * 8;
                float a1 = acc[mi][n8][half * 2 + 0];
                float a2 = acc[mi][n8][half * 2 + 1];
                float v1 = (t1 > s) ? 1.0f
                   : fmaxf(fabsf(a1 * inv_sqrt_hd * exp2f((float)(t1 - s) * l2g) * rs1), 1.0f);
                float v2 = (t1 + 1 > s) ? 1.0f
                   : fmaxf(fabsf(a2 * inv_sqrt_hd * exp2f((float)(t1 + 1 - s) * l2g) * rs2), 1.0f);
                __nv_bfloat16 h1 = __float2bfloat16(v1);
                __nv_bfloat16 h2 = __float2bfloat16(v2);
                __nv_bfloat16 l1 = __float2bfloat16(v1 - __bfloat162float(h1));
                __nv_bfloat16 l2 = __float2bfloat16(v2 - __bfloat162float(h2));
                __nv_bfloat162 hp; hp.x = h1; hp.y = h2;
                __nv_bfloat162 lp; lp.x = l1; lp.y = l2;
                *(__nv_bfloat162*)&Ahh[(size_t)s * S_ + t1] = hp;
                *(__nv_bfloat162*)&Ahl[(size_t)s * S_ + t1] = lp;
            }
        }
    }
}

// ---------------- ogemm tensor kernel: cp.async pipeline, big tiles first -
__global__ __launch_bounds__(256, 2)
void ogemm_tensor_kernel() {
    extern __shared__ __align__(16) unsigned char p_smem[];
    const int bh = blockIdx.y;
    const int b = bh >> 4, h = bh & 15;
    const int si = NSB - 1 - blockIdx.x;
    const int s0 = si * 128;
    const int KT = (si + 1) * 4;

    const int tid  = threadIdx.x;
    const int wid  = tid >> 5;
    const int lane = tid & 31;
    const int wm = wid & 3;
    const int wn = wid >> 2;

    const unsigned int smbase = (unsigned int)__cvta_generic_to_shared(p_smem);

    const __nv_bfloat16* Abase_h = d_Ahh + (size_t)h * S_ * S_;
    const __nv_bfloat16* Abase_l = d_Ahl + (size_t)h * S_ * S_;
    const __nv_bfloat16* Vbase_h = d_Vth + (size_t)(h * B_ + b) * HD_ * S_;
    const __nv_bfloat16* Vbase_l = d_Vtl + (size_t)(h * B_ + b) * HD_ * S_;
    const __nv_bfloat16* APtr[3] = {Abase_h, Abase_h, Abase_l};
    const __nv_bfloat16* BPtr[3] = {Vbase_h, Vbase_l, Vbase_h};

    float acc[2][8][4];
#pragma unroll
    for (int i = 0; i < 2; i++)
#pragma unroll
        for (int j = 0; j < 8; j++)
#pragma unroll
            for (int c = 0; c < 4; c++) acc[i][j][c] = 0.0f;

    const int a_r  = lane & 15;
    const int a_k8 = ((lane >> 4) & 1) * 8;
    const int b_r  = ((lane >> 4) << 3) + (lane & 7);
    const int b_k8 = ((lane >> 3) & 1) * 8;

    const int NITER = 3 * KT;
    const int ia0 = tid, ia1 = tid + 256;
    const unsigned int sa0 = (unsigned int)((ia0 >> 2) * T_LDS + (ia0 & 3) * 8) * 2;
    const unsigned int sa1 = (unsigned int)((ia1 >> 2) * T_LDS + (ia1 & 3) * 8) * 2;

    auto stage = [&](int j) {
        int term = j / KT;
        int kk = (j - term * KT) * 32;
        const __nv_bfloat16* Ag = APtr[term] + (size_t)s0 * S_ + kk;
        const __nv_bfloat16* Bg = BPtr[term] + kk;
        unsigned int abase = smbase + (j % 3) * STAGE_B;
        unsigned int bbase = abase + STG_B;
        cpa16(abase + sa0, Ag + (size_t)(ia0 >> 2) * S_ + (ia0 & 3) * 8);
        cpa16(abase + sa1, Ag + (size_t)(ia1 >> 2) * S_ + (ia1 & 3) * 8);
        cpa16(bbase + sa0, Bg + (size_t)(ia0 >> 2) * S_ + (ia0 & 3) * 8);
        cpa16(bbase + sa1, Bg + (size_t)(ia1 >> 2) * S_ + (ia1 & 3) * 8);
        asm volatile("cp.async.commit_group;");
    };

    stage(0);
    if (NITER > 1) stage(1);

    for (int it = 0; it < NITER; it++) {
        if (it + 1 < NITER) { asm volatile("cp.async.wait_group 1;"); }
        else                { asm volatile("cp.async.wait_group 0;"); }
        __syncthreads();
        if (it + 2 < NITER) stage(it + 2);

        const unsigned int asb = smbase + (it % 3) * STAGE_B;
        const unsigned int bsb = asb + STG_B;
#pragma unroll
        for (int ks = 0; ks < 2; ks++) {
            const int kb = ks * 16;
            unsigned int af[2][4];
#pragma unroll
            for (int mi = 0; mi < 2; mi++) {
                int row = wm * 32 + mi * 16 + a_r;
                unsigned int addr = asb + (unsigned int)(row * T_LDS + kb + a_k8) * 2;
                ldsm4(af[mi][0], af[mi][1], af[mi][2], af[mi][3], addr);
            }
#pragma unroll
            for (int nj = 0; nj < 4; nj++) {
                int nrow = wn * 64 + nj * 16 + b_r;
                unsigned int addr = bsb + (unsigned int)(nrow * T_LDS + kb + b_k8) * 2;
                unsigned int bf[4];
                ldsm4(bf[0], bf[1], bf[2], bf[3], addr);
#pragma unroll
                for (int mi = 0; mi < 2; mi++) {
                    mma16816(acc[mi][nj * 2 + 0], af[mi], &bf[0]);
                    mma16816(acc[mi][nj * 2 + 1], af[mi], &bf[2]);
                }
            }
        }
    }

    const float* suf = d_suf + ((size_t)(h * B_ + b) * NSB + si) * HD_;
    const int qr = lane >> 2;
    const int qc = (lane & 3) * 2;
#pragma unroll
    for (int mi = 0; mi < 2; mi++) {
#pragma unroll
        for (int n8 = 0; n8 < 8; n8++) {
            int e = wn * 64 + n8 * 8 + qc;
            float sv1 = suf[e], sv2 = suf[e + 1];
            int s = s0 + wm * 32 + mi * 16 + qr;
            float2 v0; v0.x = acc[mi][n8][0] + sv1; v0.y = acc[mi][n8][1] + sv2;
            float2 v1; v1.x = acc[mi][n8][2] + sv1; v1.y = acc[mi][n8][3] + sv2;
            *(float2*)&d_O[(size_t)(b * S_ + s) * DIM_ + h * HD_ + e] = v0;
            *(float2*)&d_O[(size_t)(b * S_ + s + 8) * DIM_ + h * HD_ + e] = v1;
        }
    }
}

// ---------------- tensor-core FF GEMM: A-fragment-reuse 2-pass pipeline --
// pass1: stage {Ah, Bh, Bl}, compute Ah@Bh + Ah@Bl from one A fragment
// pass2: stage {Al, Bh}, compute Al@Bh  (standard 2-operand pipeline)
#define FF_K    DIM_
__global__ __launch_bounds__(256, 2)
void ff_tensor_kernel(float* __restrict__ outParam, int mode) {
    extern __shared__ __align__(16) unsigned char p_smem[];

    const __nv_bfloat16* Ahp = d_xh;
    const __nv_bfloat16* Alp = d_xl;
    const __nv_bfloat16* Bhp = (mode == 0) ? d_wgh : d_woh;
    const __nv_bfloat16* Blp = (mode == 0) ? d_wgl : d_wol;
    float* Cm = (mode == 0) ? d_G : outParam;

    const int n0 = blockIdx.x * 128;
    const int m0 = blockIdx.y * 128;

    const int tid  = threadIdx.x;
    const int wid  = tid >> 5;
    const int lane = tid & 31;
    const int wm = wid & 3;
    const int wn = wid >> 2;

    const unsigned int smbase = (unsigned int)__cvta_generic_to_shared(p_smem);

    float acc[2][8][4];
#pragma unroll
    for (int i = 0; i < 2; i++)
#pragma unroll
        for (int j = 0; j < 8; j++)
#pragma unroll
            for (int c = 0; c < 4; c++) acc[i][j][c] = 0.0f;

    const int a_r  = lane & 15;
    const int a_k8 = ((lane >> 4) & 1) * 8;
    const int b_r  = ((lane >> 4) << 3) + (lane & 7);
    const int b_k8 = ((lane >> 3) & 1) * 8;

    const int NCH = FF_K / 32;      // 64 chunks
    const int ia0 = tid, ia1 = tid + 256;
    const unsigned int sa0 = (unsigned int)((ia0 >> 2) * T_LDS + (ia0 & 3) * 8) * 2;
    const unsigned int sa1 = (unsigned int)((ia1 >> 2) * T_LDS + (ia1 & 3) * 8) * 2;
    const size_t ga0 = (size_t)(ia0 >> 2) * FF_K + (ia0 & 3) * 8;
    const size_t ga1 = (size_t)(ia1 >> 2) * FF_K + (ia1 & 3) * 8;

    // ---- pass 1: Ah @ (Bh, Bl) ----
    auto stage1 = [&](int j) {
        int k0 = j * 32;
        const __nv_bfloat16* Ag  = Ahp + (size_t)m0 * FF_K + k0;
        const __nv_bfloat16* Bhg = Bhp + (size_t)n0 * FF_K + k0;
        const __nv_bfloat16* Blg = Blp + (size_t)n0 * FF_K + k0;
        unsigned int abase  = smbase + (j % 3) * FF_ST1_B;
        unsigned int bhbase = abase + STG_B;
        unsigned int blbase = abase + 2 * STG_B;
        cpa16(abase  + sa0, Ag  + ga0);
        cpa16(abase  + sa1, Ag  + ga1);
        cpa16(bhbase + sa0, Bhg + ga0);
        cpa16(bhbase + sa1, Bhg + ga1);
        cpa16(blbase + sa0, Blg + ga0);
        cpa16(blbase + sa1, Blg + ga1);
        asm volatile("cp.async.commit_group;");
    };

    stage1(0);
    stage1(1);

    for (int it = 0; it < NCH; it++) {
        if (it + 1 < NCH) { asm volatile("cp.async.wait_group 1;"); }
        else              { asm volatile("cp.async.wait_group 0;"); }
        __syncthreads();
        if (it + 2 < NCH) stage1(it + 2);

        const unsigned int asb  = smbase + (it % 3) * FF_ST1_B;
        const unsigned int bhb  = asb + STG_B;
        const unsigned int blb  = asb + 2 * STG_B;
#pragma unroll
        for (int ks = 0; ks < 2; ks++) {
            const int kb = ks * 16;
            unsigned int af[2][4];
#pragma unroll
            for (int mi = 0; mi < 2; mi++) {
                int row = wm * 32 + mi * 16 + a_r;
                unsigned int addr = asb + (unsigned int)(row * T_LDS + kb + a_k8) * 2;
                ldsm4(af[mi][0], af[mi][1], af[mi][2], af[mi][3], addr);
            }
#pragma unroll
            for (int nj = 0; nj < 4; nj++) {
                int nrow = wn * 64 + nj * 16 + b_r;
                unsigned int off = (unsigned int)(nrow * T_LDS + kb + b_k8) * 2;
                unsigned int bf[4];
                ldsm4(bf[0], bf[1], bf[2], bf[3], bhb + off);
#pragma unroll
                for (int mi = 0; mi < 2; mi++) {
                    mma16816(acc[mi][nj * 2 + 0], af[mi], &bf[0]);
                    mma16816(acc[mi][nj * 2 + 1], af[mi], &bf[2]);
                }
                ldsm4(bf[0], bf[1], bf[2], bf[3], blb + off);
#pragma unroll
                for (int mi = 0; mi < 2; mi++) {
                    mma16816(acc[mi][nj * 2 + 0], af[mi], &bf[0]);
                    mma16816(acc[mi][nj * 2 + 1], af[mi], &bf[2]);
                }
            }
        }
    }
    __syncthreads();   // all pass-1 reads done before restaging

    // ---- pass 2: Al @ Bh ----
    auto stage2 = [&](int j) {
        int k0 = j * 32;
        const __nv_bfloat16* Ag = Alp + (size_t)m0 * FF_K + k0;
        const __nv_bfloat16* Bg = Bhp + (size_t)n0 * FF_K + k0;
        unsigned int abase = smbase + (j % 3) * STAGE_B;
        unsigned int bbase = abase + STG_B;
        cpa16(abase + sa0, Ag + ga0);
        cpa16(abase + sa1, Ag + ga1);
        cpa16(bbase + sa0, Bg + ga0);
        cpa16(bbase + sa1, Bg + ga1);
        asm volatile("cp.async.commit_group;");
    };

    stage2(0);
    stage2(1);

    for (int it = 0; it < NCH; it++) {
        if (it + 1 < NCH) { asm volatile("cp.async.wait_group 1;"); }
        else              { asm volatile("cp.async.wait_group 0;"); }
        __syncthreads();
        if (it + 2 < NCH) stage2(it + 2);

        const unsigned int asb = smbase + (it % 3) * STAGE_B;
        const unsigned int bsb = asb + STG_B;
#pragma unroll
        for (int ks = 0; ks < 2; ks++) {
            const int kb = ks * 16;
            unsigned int af[2][4];
#pragma unroll
            for (int mi = 0; mi < 2; mi++) {
                int row = wm * 32 + mi * 16 + a_r;
                unsigned int addr = asb + (unsigned int)(row * T_LDS + kb + a_k8) * 2;
                ldsm4(af[mi][0], af[mi][1], af[mi][2], af[mi][3], addr);
            }
#pragma unroll
            for (int nj = 0; nj < 4; nj++) {
                int nrow = wn * 64 + nj * 16 + b_r;
                unsigned int addr = bsb + (unsigned int)(nrow * T_LDS + kb + b_k8) * 2;
                unsigned int bf[4];
                ldsm4(bf[0], bf[1], bf[2], bf[3], addr);
#pragma unroll
                for (int mi = 0; mi < 2; mi++) {
                    mma16816(acc[mi][nj * 2 + 0], af[mi], &bf[0]);
                    mma16816(acc[mi][nj * 2 + 1], af[mi], &bf[2]);
                }
            }
        }
    }

    const int qr = lane >> 2;
    const int qc = (lane & 3) * 2;
#pragma unroll
    for (int mi = 0; mi < 2; mi++) {
#pragma unroll
        for (int n8 = 0; n8 < 8; n8++) {
            int m = m0 + wm * 32 + mi * 16 + qr;
            int n = n0 + wn * 64 + n8 * 8 + qc;
            float2 v0; v0.x = acc[mi][n8][0]; v0.y = acc[mi][n8][1];
            float2 v1; v1.x = acc[mi][n8][2]; v1.y = acc[mi][n8][3];
            if (mode == 0) {
                v0.x = fmaxf(v0.x, 0.f); v0.y = fmaxf(v0.y, 0.f);
                v1.x = fmaxf(v1.x, 0.f); v1.y = fmaxf(v1.y, 0.f);
            }
            *(float2*)&Cm[(size_t)m * DIM_ + n] = v0;
            *(float2*)&Cm[(size_t)(m + 8) * DIM_ + n] = v1;
        }
    }
}

// ---------------- layernorm + gate mul: single-pass variance -------------
__global__ void gn_kernel(const float* __restrict__ gamma,
                          const float* __restrict__ beta) {
    const int row = blockIdx.x;
    const float* orow = d_O + (size_t)row * DIM_;
    const float* grow = d_G + (size_t)row * DIM_;
    __nv_bfloat16* hrow = d_xh + (size_t)row * DIM_;
    __nv_bfloat16* lrow = d_xl + (size_t)row * DIM_;
    const int tid = threadIdx.x;

    float v[8];
#pragma unroll
    for (int i = 0; i < 2; i++) {
        float4 t = *(const float4*)&orow[tid * 8 + i * 4];
        v[i * 4 + 0] = t.x; v[i * 4 + 1] = t.y;
        v[i * 4 + 2] = t.z; v[i * 4 + 3] = t.w;
    }

    __shared__ float redS[8];
    __shared__ float redQ[8];
    __shared__ float s_mu, s_inv;

    float lsum = 0.f, lsq = 0.f;
#pragma unroll
    for (int i = 0; i < 8; i++) { lsum += v[i]; lsq += v[i] * v[i]; }
#pragma unroll
    for (int off = 16; off > 0; off >>= 1) {
        lsum += __shfl_xor_sync(0xffffffffu, lsum, off);
        lsq  += __shfl_xor_sync(0xffffffffu, lsq,  off);
    }
    if ((tid & 31) == 0) { redS[tid >> 5] = lsum; redQ[tid >> 5] = lsq; }
    __syncthreads();
    if (tid == 0) {
        float s = 0.f, q = 0.f;
#pragma unroll
        for (int w = 0; w < 8; w++) { s += redS[w]; q += redQ[w]; }
        float mu = s * (1.0f / DIM_);
        s_mu = mu;
        s_inv = rsqrtf(q * (1.0f / DIM_) - mu * mu + 1e-3f);
    }
    __syncthreads();
    const float mu = s_mu;
    const float inv = s_inv;

#pragma unroll
    for (int i = 0; i < 2; i++) {
        int c0 = tid * 8 + i * 4;
        float4 g4 = *(const float4*)&grow[c0];
        float4 gm = *(const float4*)&gamma[c0];
        float4 bt = *(const float4*)&beta[c0];
        float o0 = g4.x * ((v[i * 4 + 0] - mu) * inv * gm.x + bt.x);
        float o1 = g4.y * ((v[i * 4 + 1] - mu) * inv * gm.y + bt.y);
        float o2 = g4.z * ((v[i * 4 + 2] - mu) * inv * gm.z + bt.z);
        float o3 = g4.w * ((v[i * 4 + 3] - mu) * inv * gm.w + bt.w);
        __nv_bfloat16 h0 = __float2bfloat16(o0);
        __nv_bfloat16 h1 = __float2bfloat16(o1);
        __nv_bfloat16 h2 = __float2bfloat16(o2);
        __nv_bfloat16 h3 = __float2bfloat16(o3);
        __nv_bfloat16 l0 = __float2bfloat16(o0 - __bfloat162float(h0));
        __nv_bfloat16 l1 = __float2bfloat16(o1 - __bfloat162float(h1));
        __nv_bfloat16 l2 = __float2bfloat16(o2 - __bfloat162float(h2));
        __nv_bfloat16 l3 = __float2bfloat16(o3 - __bfloat162float(h3));
        __nv_bfloat162 hA; hA.x = h0; hA.y = h1;
        __nv_bfloat162 hB; hB.x = h2; hB.y = h3;
        __nv_bfloat162 lA; lA.x = l0; lA.y = l1;
        __nv_bfloat162 lB; lB.x = l2; lB.y = l3;
        *(__nv_bfloat162*)&hrow[c0]     = hA;
        *(__nv_bfloat162*)&hrow[c0 + 2] = hB;
        *(__nv_bfloat162*)&lrow[c0]     = lA;
        *(__nv_bfloat162*)&lrow[c0 + 2] = lB;
    }
}

// ---------------- launch ----------------
extern "C" void kernel_launch(void* const* d_in, const int* in_sizes, int n_in,
                              void* d_out, int out_size) {
    const float* x     = (const float*)d_in[0];
    const float* k     = (const float*)d_in[1];
    const float* v     = (const float*)d_in[2];
    const float* Wh    = (const float*)d_in[3];
    const float* wg_w  = (const float*)d_in[4];
    const float* wo_w  = (const float*)d_in[5];
    const float* gamma = (const float*)d_in[6];
    const float* beta  = (const float*)d_in[7];
    float* out = (float*)d_out;

    cudaFuncSetAttribute(ff_tensor_kernel,
                         cudaFuncAttributeMaxDynamicSharedMemorySize, FF_SMEM);
    cudaFuncSetAttribute(scores_tensor_kernel,
                         cudaFuncAttributeMaxDynamicSharedMemorySize, PIPE_SMEM);
    cudaFuncSetAttribute(ogemm_tensor_kernel,
                         cudaFuncAttributeMaxDynamicSharedMemorySize, PIPE_SMEM);

    decay_kernel<<<H_, S_>>>();
    qkv_kernel<<<dim3(BSTOT / 128, H_, 3), 256>>>(x, k, v, Wh);
    bsum_kernel<<<dim3(H_ * B_, NSB), HD_>>>();
    sufscan_kernel<<<H_ * B_, HD_>>>();
    scores_tensor_kernel<<<dim3(NTRI, H_), 256, PIPE_SMEM>>>();

    wtrans_kernel<<<dim3(DIM_ / 32, DIM_ / 32, 2), dim3(32, 8)>>>(wg_w, wo_w);
    split_kernel<<<(BSTOT * (DIM_ / 4)) / 256, 256>>>(x);

    ff_tensor_kernel<<<dim3(DIM_ / 128, BSTOT / 128), 256, FF_SMEM>>>(out, 0);
    ogemm_tensor_kernel<<<dim3(NSB, B_ * H_), 256, PIPE_SMEM>>>();
    gn_kernel<<<BSTOT, 256>>>(gamma, beta);
    ff_tensor_kernel<<<dim3(DIM_ / 128, BSTOT / 128), 256, FF_SMEM>>>(out, 1);
}